// round 6
// baseline (speedup 1.0000x reference)
#include <cuda_runtime.h>
#include <cuda_bf16.h>
#include <math.h>

#define LREF 384
#define DPC 128
#define HN 4
#define DHD 32
#define KTOT (LREF*DHD)   // 12288

typedef __nv_bfloat16 bf16;
typedef __nv_bfloat162 bf162;

#define NB_PROJ (LREF*LREF/128)   // 1152
#define NB_BIAS (LREF*LREF/32)    // 4608

// ---------------- scratch (device globals) ----------------------------------
__device__ unsigned char g_q8[(size_t)HN*LREF*KTOT]; // [h][i][n*32+d] e4m3, unscaled
__device__ unsigned char g_k8[(size_t)HN*LREF*KTOT]; // [h][j][n*32+d] e4m3, unscaled
__device__ bf16 g_vb[(size_t)HN*LREF*KTOT];     // [h][j][n*32+d]
__device__ bf16 g_gateb[(size_t)LREF*LREF*DPC]; // [row=n*L+i][c]
__device__ bf16 g_omb[(size_t)LREF*LREF*DPC];   // [row=n*L+i][h*32+d]
__device__ float g_attn[(size_t)HN*LREF*LREF];  // fp32 logits (bias-init + atomics)
__device__ bf16 g_attnb[(size_t)HN*LREF*LREF];  // softmaxed, bf16

// ---------------- ptx helpers ------------------------------------------------
__device__ __forceinline__ void ldsm4(unsigned &r0,unsigned &r1,unsigned &r2,unsigned &r3,unsigned a){
    asm volatile("ldmatrix.sync.aligned.m8n8.x4.shared.b16 {%0,%1,%2,%3},[%4];"
        :"=r"(r0),"=r"(r1),"=r"(r2),"=r"(r3):"r"(a));
}
__device__ __forceinline__ void ldsm4t(unsigned &r0,unsigned &r1,unsigned &r2,unsigned &r3,unsigned a){
    asm volatile("ldmatrix.sync.aligned.m8n8.x4.trans.shared.b16 {%0,%1,%2,%3},[%4];"
        :"=r"(r0),"=r"(r1),"=r"(r2),"=r"(r3):"r"(a));
}
__device__ __forceinline__ void mma_bf16(float c[4], const unsigned a[4], const unsigned b[2]){
    asm volatile("mma.sync.aligned.m16n8k16.row.col.f32.bf16.bf16.f32 "
        "{%0,%1,%2,%3},{%4,%5,%6,%7},{%8,%9},{%0,%1,%2,%3};"
        :"+f"(c[0]),"+f"(c[1]),"+f"(c[2]),"+f"(c[3])
        :"r"(a[0]),"r"(a[1]),"r"(a[2]),"r"(a[3]),"r"(b[0]),"r"(b[1]));
}
__device__ __forceinline__ void mma_fp8(float c[4], const unsigned a[4], const unsigned b[2]){
    asm volatile("mma.sync.aligned.m16n8k32.row.col.f32.e4m3.e4m3.f32 "
        "{%0,%1,%2,%3},{%4,%5,%6,%7},{%8,%9},{%0,%1,%2,%3};"
        :"+f"(c[0]),"+f"(c[1]),"+f"(c[2]),"+f"(c[3])
        :"r"(a[0]),"r"(a[1]),"r"(a[2]),"r"(a[3]),"r"(b[0]),"r"(b[1]));
}
__device__ __forceinline__ void cpa16(unsigned saddr, const void* g) {
    asm volatile("cp.async.cg.shared.global [%0],[%1],16;\n" :: "r"(saddr), "l"(g));
}
__device__ __forceinline__ void cpa_commit() { asm volatile("cp.async.commit_group;\n"); }
template<int N>
__device__ __forceinline__ void cpa_wait() { asm volatile("cp.async.wait_group %0;\n" :: "n"(N)); }

__device__ __forceinline__ unsigned pk2(float a, float b){
    bf162 t = __floats2bfloat162_rn(a, b);
    return *(unsigned*)&t;
}
__device__ __forceinline__ unsigned short pk8(float lo, float hi){
    unsigned short u;
    asm("cvt.rn.satfinite.e4m3x2.f32 %0, %2, %1;" : "=h"(u) : "f"(lo), "f"(hi));
    return u;
}

// warp k16-step (bf16): A rows 128B [m][k64], B rows 128B [n][k64], SW128-swizzled
template<int MT,int NT>
__device__ __forceinline__ void wstep(float (&acc)[MT][NT][4], unsigned sA, unsigned sB,
                                      int m0, int n0, int k0, int lane)
{
    unsigned a[MT][4];
    int arow = lane & 15, acg = (k0>>3) + (lane>>4);
#pragma unroll
    for (int mt = 0; mt < MT; mt++) {
        int r = m0 + mt*16 + arow;
        ldsm4(a[mt][0],a[mt][1],a[mt][2],a[mt][3], sA + r*128 + ((acg ^ (r&7))<<4));
    }
    int brow_off = (lane & 7) + ((lane>>4)<<3);
    int bcg = (k0>>3) + ((lane>>3)&1);
#pragma unroll
    for (int nt = 0; nt < NT; nt += 2) {
        int r = n0 + nt*8 + brow_off;
        unsigned b[4];
        ldsm4(b[0],b[1],b[2],b[3], sB + r*128 + ((bcg ^ (r&7))<<4));
#pragma unroll
        for (int mt = 0; mt < MT; mt++) {
            mma_bf16(acc[mt][nt],   a[mt], b);
            mma_bf16(acc[mt][nt+1], a[mt], b+2);
        }
    }
}

// warp k32-step (fp8): A rows 128B [m][k128 bytes], B rows 128B [n][k128 bytes]
template<int MT,int NT>
__device__ __forceinline__ void wstep8(float (&acc)[MT][NT][4], unsigned sA, unsigned sB,
                                       int m0, int n0, int kb, int lane)
{
    unsigned a[MT][4];
    int arow = lane & 15, acg = (kb>>4) + (lane>>4);
#pragma unroll
    for (int mt = 0; mt < MT; mt++) {
        int r = m0 + mt*16 + arow;
        ldsm4(a[mt][0],a[mt][1],a[mt][2],a[mt][3], sA + r*128 + ((acg ^ (r&7))<<4));
    }
    int brow_off = (lane & 7) + ((lane>>4)<<3);
    int bcg = (kb>>4) + ((lane>>3)&1);
#pragma unroll
    for (int nt = 0; nt < NT; nt += 2) {
        int r = n0 + nt*8 + brow_off;
        unsigned b[4];
        ldsm4(b[0],b[1],b[2],b[3], sB + r*128 + ((bcg ^ (r&7))<<4));
#pragma unroll
        for (int mt = 0; mt < MT; mt++) {
            mma_fp8(acc[mt][nt],   a[mt], b);
            mma_fp8(acc[mt][nt+1], a[mt], b+2);
        }
    }
}

// warp k16-step with transposed B: B buffer 256B rows [k64][n128]
template<int MT,int NT>
__device__ __forceinline__ void wstep_t(float (&acc)[MT][NT][4], unsigned sA, unsigned sB,
                                        int m0, int n0, int k0, int lane)
{
    unsigned a[MT][4];
    int arow = lane & 15, acg = (k0>>3) + (lane>>4);
#pragma unroll
    for (int mt = 0; mt < MT; mt++) {
        int r = m0 + mt*16 + arow;
        ldsm4(a[mt][0],a[mt][1],a[mt][2],a[mt][3], sA + r*128 + ((acg ^ (r&7))<<4));
    }
    int brow = k0 + (lane & 7) + (((lane>>3)&1)<<3);
    int bcg_off = lane >> 4;
#pragma unroll
    for (int nt = 0; nt < NT; nt += 2) {
        int cg = ((n0 + nt*8) >> 3) + bcg_off;
        unsigned b[4];
        ldsm4t(b[0],b[1],b[2],b[3], sB + brow*256 + ((cg ^ (brow&7))<<4));
#pragma unroll
        for (int mt = 0; mt < MT; mt++) {
            mma_bf16(acc[mt][nt],   a[mt], b);
            mma_bf16(acc[mt][nt+1], a[mt], b+2);
        }
    }
}

// -------- fused kernel A: proj (blocks 0..NB_PROJ) + bias (rest) -------------
// proj: 128-row tile (fixed n), single-pass warp LN, warp-mma 2m x 4n (64x32).
// bias: warp-per-row LN + 4-head dot, writes fp32 attn init.
__global__ void __launch_bounds__(256) pb_kernel(
    const float* __restrict__ pair, const float* __restrict__ biasp,
    const float* __restrict__ lnpg, const float* __restrict__ lnpb,
    const float* __restrict__ lnbg, const float* __restrict__ lnbb,
    const float* __restrict__ Wq, const float* __restrict__ Wk, const float* __restrict__ Wv,
    const float* __restrict__ Wg, const float* __restrict__ bg,
    const float* __restrict__ Wb)
{
    extern __shared__ unsigned char sm[];
    int tid = threadIdx.x, lane = tid & 31, wid = tid >> 5;

    if (blockIdx.x < NB_PROJ) {
        // ================= proj =================
        unsigned sXa = (unsigned)__cvta_generic_to_shared(sm);   // 2 x 16KB
        unsigned sWa = sXa + 32768;                              // 2 x 16KB
        int wm = wid >> 2, wn = wid & 3;
        int row0 = blockIdx.x * 128;
        int nn = row0 / LREF, i0b = row0 % LREF;

        // warp-cooperative single-pass LN: warp handles 16 rows
        for (int rr = 0; rr < 16; rr++) {
            int r = wid * 16 + rr;
            int i = i0b + r;
            const float* x = pair + ((size_t)i*LREF + nn) * DPC;
            float4 t = *(const float4*)(x + lane*4);
            float s  = t.x + t.y + t.z + t.w;
            float s2 = t.x*t.x + t.y*t.y + t.z*t.z + t.w*t.w;
#pragma unroll
            for (int o = 16; o; o >>= 1) {
                s  += __shfl_xor_sync(0xffffffffu, s,  o);
                s2 += __shfl_xor_sync(0xffffffffu, s2, o);
            }
            float mean = s * (1.f/DPC);
            float rstd = rsqrtf(s2 * (1.f/DPC) - mean*mean + 1e-5f);
            float4 wv = *(const float4*)(lnpg + lane*4);
            float4 bv = *(const float4*)(lnpb + lane*4);
            unsigned p0 = pk2((t.x-mean)*rstd*wv.x + bv.x, (t.y-mean)*rstd*wv.y + bv.y);
            unsigned p1 = pk2((t.z-mean)*rstd*wv.z + bv.z, (t.w-mean)*rstd*wv.w + bv.w);
            int kc = lane >> 4, g = (lane & 15) >> 1;
            *(uint2*)(sm + kc*16384 + r*128 + ((g ^ (r&7))<<4) + (lane&1)*8) = make_uint2(p0, p1);
        }
        __syncthreads();

        const float* Ws[4] = { Wq, Wk, Wv, Wg };
        for (int mat = 0; mat < 4; mat++) {
            if (mat) __syncthreads();
            // stage whole W (128x128) bf16, both K chunks
            for (int k = 0; k < 8; k++) {
                int idx = tid + k*256;
                int r = idx >> 4, g16 = idx & 15;
                int kc = g16 >> 3, gg = g16 & 7;
                const float* src = Ws[mat] + (size_t)r*DPC + kc*64 + gg*8;
                float4 t0 = *(const float4*)src;
                float4 t1 = *(const float4*)(src + 4);
                uint4 o;
                o.x = pk2(t0.x,t0.y); o.y = pk2(t0.z,t0.w);
                o.z = pk2(t1.x,t1.y); o.w = pk2(t1.z,t1.w);
                *(uint4*)(sm + 32768 + kc*16384 + r*128 + ((gg ^ (r&7))<<4)) = o;
            }
            __syncthreads();

            float acc[4][4][4];
#pragma unroll
            for (int a = 0; a < 4; a++)
#pragma unroll
                for (int b = 0; b < 4; b++)
#pragma unroll
                    for (int cc = 0; cc < 4; cc++) acc[a][b][cc] = 0.f;
#pragma unroll
            for (int kc = 0; kc < 2; kc++)
#pragma unroll
                for (int kk = 0; kk < 4; kk++)
                    wstep<4,4>(acc, sXa + kc*16384, sWa + kc*16384, wm*64, wn*32, kk*16, lane);

#pragma unroll
            for (int mt = 0; mt < 4; mt++)
#pragma unroll
                for (int nt = 0; nt < 4; nt++) {
                    float* ac = acc[mt][nt];
                    int rl = wm*64 + mt*16 + (lane >> 2);
                    int c  = wn*32 + nt*8 + 2*(lane & 3);
                    int hh = c >> 5, d = c & 31;
#pragma unroll
                    for (int half = 0; half < 2; half++) {
                        int i = i0b + rl + half*8;
                        float v0 = ac[half*2+0], v1 = ac[half*2+1];
                        size_t qidx = ((size_t)(hh*LREF + i))*KTOT + nn*DHD + d;
                        if (mat == 0) {
                            *(unsigned short*)&g_q8[qidx] = pk8(v0, v1);
                        } else if (mat == 1) {
                            *(unsigned short*)&g_k8[qidx] = pk8(v0, v1);
                        } else if (mat == 2) {
                            *(bf162*)&g_vb[qidx] = __floats2bfloat162_rn(v0, v1);
                        } else {
                            float z0 = v0 + bg[c], z1 = v1 + bg[c+1];
                            *(bf162*)&g_gateb[((size_t)(nn*LREF + i))*DPC + c] =
                                __floats2bfloat162_rn(1.f/(1.f+expf(-z0)), 1.f/(1.f+expf(-z1)));
                        }
                    }
                }
        }
    } else {
        // ================= bias =================
        float* sWb = (float*)sm;           // 4*128 floats
        int bid = blockIdx.x - NB_PROJ;
        for (int c = tid; c < 4*DPC; c += 256) sWb[c] = Wb[c];
        __syncthreads();

        float4 wg = *(const float4*)(lnbg + lane*4);
        float4 wb = *(const float4*)(lnbb + lane*4);
        float4 W0 = *(const float4*)(sWb + 0*DPC + lane*4);
        float4 W1 = *(const float4*)(sWb + 1*DPC + lane*4);
        float4 W2 = *(const float4*)(sWb + 2*DPC + lane*4);
        float4 W3 = *(const float4*)(sWb + 3*DPC + lane*4);

        for (int rr = 0; rr < 4; rr++) {
            int row = bid*32 + wid*4 + rr;    // row = i*L + j
            int i = row / LREF, j = row - i*LREF;
            const float* x = biasp + ((size_t)j*LREF + i) * DPC;
            float4 t = *(const float4*)(x + lane*4);
            float s  = t.x + t.y + t.z + t.w;
            float s2 = t.x*t.x + t.y*t.y + t.z*t.z + t.w*t.w;
#pragma unroll
            for (int o = 16; o; o >>= 1) {
                s  += __shfl_xor_sync(0xffffffffu, s,  o);
                s2 += __shfl_xor_sync(0xffffffffu, s2, o);
            }
            float mean = s * (1.f/DPC);
            float rstd = rsqrtf(s2 * (1.f/DPC) - mean*mean + 1e-5f);
            float e0 = (t.x-mean)*rstd*wg.x + wb.x;
            float e1 = (t.y-mean)*rstd*wg.y + wb.y;
            float e2 = (t.z-mean)*rstd*wg.z + wb.z;
            float e3 = (t.w-mean)*rstd*wg.w + wb.w;
            float p0 = e0*W0.x + e1*W0.y + e2*W0.z + e3*W0.w;
            float p1 = e0*W1.x + e1*W1.y + e2*W1.z + e3*W1.w;
            float p2 = e0*W2.x + e1*W2.y + e2*W2.z + e3*W2.w;
            float p3 = e0*W3.x + e1*W3.y + e2*W3.z + e3*W3.w;
#pragma unroll
            for (int o = 16; o; o >>= 1) {
                p0 += __shfl_xor_sync(0xffffffffu, p0, o);
                p1 += __shfl_xor_sync(0xffffffffu, p1, o);
                p2 += __shfl_xor_sync(0xffffffffu, p2, o);
                p3 += __shfl_xor_sync(0xffffffffu, p3, o);
            }
            if (lane == 0) {
                g_attn[((size_t)0*LREF + i)*LREF + j] = p0;
                g_attn[((size_t)1*LREF + i)*LREF + j] = p1;
                g_attn[((size_t)2*LREF + i)*LREF + j] = p2;
                g_attn[((size_t)3*LREF + i)*LREF + j] = p3;
            }
        }
    }
}

// -------- kernel C: attn += scale*(q8.k8)  (128x128 tiles, split-K 8, fp8) ---
__global__ void __launch_bounds__(256) score_kernel()
{
    extern __shared__ unsigned char sm[];
    unsigned sA = (unsigned)__cvta_generic_to_shared(sm);     // 2 x 16KB
    unsigned sB = sA + 32768;                                 // 2 x 16KB
    int tid = threadIdx.x, lane = tid & 31, warp = tid >> 5;
    int wm = warp & 3, wn = warp >> 2;
    int h = blockIdx.z >> 3, ks = blockIdx.z & 7;
    int i0 = blockIdx.x * 128, j0 = blockIdx.y * 128;

    const unsigned char* ga = g_q8 + ((size_t)(h*LREF + i0))*KTOT + ks*(KTOT/8);
    const unsigned char* gb = g_k8 + ((size_t)(h*LREF + j0))*KTOT + ks*(KTOT/8);

    float acc[2][8][4];
#pragma unroll
    for (int a = 0; a < 2; a++)
#pragma unroll
        for (int b = 0; b < 8; b++)
#pragma unroll
            for (int cc = 0; cc < 4; cc++) acc[a][b][cc] = 0.f;

    const int NIT = (KTOT/8)/128;   // 12 iterations of k=128 bytes
    auto stage = [&](int it) {
        unsigned off = (it & 1) * 16384;
        for (int c = tid; c < 1024; c += 256) {
            int r = c >> 3, g = c & 7;
            unsigned d = r*128 + ((g ^ (r&7))<<4);
            cpa16(sA + off + d, ga + (size_t)r*KTOT + it*128 + g*16);
            cpa16(sB + off + d, gb + (size_t)r*KTOT + it*128 + g*16);
        }
        cpa_commit();
    };
    stage(0);
    for (int it = 0; it < NIT; it++) {
        if (it + 1 < NIT) { stage(it + 1); cpa_wait<1>(); }
        else cpa_wait<0>();
        __syncthreads();
        unsigned off = (it & 1) * 16384;
#pragma unroll
        for (int kk = 0; kk < 4; kk++)
            wstep8<2,8>(acc, sA + off, sB + off, wm*32, wn*64, kk*32, lane);
        __syncthreads();
    }

    const float SC = 0.17677669529663687f / 384.0f;
#pragma unroll
    for (int mt = 0; mt < 2; mt++)
#pragma unroll
        for (int nt = 0; nt < 8; nt++) {
            float* ac = acc[mt][nt];
            int r = i0 + wm*32 + mt*16 + (lane >> 2);
            int c = j0 + wn*64 + nt*8 + 2*(lane & 3);
            size_t base = ((size_t)h*LREF + r)*LREF + c;
            atomicAdd(&g_attn[base],            ac[0]*SC);
            atomicAdd(&g_attn[base + 1],        ac[1]*SC);
            atomicAdd(&g_attn[base + 8*LREF],   ac[2]*SC);
            atomicAdd(&g_attn[base + 8*LREF+1], ac[3]*SC);
        }
}

// -------- softmax over j per (h,i): fp32 in, bf16 out ------------------------
__global__ void __launch_bounds__(128) softmax_kernel()
{
    int i = blockIdx.x, h = blockIdx.y;
    const float* row = g_attn + ((size_t)h * LREF + i) * LREF;
    bf16* orow = g_attnb + ((size_t)h * LREF + i) * LREF;
    int tid = threadIdx.x, warp = tid >> 5, lane = tid & 31;
    __shared__ float smax[4], ssum[4];

    float a0 = row[tid], a1 = row[tid + 128], a2 = row[tid + 256];
    float m = fmaxf(a0, fmaxf(a1, a2));
#pragma unroll
    for (int o = 16; o; o >>= 1) m = fmaxf(m, __shfl_xor_sync(0xffffffffu, m, o));
    if (lane == 0) smax[warp] = m;
    __syncthreads();
    float M = fmaxf(fmaxf(smax[0], smax[1]), fmaxf(smax[2], smax[3]));

    float e0 = expf(a0 - M), e1 = expf(a1 - M), e2 = expf(a2 - M);
    float s = e0 + e1 + e2;
#pragma unroll
    for (int o = 16; o; o >>= 1) s += __shfl_xor_sync(0xffffffffu, s, o);
    if (lane == 0) ssum[warp] = s;
    __syncthreads();
    float S = ssum[0] + ssum[1] + ssum[2] + ssum[3];
    float inv = 1.f / S;
    orow[tid]       = __float2bfloat16_rn(e0 * inv);
    orow[tid + 128] = __float2bfloat16_rn(e1 * inv);
    orow[tid + 256] = __float2bfloat16_rn(e2 * inv);
}

// -------- kernel D: om[n*L+i][h*32+d] = attn_b[h] @ v  (trans-B MMA) ---------
__global__ void __launch_bounds__(256) av_kernel()
{
    extern __shared__ unsigned char sm[];
    unsigned sA = (unsigned)__cvta_generic_to_shared(sm);     // 2 x 16KB
    unsigned sB = sA + 32768;                                 // 2 x 16KB
    int tid = threadIdx.x, lane = tid & 31, warp = tid >> 5;
    int wm = warp & 3, wn = warp >> 2;
    int i0 = blockIdx.x * 128, col0 = blockIdx.y * 128, h = blockIdx.z;

    const bf16* ga = g_attnb + ((size_t)(h*LREF + i0))*LREF;
    const bf16* gv = g_vb + (size_t)h*LREF*KTOT + col0;

    float acc[2][8][4];
#pragma unroll
    for (int a = 0; a < 2; a++)
#pragma unroll
        for (int b = 0; b < 8; b++)
#pragma unroll
            for (int cc = 0; cc < 4; cc++) acc[a][b][cc] = 0.f;

    const int NIT = LREF/64;   // 6
    auto stage = [&](int it) {
        unsigned off = (it & 1) * 16384;
        for (int c = tid; c < 1024; c += 256) {
            int ra = c >> 3, gA = c & 7;
            cpa16(sA + off + ra*128 + ((gA ^ (ra&7))<<4), ga + (size_t)ra*LREF + it*64 + gA*8);
            int rb = c >> 4, gB = c & 15;
            cpa16(sB + off + rb*256 + ((gB ^ (rb&7))<<4), gv + (size_t)(it*64 + rb)*KTOT + gB*8);
        }
        cpa_commit();
    };
    stage(0);
    for (int it = 0; it < NIT; it++) {
        if (it + 1 < NIT) { stage(it + 1); cpa_wait<1>(); }
        else cpa_wait<0>();
        __syncthreads();
        unsigned off = (it & 1) * 16384;
#pragma unroll
        for (int kk = 0; kk < 4; kk++)
            wstep_t<2,8>(acc, sA + off, sB + off, wm*32, wn*64, kk*16, lane);
        __syncthreads();
    }

#pragma unroll
    for (int mt = 0; mt < 2; mt++)
#pragma unroll
        for (int nt = 0; nt < 8; nt++) {
            float* ac = acc[mt][nt];
            int c = col0 + wn*64 + nt*8 + 2*(lane & 3);
            int n = c >> 5, d = c & 31;
#pragma unroll
            for (int half = 0; half < 2; half++) {
                int i = i0 + wm*32 + mt*16 + (lane >> 2) + half*8;
                *(bf162*)&g_omb[((size_t)n*LREF + i)*DPC + h*DHD + d] =
                    __floats2bfloat162_rn(ac[half*2+0], ac[half*2+1]);
            }
        }
}

// -------- kernel E: y = (gate .* om) @ Wo^T + bo, write transposed -----------
__global__ void __launch_bounds__(256) out_kernel(
    const float* __restrict__ Wo, const float* __restrict__ bo, float* __restrict__ outp)
{
    extern __shared__ unsigned char sm[];
    unsigned sXa = (unsigned)__cvta_generic_to_shared(sm);   // 2 chunks x 32KB
    unsigned sWa = sXa + 65536;                              // 16KB
    int tid = threadIdx.x, lane = tid & 31, warp = tid >> 5;
    int wm = warp >> 1, wn = warp & 1;
    int row0 = blockIdx.x * 256;

    {
        int r = tid;
        size_t grow = (size_t)(row0 + r) * DPC;
#pragma unroll
        for (int g = 0; g < 16; g++) {
            uint4 gt = *(const uint4*)&g_gateb[grow + g*8];
            uint4 ot = *(const uint4*)&g_omb[grow + g*8];
            uint4 o;
            ((bf162*)&o)[0] = __hmul2(((bf162*)&gt)[0], ((bf162*)&ot)[0]);
            ((bf162*)&o)[1] = __hmul2(((bf162*)&gt)[1], ((bf162*)&ot)[1]);
            ((bf162*)&o)[2] = __hmul2(((bf162*)&gt)[2], ((bf162*)&ot)[2]);
            ((bf162*)&o)[3] = __hmul2(((bf162*)&gt)[3], ((bf162*)&ot)[3]);
            int kc = g >> 3, gg = g & 7;
            *(uint4*)(sm + kc*32768 + r*128 + ((gg ^ (r&7))<<4)) = o;
        }
    }
    __syncthreads();

    float acc[4][8][4];
#pragma unroll
    for (int a = 0; a < 4; a++)
#pragma unroll
        for (int b = 0; b < 8; b++)
#pragma unroll
            for (int cc = 0; cc < 4; cc++) acc[a][b][cc] = 0.f;

    for (int kc = 0; kc < 2; kc++) {
        __syncthreads();
        for (int c = tid; c < 1024; c += 256) {
            int r = c >> 3, g = c & 7;
            const float* src = Wo + (size_t)r*DPC + kc*64 + g*8;
            float4 t0 = *(const float4*)src;
            float4 t1 = *(const float4*)(src + 4);
            uint4 o;
            o.x = pk2(t0.x, t0.y); o.y = pk2(t0.z, t0.w);
            o.z = pk2(t1.x, t1.y); o.w = pk2(t1.z, t1.w);
            *(uint4*)(sm + 65536 + r*128 + ((g ^ (r&7))<<4)) = o;
        }
        __syncthreads();
#pragma unroll
        for (int kk = 0; kk < 4; kk++)
            wstep<4,8>(acc, sXa + kc*32768, sWa, wm*64, wn*64, kk*16, lane);
    }

#pragma unroll
    for (int mt = 0; mt < 4; mt++)
#pragma unroll
        for (int nt = 0; nt < 8; nt++) {
            float* ac = acc[mt][nt];
            int rl = wm*64 + mt*16 + (lane >> 2);
            int c  = wn*64 + nt*8 + 2*(lane & 3);
            float b0 = bo[c], b1 = bo[c+1];
#pragma unroll
            for (int half = 0; half < 2; half++) {
                int row = row0 + rl + half*8;
                int n = row / LREF, i = row - n*LREF;
                *(float2*)&outp[((size_t)i*LREF + n)*DPC + c] =
                    make_float2(ac[half*2+0] + b0, ac[half*2+1] + b1);
            }
        }
}

extern "C" void kernel_launch(void* const* d_in, const int* in_sizes, int n_in,
                              void* d_out, int out_size)
{
    (void)in_sizes; (void)n_in; (void)out_size;
    const float* pair      = (const float*)d_in[0];
    const float* bias      = (const float*)d_in[1];
    const float* ln_pair_g = (const float*)d_in[2];
    const float* ln_pair_b = (const float*)d_in[3];
    const float* ln_bias_g = (const float*)d_in[4];
    const float* ln_bias_b = (const float*)d_in[5];
    const float* Wq = (const float*)d_in[6];
    const float* Wk = (const float*)d_in[7];
    const float* Wv = (const float*)d_in[8];
    const float* Wb = (const float*)d_in[9];
    const float* Wg = (const float*)d_in[10];
    const float* bg = (const float*)d_in[11];
    const float* Wo = (const float*)d_in[12];
    const float* bo = (const float*)d_in[13];
    float* outp = (float*)d_out;

    const int PB_SMEM   = 65536;
    const int GEMM_SMEM = 65536;
    const int OUT_SMEM  = 81920;
    cudaFuncSetAttribute(pb_kernel,    cudaFuncAttributeMaxDynamicSharedMemorySize, PB_SMEM);
    cudaFuncSetAttribute(score_kernel, cudaFuncAttributeMaxDynamicSharedMemorySize, GEMM_SMEM);
    cudaFuncSetAttribute(av_kernel,    cudaFuncAttributeMaxDynamicSharedMemorySize, GEMM_SMEM);
    cudaFuncSetAttribute(out_kernel,   cudaFuncAttributeMaxDynamicSharedMemorySize, OUT_SMEM);

    pb_kernel<<<NB_PROJ + NB_BIAS, 256, PB_SMEM>>>(pair, bias,
        ln_pair_g, ln_pair_b, ln_bias_g, ln_bias_b, Wq, Wk, Wv, Wg, bg, Wb);
    score_kernel<<<dim3(3, 3, 32), 256, GEMM_SMEM>>>();
    softmax_kernel<<<dim3(LREF, HN), 128>>>();
    av_kernel<<<dim3(3, KTOT/128, HN), 256, GEMM_SMEM>>>();
    out_kernel<<<LREF*LREF/256, 256, OUT_SMEM>>>(Wo, bo, outp);
}

// round 7
// speedup vs baseline: 1.3438x; 1.3438x over previous
#include <cuda_runtime.h>
#include <cuda_bf16.h>
#include <math.h>

#define LREF 384
#define DPC 128
#define HN 4
#define DHD 32
#define KTOT (LREF*DHD)   // 12288

typedef __nv_bfloat16 bf16;
typedef __nv_bfloat162 bf162;

#define NB_PROJ (LREF*LREF/128)   // 1152
#define NB_BIAS (LREF*LREF/32)    // 4608

// ---------------- scratch (device globals) ----------------------------------
__device__ unsigned char g_q8[(size_t)HN*LREF*KTOT]; // [h][i][n*32+d] e4m3, unscaled
__device__ unsigned char g_k8[(size_t)HN*LREF*KTOT]; // [h][j][n*32+d] e4m3, unscaled
__device__ bf16 g_vb[(size_t)HN*LREF*KTOT];     // [h][j][n*32+d]
__device__ bf16 g_gateb[(size_t)LREF*LREF*DPC]; // [row=n*L+i][c]
__device__ bf16 g_omb[(size_t)LREF*LREF*DPC];   // [row=n*L+i][h*32+d]
__device__ float g_attn[(size_t)HN*LREF*LREF];  // fp32 logits (bias-init + atomics)
__device__ bf16 g_attnb[(size_t)HN*LREF*LREF];  // softmaxed, bf16

// ---------------- ptx helpers ------------------------------------------------
__device__ __forceinline__ void ldsm4(unsigned &r0,unsigned &r1,unsigned &r2,unsigned &r3,unsigned a){
    asm volatile("ldmatrix.sync.aligned.m8n8.x4.shared.b16 {%0,%1,%2,%3},[%4];"
        :"=r"(r0),"=r"(r1),"=r"(r2),"=r"(r3):"r"(a));
}
__device__ __forceinline__ void ldsm4t(unsigned &r0,unsigned &r1,unsigned &r2,unsigned &r3,unsigned a){
    asm volatile("ldmatrix.sync.aligned.m8n8.x4.trans.shared.b16 {%0,%1,%2,%3},[%4];"
        :"=r"(r0),"=r"(r1),"=r"(r2),"=r"(r3):"r"(a));
}
__device__ __forceinline__ void mma_bf16(float c[4], const unsigned a[4], const unsigned b[2]){
    asm volatile("mma.sync.aligned.m16n8k16.row.col.f32.bf16.bf16.f32 "
        "{%0,%1,%2,%3},{%4,%5,%6,%7},{%8,%9},{%0,%1,%2,%3};"
        :"+f"(c[0]),"+f"(c[1]),"+f"(c[2]),"+f"(c[3])
        :"r"(a[0]),"r"(a[1]),"r"(a[2]),"r"(a[3]),"r"(b[0]),"r"(b[1]));
}
__device__ __forceinline__ void mma_fp8(float c[4], const unsigned a[4], const unsigned b[2]){
    asm volatile("mma.sync.aligned.m16n8k32.row.col.f32.e4m3.e4m3.f32 "
        "{%0,%1,%2,%3},{%4,%5,%6,%7},{%8,%9},{%0,%1,%2,%3};"
        :"+f"(c[0]),"+f"(c[1]),"+f"(c[2]),"+f"(c[3])
        :"r"(a[0]),"r"(a[1]),"r"(a[2]),"r"(a[3]),"r"(b[0]),"r"(b[1]));
}
__device__ __forceinline__ void cpa16(unsigned saddr, const void* g) {
    asm volatile("cp.async.cg.shared.global [%0],[%1],16;\n" :: "r"(saddr), "l"(g));
}
__device__ __forceinline__ void cpa_commit() { asm volatile("cp.async.commit_group;\n"); }
template<int N>
__device__ __forceinline__ void cpa_wait() { asm volatile("cp.async.wait_group %0;\n" :: "n"(N)); }

__device__ __forceinline__ unsigned pk2(float a, float b){
    bf162 t = __floats2bfloat162_rn(a, b);
    return *(unsigned*)&t;
}
__device__ __forceinline__ unsigned short pk8(float lo, float hi){
    unsigned short u;
    asm("cvt.rn.satfinite.e4m3x2.f32 %0, %2, %1;" : "=h"(u) : "f"(lo), "f"(hi));
    return u;
}

// warp k16-step (bf16): A rows 128B [m][k64], B rows 128B [n][k64], SW128-swizzled
template<int MT,int NT>
__device__ __forceinline__ void wstep(float (&acc)[MT][NT][4], unsigned sA, unsigned sB,
                                      int m0, int n0, int k0, int lane)
{
    unsigned a[MT][4];
    int arow = lane & 15, acg = (k0>>3) + (lane>>4);
#pragma unroll
    for (int mt = 0; mt < MT; mt++) {
        int r = m0 + mt*16 + arow;
        ldsm4(a[mt][0],a[mt][1],a[mt][2],a[mt][3], sA + r*128 + ((acg ^ (r&7))<<4));
    }
    int brow_off = (lane & 7) + ((lane>>4)<<3);
    int bcg = (k0>>3) + ((lane>>3)&1);
#pragma unroll
    for (int nt = 0; nt < NT; nt += 2) {
        int r = n0 + nt*8 + brow_off;
        unsigned b[4];
        ldsm4(b[0],b[1],b[2],b[3], sB + r*128 + ((bcg ^ (r&7))<<4));
#pragma unroll
        for (int mt = 0; mt < MT; mt++) {
            mma_bf16(acc[mt][nt],   a[mt], b);
            mma_bf16(acc[mt][nt+1], a[mt], b+2);
        }
    }
}

// warp k32-step (fp8): A rows 128B [m][k128 bytes], B rows 128B [n][k128 bytes]
template<int MT,int NT>
__device__ __forceinline__ void wstep8(float (&acc)[MT][NT][4], unsigned sA, unsigned sB,
                                       int m0, int n0, int kb, int lane)
{
    unsigned a[MT][4];
    int arow = lane & 15, acg = (kb>>4) + (lane>>4);
#pragma unroll
    for (int mt = 0; mt < MT; mt++) {
        int r = m0 + mt*16 + arow;
        ldsm4(a[mt][0],a[mt][1],a[mt][2],a[mt][3], sA + r*128 + ((acg ^ (r&7))<<4));
    }
    int brow_off = (lane & 7) + ((lane>>4)<<3);
    int bcg = (kb>>4) + ((lane>>3)&1);
#pragma unroll
    for (int nt = 0; nt < NT; nt += 2) {
        int r = n0 + nt*8 + brow_off;
        unsigned b[4];
        ldsm4(b[0],b[1],b[2],b[3], sB + r*128 + ((bcg ^ (r&7))<<4));
#pragma unroll
        for (int mt = 0; mt < MT; mt++) {
            mma_fp8(acc[mt][nt],   a[mt], b);
            mma_fp8(acc[mt][nt+1], a[mt], b+2);
        }
    }
}

// warp k16-step with transposed B: B buffer 256B rows [k64][n128]
template<int MT,int NT>
__device__ __forceinline__ void wstep_t(float (&acc)[MT][NT][4], unsigned sA, unsigned sB,
                                        int m0, int n0, int k0, int lane)
{
    unsigned a[MT][4];
    int arow = lane & 15, acg = (k0>>3) + (lane>>4);
#pragma unroll
    for (int mt = 0; mt < MT; mt++) {
        int r = m0 + mt*16 + arow;
        ldsm4(a[mt][0],a[mt][1],a[mt][2],a[mt][3], sA + r*128 + ((acg ^ (r&7))<<4));
    }
    int brow = k0 + (lane & 7) + (((lane>>3)&1)<<3);
    int bcg_off = lane >> 4;
#pragma unroll
    for (int nt = 0; nt < NT; nt += 2) {
        int cg = ((n0 + nt*8) >> 3) + bcg_off;
        unsigned b[4];
        ldsm4t(b[0],b[1],b[2],b[3], sB + brow*256 + ((cg ^ (brow&7))<<4));
#pragma unroll
        for (int mt = 0; mt < MT; mt++) {
            mma_bf16(acc[mt][nt],   a[mt], b);
            mma_bf16(acc[mt][nt+1], a[mt], b+2);
        }
    }
}

// -------- fused kernel A: proj (blocks 0..NB_PROJ) + bias (rest) -------------
// proj: 128-row tile (fixed n), 16 warps, warp tile 32x32.
__global__ void __launch_bounds__(512,2) pb_kernel(
    const float* __restrict__ pair, const float* __restrict__ biasp,
    const float* __restrict__ lnpg, const float* __restrict__ lnpb,
    const float* __restrict__ lnbg, const float* __restrict__ lnbb,
    const float* __restrict__ Wq, const float* __restrict__ Wk, const float* __restrict__ Wv,
    const float* __restrict__ Wg, const float* __restrict__ bg,
    const float* __restrict__ Wb)
{
    extern __shared__ unsigned char sm[];
    int tid = threadIdx.x, lane = tid & 31, wid = tid >> 5;

    if (blockIdx.x < NB_PROJ) {
        // ================= proj =================
        unsigned sXa = (unsigned)__cvta_generic_to_shared(sm);   // 2 x 16KB
        unsigned sWa = sXa + 32768;                              // 2 x 16KB
        int wm = wid & 3, wn = wid >> 2;     // 4m x 4n warps, tile 32x32
        int row0 = blockIdx.x * 128;
        int nn = row0 / LREF, i0b = row0 % LREF;

        // warp-cooperative single-pass LN: warp handles 8 rows
        for (int rr = 0; rr < 8; rr++) {
            int r = wid * 8 + rr;
            int i = i0b + r;
            const float* x = pair + ((size_t)i*LREF + nn) * DPC;
            float4 t = *(const float4*)(x + lane*4);
            float s  = t.x + t.y + t.z + t.w;
            float s2 = t.x*t.x + t.y*t.y + t.z*t.z + t.w*t.w;
#pragma unroll
            for (int o = 16; o; o >>= 1) {
                s  += __shfl_xor_sync(0xffffffffu, s,  o);
                s2 += __shfl_xor_sync(0xffffffffu, s2, o);
            }
            float mean = s * (1.f/DPC);
            float rstd = rsqrtf(s2 * (1.f/DPC) - mean*mean + 1e-5f);
            float4 wv = *(const float4*)(lnpg + lane*4);
            float4 bv = *(const float4*)(lnpb + lane*4);
            unsigned p0 = pk2((t.x-mean)*rstd*wv.x + bv.x, (t.y-mean)*rstd*wv.y + bv.y);
            unsigned p1 = pk2((t.z-mean)*rstd*wv.z + bv.z, (t.w-mean)*rstd*wv.w + bv.w);
            int kc = lane >> 4, g = (lane & 15) >> 1;
            *(uint2*)(sm + kc*16384 + r*128 + ((g ^ (r&7))<<4) + (lane&1)*8) = make_uint2(p0, p1);
        }
        __syncthreads();

        const float* Ws[4] = { Wq, Wk, Wv, Wg };
        for (int mat = 0; mat < 4; mat++) {
            if (mat) __syncthreads();
            // stage whole W (128x128) bf16, both K chunks
            for (int idx = tid; idx < 2048; idx += 512) {
                int r = idx >> 4, g16 = idx & 15;
                int kc = g16 >> 3, gg = g16 & 7;
                const float* src = Ws[mat] + (size_t)r*DPC + kc*64 + gg*8;
                float4 t0 = *(const float4*)src;
                float4 t1 = *(const float4*)(src + 4);
                uint4 o;
                o.x = pk2(t0.x,t0.y); o.y = pk2(t0.z,t0.w);
                o.z = pk2(t1.x,t1.y); o.w = pk2(t1.z,t1.w);
                *(uint4*)(sm + 32768 + kc*16384 + r*128 + ((gg ^ (r&7))<<4)) = o;
            }
            __syncthreads();

            float acc[2][4][4];
#pragma unroll
            for (int a = 0; a < 2; a++)
#pragma unroll
                for (int b = 0; b < 4; b++)
#pragma unroll
                    for (int cc = 0; cc < 4; cc++) acc[a][b][cc] = 0.f;
#pragma unroll
            for (int kc = 0; kc < 2; kc++)
#pragma unroll
                for (int kk = 0; kk < 4; kk++)
                    wstep<2,4>(acc, sXa + kc*16384, sWa + kc*16384, wm*32, wn*32, kk*16, lane);

#pragma unroll
            for (int mt = 0; mt < 2; mt++)
#pragma unroll
                for (int nt = 0; nt < 4; nt++) {
                    float* ac = acc[mt][nt];
                    int rl = wm*32 + mt*16 + (lane >> 2);
                    int c  = wn*32 + nt*8 + 2*(lane & 3);
                    int hh = c >> 5, d = c & 31;
#pragma unroll
                    for (int half = 0; half < 2; half++) {
                        int i = i0b + rl + half*8;
                        float v0 = ac[half*2+0], v1 = ac[half*2+1];
                        size_t qidx = ((size_t)(hh*LREF + i))*KTOT + nn*DHD + d;
                        if (mat == 0) {
                            *(unsigned short*)&g_q8[qidx] = pk8(v0, v1);
                        } else if (mat == 1) {
                            *(unsigned short*)&g_k8[qidx] = pk8(v0, v1);
                        } else if (mat == 2) {
                            *(bf162*)&g_vb[qidx] = __floats2bfloat162_rn(v0, v1);
                        } else {
                            float z0 = v0 + bg[c], z1 = v1 + bg[c+1];
                            *(bf162*)&g_gateb[((size_t)(nn*LREF + i))*DPC + c] =
                                __floats2bfloat162_rn(1.f/(1.f+expf(-z0)), 1.f/(1.f+expf(-z1)));
                        }
                    }
                }
        }
    } else {
        // ================= bias =================
        float* sWb = (float*)sm;           // 4*128 floats
        int bid = blockIdx.x - NB_PROJ;
        for (int c = tid; c < 4*DPC; c += 512) sWb[c] = Wb[c];
        __syncthreads();

        float4 wg = *(const float4*)(lnbg + lane*4);
        float4 wb = *(const float4*)(lnbb + lane*4);
        float4 W0 = *(const float4*)(sWb + 0*DPC + lane*4);
        float4 W1 = *(const float4*)(sWb + 1*DPC + lane*4);
        float4 W2 = *(const float4*)(sWb + 2*DPC + lane*4);
        float4 W3 = *(const float4*)(sWb + 3*DPC + lane*4);

        for (int rr = 0; rr < 2; rr++) {
            int row = bid*32 + wid*2 + rr;    // row = i*L + j
            int i = row / LREF, j = row - i*LREF;
            const float* x = biasp + ((size_t)j*LREF + i) * DPC;
            float4 t = *(const float4*)(x + lane*4);
            float s  = t.x + t.y + t.z + t.w;
            float s2 = t.x*t.x + t.y*t.y + t.z*t.z + t.w*t.w;
#pragma unroll
            for (int o = 16; o; o >>= 1) {
                s  += __shfl_xor_sync(0xffffffffu, s,  o);
                s2 += __shfl_xor_sync(0xffffffffu, s2, o);
            }
            float mean = s * (1.f/DPC);
            float rstd = rsqrtf(s2 * (1.f/DPC) - mean*mean + 1e-5f);
            float e0 = (t.x-mean)*rstd*wg.x + wb.x;
            float e1 = (t.y-mean)*rstd*wg.y + wb.y;
            float e2 = (t.z-mean)*rstd*wg.z + wb.z;
            float e3 = (t.w-mean)*rstd*wg.w + wb.w;
            float p0 = e0*W0.x + e1*W0.y + e2*W0.z + e3*W0.w;
            float p1 = e0*W1.x + e1*W1.y + e2*W1.z + e3*W1.w;
            float p2 = e0*W2.x + e1*W2.y + e2*W2.z + e3*W2.w;
            float p3 = e0*W3.x + e1*W3.y + e2*W3.z + e3*W3.w;
#pragma unroll
            for (int o = 16; o; o >>= 1) {
                p0 += __shfl_xor_sync(0xffffffffu, p0, o);
                p1 += __shfl_xor_sync(0xffffffffu, p1, o);
                p2 += __shfl_xor_sync(0xffffffffu, p2, o);
                p3 += __shfl_xor_sync(0xffffffffu, p3, o);
            }
            if (lane == 0) {
                g_attn[((size_t)0*LREF + i)*LREF + j] = p0;
                g_attn[((size_t)1*LREF + i)*LREF + j] = p1;
                g_attn[((size_t)2*LREF + i)*LREF + j] = p2;
                g_attn[((size_t)3*LREF + i)*LREF + j] = p3;
            }
        }
    }
}

// -------- kernel C: attn += scale*(q8.k8)  (128x128 tiles, split-K 8, fp8) ---
__global__ void __launch_bounds__(512,2) score_kernel()
{
    extern __shared__ unsigned char sm[];
    unsigned sA = (unsigned)__cvta_generic_to_shared(sm);     // 2 x 16KB
    unsigned sB = sA + 32768;                                 // 2 x 16KB
    int tid = threadIdx.x, lane = tid & 31, warp = tid >> 5;
    int wm = warp & 3, wn = warp >> 2;
    int h = blockIdx.z >> 3, ks = blockIdx.z & 7;
    int i0 = blockIdx.x * 128, j0 = blockIdx.y * 128;

    const unsigned char* ga = g_q8 + ((size_t)(h*LREF + i0))*KTOT + ks*(KTOT/8);
    const unsigned char* gb = g_k8 + ((size_t)(h*LREF + j0))*KTOT + ks*(KTOT/8);

    float acc[2][4][4];
#pragma unroll
    for (int a = 0; a < 2; a++)
#pragma unroll
        for (int b = 0; b < 4; b++)
#pragma unroll
            for (int cc = 0; cc < 4; cc++) acc[a][b][cc] = 0.f;

    const int NIT = (KTOT/8)/128;   // 12 iterations of k=128 bytes
    auto stage = [&](int it) {
        unsigned off = (it & 1) * 16384;
        for (int c = tid; c < 1024; c += 512) {
            int r = c >> 3, g = c & 7;
            unsigned d = r*128 + ((g ^ (r&7))<<4);
            cpa16(sA + off + d, ga + (size_t)r*KTOT + it*128 + g*16);
            cpa16(sB + off + d, gb + (size_t)r*KTOT + it*128 + g*16);
        }
        cpa_commit();
    };
    stage(0);
    for (int it = 0; it < NIT; it++) {
        if (it + 1 < NIT) { stage(it + 1); cpa_wait<1>(); }
        else cpa_wait<0>();
        __syncthreads();
        unsigned off = (it & 1) * 16384;
#pragma unroll
        for (int kk = 0; kk < 4; kk++)
            wstep8<2,4>(acc, sA + off, sB + off, wm*32, wn*32, kk*32, lane);
        __syncthreads();
    }

    const float SC = 0.17677669529663687f / 384.0f;
#pragma unroll
    for (int mt = 0; mt < 2; mt++)
#pragma unroll
        for (int nt = 0; nt < 4; nt++) {
            float* ac = acc[mt][nt];
            int r = i0 + wm*32 + mt*16 + (lane >> 2);
            int c = j0 + wn*32 + nt*8 + 2*(lane & 3);
            size_t base = ((size_t)h*LREF + r)*LREF + c;
            atomicAdd(&g_attn[base],            ac[0]*SC);
            atomicAdd(&g_attn[base + 1],        ac[1]*SC);
            atomicAdd(&g_attn[base + 8*LREF],   ac[2]*SC);
            atomicAdd(&g_attn[base + 8*LREF+1], ac[3]*SC);
        }
}

// -------- softmax over j per (h,i): fp32 in, bf16 out ------------------------
__global__ void __launch_bounds__(128) softmax_kernel()
{
    int i = blockIdx.x, h = blockIdx.y;
    const float* row = g_attn + ((size_t)h * LREF + i) * LREF;
    bf16* orow = g_attnb + ((size_t)h * LREF + i) * LREF;
    int tid = threadIdx.x, warp = tid >> 5, lane = tid & 31;
    __shared__ float smax[4], ssum[4];

    float a0 = row[tid], a1 = row[tid + 128], a2 = row[tid + 256];
    float m = fmaxf(a0, fmaxf(a1, a2));
#pragma unroll
    for (int o = 16; o; o >>= 1) m = fmaxf(m, __shfl_xor_sync(0xffffffffu, m, o));
    if (lane == 0) smax[warp] = m;
    __syncthreads();
    float M = fmaxf(fmaxf(smax[0], smax[1]), fmaxf(smax[2], smax[3]));

    float e0 = expf(a0 - M), e1 = expf(a1 - M), e2 = expf(a2 - M);
    float s = e0 + e1 + e2;
#pragma unroll
    for (int o = 16; o; o >>= 1) s += __shfl_xor_sync(0xffffffffu, s, o);
    if (lane == 0) ssum[warp] = s;
    __syncthreads();
    float S = ssum[0] + ssum[1] + ssum[2] + ssum[3];
    float inv = 1.f / S;
    orow[tid]       = __float2bfloat16_rn(e0 * inv);
    orow[tid + 128] = __float2bfloat16_rn(e1 * inv);
    orow[tid + 256] = __float2bfloat16_rn(e2 * inv);
}

// -------- kernel D: om[n*L+i][h*32+d] = attn_b[h] @ v  (trans-B MMA) ---------
__global__ void __launch_bounds__(512,2) av_kernel()
{
    extern __shared__ unsigned char sm[];
    unsigned sA = (unsigned)__cvta_generic_to_shared(sm);     // 2 x 16KB
    unsigned sB = sA + 32768;                                 // 2 x 16KB
    int tid = threadIdx.x, lane = tid & 31, warp = tid >> 5;
    int wm = warp & 3, wn = warp >> 2;
    int i0 = blockIdx.x * 128, col0 = blockIdx.y * 128, h = blockIdx.z;

    const bf16* ga = g_attnb + ((size_t)(h*LREF + i0))*LREF;
    const bf16* gv = g_vb + (size_t)h*LREF*KTOT + col0;

    float acc[2][4][4];
#pragma unroll
    for (int a = 0; a < 2; a++)
#pragma unroll
        for (int b = 0; b < 4; b++)
#pragma unroll
            for (int cc = 0; cc < 4; cc++) acc[a][b][cc] = 0.f;

    const int NIT = LREF/64;   // 6
    auto stage = [&](int it) {
        unsigned off = (it & 1) * 16384;
        for (int c = tid; c < 1024; c += 512) {
            int ra = c >> 3, gA = c & 7;
            cpa16(sA + off + ra*128 + ((gA ^ (ra&7))<<4), ga + (size_t)ra*LREF + it*64 + gA*8);
            int rb = c >> 4, gB = c & 15;
            cpa16(sB + off + rb*256 + ((gB ^ (rb&7))<<4), gv + (size_t)(it*64 + rb)*KTOT + gB*8);
        }
        cpa_commit();
    };
    stage(0);
    for (int it = 0; it < NIT; it++) {
        if (it + 1 < NIT) { stage(it + 1); cpa_wait<1>(); }
        else cpa_wait<0>();
        __syncthreads();
        unsigned off = (it & 1) * 16384;
#pragma unroll
        for (int kk = 0; kk < 4; kk++)
            wstep_t<2,4>(acc, sA + off, sB + off, wm*32, wn*32, kk*16, lane);
        __syncthreads();
    }

#pragma unroll
    for (int mt = 0; mt < 2; mt++)
#pragma unroll
        for (int nt = 0; nt < 4; nt++) {
            float* ac = acc[mt][nt];
            int c = col0 + wn*32 + nt*8 + 2*(lane & 3);
            int n = c >> 5, d = c & 31;
#pragma unroll
            for (int half = 0; half < 2; half++) {
                int i = i0 + wm*32 + mt*16 + (lane >> 2) + half*8;
                *(bf162*)&g_omb[((size_t)n*LREF + i)*DPC + h*DHD + d] =
                    __floats2bfloat162_rn(ac[half*2+0], ac[half*2+1]);
            }
        }
}

// -------- kernel E: y = (gate .* om) @ Wo^T + bo, write transposed -----------
__global__ void __launch_bounds__(512,2) out_kernel(
    const float* __restrict__ Wo, const float* __restrict__ bo, float* __restrict__ outp)
{
    extern __shared__ unsigned char sm[];
    unsigned sXa = (unsigned)__cvta_generic_to_shared(sm);   // 2 x 16KB
    unsigned sWa = sXa + 32768;                              // 2 x 16KB
    int tid = threadIdx.x, lane = tid & 31, warp = tid >> 5;
    int wm = warp & 3, wn = warp >> 2;
    int row0 = blockIdx.x * 128;

    // stage X = gate .* om (128 rows x 128 bf16) swizzled, both k-chunks
    for (int idx = tid; idx < 2048; idx += 512) {
        int r = idx >> 4, g16 = idx & 15;
        size_t goff = (size_t)(row0 + r) * DPC + g16*8;
        uint4 gt = *(const uint4*)&g_gateb[goff];
        uint4 ot = *(const uint4*)&g_omb[goff];
        uint4 o;
        ((bf162*)&o)[0] = __hmul2(((bf162*)&gt)[0], ((bf162*)&ot)[0]);
        ((bf162*)&o)[1] = __hmul2(((bf162*)&gt)[1], ((bf162*)&ot)[1]);
        ((bf162*)&o)[2] = __hmul2(((bf162*)&gt)[2], ((bf162*)&ot)[2]);
        ((bf162*)&o)[3] = __hmul2(((bf162*)&gt)[3], ((bf162*)&ot)[3]);
        int kc = g16 >> 3, gg = g16 & 7;
        *(uint4*)(sm + kc*16384 + r*128 + ((gg ^ (r&7))<<4)) = o;
    }
    // stage Wo (128x128) bf16, both k-chunks
    for (int idx = tid; idx < 2048; idx += 512) {
        int r = idx >> 4, g16 = idx & 15;
        int kc = g16 >> 3, gg = g16 & 7;
        const float* src = Wo + (size_t)r*DPC + kc*64 + gg*8;
        float4 t0 = *(const float4*)src;
        float4 t1 = *(const float4*)(src + 4);
        uint4 o;
        o.x = pk2(t0.x, t0.y); o.y = pk2(t0.z, t0.w);
        o.z = pk2(t1.x, t1.y); o.w = pk2(t1.z, t1.w);
        *(uint4*)(sm + 32768 + kc*16384 + r*128 + ((gg ^ (r&7))<<4)) = o;
    }
    __syncthreads();

    float acc[2][4][4];
#pragma unroll
    for (int a = 0; a < 2; a++)
#pragma unroll
        for (int b = 0; b < 4; b++)
#pragma unroll
            for (int cc = 0; cc < 4; cc++) acc[a][b][cc] = 0.f;

#pragma unroll
    for (int kc = 0; kc < 2; kc++)
#pragma unroll
        for (int kk = 0; kk < 4; kk++)
            wstep<2,4>(acc, sXa + kc*16384, sWa + kc*16384, wm*32, wn*32, kk*16, lane);

#pragma unroll
    for (int mt = 0; mt < 2; mt++)
#pragma unroll
        for (int nt = 0; nt < 4; nt++) {
            float* ac = acc[mt][nt];
            int rl = wm*32 + mt*16 + (lane >> 2);
            int c  = wn*32 + nt*8 + 2*(lane & 3);
            float b0 = bo[c], b1 = bo[c+1];
#pragma unroll
            for (int half = 0; half < 2; half++) {
                int row = row0 + rl + half*8;
                int n = row / LREF, i = row - n*LREF;
                *(float2*)&outp[((size_t)i*LREF + n)*DPC + c] =
                    make_float2(ac[half*2+0] + b0, ac[half*2+1] + b1);
            }
        }
}

extern "C" void kernel_launch(void* const* d_in, const int* in_sizes, int n_in,
                              void* d_out, int out_size)
{
    (void)in_sizes; (void)n_in; (void)out_size;
    const float* pair      = (const float*)d_in[0];
    const float* bias      = (const float*)d_in[1];
    const float* ln_pair_g = (const float*)d_in[2];
    const float* ln_pair_b = (const float*)d_in[3];
    const float* ln_bias_g = (const float*)d_in[4];
    const float* ln_bias_b = (const float*)d_in[5];
    const float* Wq = (const float*)d_in[6];
    const float* Wk = (const float*)d_in[7];
    const float* Wv = (const float*)d_in[8];
    const float* Wb = (const float*)d_in[9];
    const float* Wg = (const float*)d_in[10];
    const float* bg = (const float*)d_in[11];
    const float* Wo = (const float*)d_in[12];
    const float* bo = (const float*)d_in[13];
    float* outp = (float*)d_out;

    const int SMEM = 65536;
    cudaFuncSetAttribute(pb_kernel,    cudaFuncAttributeMaxDynamicSharedMemorySize, SMEM);
    cudaFuncSetAttribute(score_kernel, cudaFuncAttributeMaxDynamicSharedMemorySize, SMEM);
    cudaFuncSetAttribute(av_kernel,    cudaFuncAttributeMaxDynamicSharedMemorySize, SMEM);
    cudaFuncSetAttribute(out_kernel,   cudaFuncAttributeMaxDynamicSharedMemorySize, SMEM);

    pb_kernel<<<NB_PROJ + NB_BIAS, 512, SMEM>>>(pair, bias,
        ln_pair_g, ln_pair_b, ln_bias_g, ln_bias_b, Wq, Wk, Wv, Wg, bg, Wb);
    score_kernel<<<dim3(3, 3, 32), 512, SMEM>>>();
    softmax_kernel<<<dim3(LREF, HN), 128>>>();
    av_kernel<<<dim3(3, KTOT/128, HN), 512, SMEM>>>();
    out_kernel<<<LREF*LREF/128, 512, SMEM>>>(Wo, bo, outp);
}

// round 9
// speedup vs baseline: 1.5798x; 1.1757x over previous
#include <cuda_runtime.h>
#include <cuda_bf16.h>
#include <math.h>

#define LREF 384
#define DPC 128
#define HN 4
#define DHD 32
#define KTOT (LREF*DHD)   // 12288

typedef __nv_bfloat16 bf16;
typedef __nv_bfloat162 bf162;

#define NB_PROJ (LREF*LREF/128)   // 1152
#define NB_BIAS (LREF*LREF/32)    // 4608

// ---------------- scratch (device globals) ----------------------------------
__device__ unsigned char g_q8[(size_t)HN*LREF*KTOT]; // [h][i][n*32+d] e4m3, unscaled
__device__ unsigned char g_k8[(size_t)HN*LREF*KTOT]; // [h][j][n*32+d] e4m3, unscaled
__device__ bf16 g_v2[(size_t)HN*KTOT*LREF];     // [h][col=n*32+d][j]  K-major(j)
__device__ bf16 g_gateb[(size_t)LREF*LREF*DPC]; // [row=n*L+i][c]
__device__ bf16 g_omb[(size_t)LREF*LREF*DPC];   // [row=n*L+i][h*32+d]
__device__ float g_attn[(size_t)HN*LREF*LREF];  // fp32 logits (bias-init + atomics)
__device__ bf16 g_attnb[(size_t)HN*LREF*LREF];  // softmaxed, bf16

// ---------------- ptx helpers ------------------------------------------------
__device__ __forceinline__ void ldsm4(unsigned &r0,unsigned &r1,unsigned &r2,unsigned &r3,unsigned a){
    asm volatile("ldmatrix.sync.aligned.m8n8.x4.shared.b16 {%0,%1,%2,%3},[%4];"
        :"=r"(r0),"=r"(r1),"=r"(r2),"=r"(r3):"r"(a));
}
__device__ __forceinline__ void mma_bf16(float c[4], const unsigned a[4], const unsigned b[2]){
    asm volatile("mma.sync.aligned.m16n8k16.row.col.f32.bf16.bf16.f32 "
        "{%0,%1,%2,%3},{%4,%5,%6,%7},{%8,%9},{%0,%1,%2,%3};"
        :"+f"(c[0]),"+f"(c[1]),"+f"(c[2]),"+f"(c[3])
        :"r"(a[0]),"r"(a[1]),"r"(a[2]),"r"(a[3]),"r"(b[0]),"r"(b[1]));
}
__device__ __forceinline__ void mma_fp8(float c[4], const unsigned a[4], const unsigned b[2]){
    asm volatile("mma.sync.aligned.m16n8k32.row.col.f32.e4m3.e4m3.f32 "
        "{%0,%1,%2,%3},{%4,%5,%6,%7},{%8,%9},{%0,%1,%2,%3};"
        :"+f"(c[0]),"+f"(c[1]),"+f"(c[2]),"+f"(c[3])
        :"r"(a[0]),"r"(a[1]),"r"(a[2]),"r"(a[3]),"r"(b[0]),"r"(b[1]));
}
__device__ __forceinline__ void cpa16(unsigned saddr, const void* g) {
    asm volatile("cp.async.cg.shared.global [%0],[%1],16;\n" :: "r"(saddr), "l"(g));
}
__device__ __forceinline__ void cpa_commit() { asm volatile("cp.async.commit_group;\n"); }
template<int N>
__device__ __forceinline__ void cpa_wait() { asm volatile("cp.async.wait_group %0;\n" :: "n"(N)); }

__device__ __forceinline__ unsigned pk2(float a, float b){
    bf162 t = __floats2bfloat162_rn(a, b);
    return *(unsigned*)&t;
}
__device__ __forceinline__ unsigned short pk8(float lo, float hi){
    unsigned short u;
    asm("cvt.rn.satfinite.e4m3x2.f32 %0, %2, %1;" : "=h"(u) : "f"(lo), "f"(hi));
    return u;
}

// warp k16-step (bf16): A rows 128B [m][k64], B rows 128B [n][k64], SW128-swizzled
template<int MT,int NT>
__device__ __forceinline__ void wstep(float (&acc)[MT][NT][4], unsigned sA, unsigned sB,
                                      int m0, int n0, int k0, int lane)
{
    unsigned a[MT][4];
    int arow = lane & 15, acg = (k0>>3) + (lane>>4);
#pragma unroll
    for (int mt = 0; mt < MT; mt++) {
        int r = m0 + mt*16 + arow;
        ldsm4(a[mt][0],a[mt][1],a[mt][2],a[mt][3], sA + r*128 + ((acg ^ (r&7))<<4));
    }
    int brow_off = (lane & 7) + ((lane>>4)<<3);
    int bcg = (k0>>3) + ((lane>>3)&1);
#pragma unroll
    for (int nt = 0; nt < NT; nt += 2) {
        int r = n0 + nt*8 + brow_off;
        unsigned b[4];
        ldsm4(b[0],b[1],b[2],b[3], sB + r*128 + ((bcg ^ (r&7))<<4));
#pragma unroll
        for (int mt = 0; mt < MT; mt++) {
            mma_bf16(acc[mt][nt],   a[mt], b);
            mma_bf16(acc[mt][nt+1], a[mt], b+2);
        }
    }
}

// warp k32-step (fp8): A rows 128B [m][k128 bytes], B rows 128B [n][k128 bytes]
template<int MT,int NT>
__device__ __forceinline__ void wstep8(float (&acc)[MT][NT][4], unsigned sA, unsigned sB,
                                       int m0, int n0, int kb, int lane)
{
    unsigned a[MT][4];
    int arow = lane & 15, acg = (kb>>4) + (lane>>4);
#pragma unroll
    for (int mt = 0; mt < MT; mt++) {
        int r = m0 + mt*16 + arow;
        ldsm4(a[mt][0],a[mt][1],a[mt][2],a[mt][3], sA + r*128 + ((acg ^ (r&7))<<4));
    }
    int brow_off = (lane & 7) + ((lane>>4)<<3);
    int bcg = (kb>>4) + ((lane>>3)&1);
#pragma unroll
    for (int nt = 0; nt < NT; nt += 2) {
        int r = n0 + nt*8 + brow_off;
        unsigned b[4];
        ldsm4(b[0],b[1],b[2],b[3], sB + r*128 + ((bcg ^ (r&7))<<4));
#pragma unroll
        for (int mt = 0; mt < MT; mt++) {
            mma_fp8(acc[mt][nt],   a[mt], b);
            mma_fp8(acc[mt][nt+1], a[mt], b+2);
        }
    }
}

// -------- fused kernel A: proj (blocks 0..NB_PROJ) + bias (rest) -------------
__global__ void __launch_bounds__(512,2) pb_kernel(
    const float* __restrict__ pair, const float* __restrict__ biasp,
    const float* __restrict__ lnpg, const float* __restrict__ lnpb,
    const float* __restrict__ lnbg, const float* __restrict__ lnbb,
    const float* __restrict__ Wq, const float* __restrict__ Wk, const float* __restrict__ Wv,
    const float* __restrict__ Wg, const float* __restrict__ bg,
    const float* __restrict__ Wb)
{
    extern __shared__ unsigned char sm[];
    int tid = threadIdx.x, lane = tid & 31, wid = tid >> 5;

    if (blockIdx.x < NB_PROJ) {
        // ================= proj =================
        unsigned sXa = (unsigned)__cvta_generic_to_shared(sm);   // 2 x 16KB LN'ed X
        unsigned sWa = sXa + 32768;                              // 2 x 16KB W (also staging)
        int wm = wid & 3, wn = wid >> 2;     // 4m x 4n warps, tile 32x32
        int row0 = blockIdx.x * 128;
        int nn = row0 / LREF, i0b = row0 % LREF;

        // warp-cooperative single-pass LN: warp handles 8 rows
        for (int rr = 0; rr < 8; rr++) {
            int r = wid * 8 + rr;
            int i = i0b + r;
            const float* x = pair + ((size_t)i*LREF + nn) * DPC;
            float4 t = *(const float4*)(x + lane*4);
            float s  = t.x + t.y + t.z + t.w;
            float s2 = t.x*t.x + t.y*t.y + t.z*t.z + t.w*t.w;
#pragma unroll
            for (int o = 16; o; o >>= 1) {
                s  += __shfl_xor_sync(0xffffffffu, s,  o);
                s2 += __shfl_xor_sync(0xffffffffu, s2, o);
            }
            float mean = s * (1.f/DPC);
            float rstd = rsqrtf(s2 * (1.f/DPC) - mean*mean + 1e-5f);
            float4 wv = *(const float4*)(lnpg + lane*4);
            float4 bv = *(const float4*)(lnpb + lane*4);
            unsigned p0 = pk2((t.x-mean)*rstd*wv.x + bv.x, (t.y-mean)*rstd*wv.y + bv.y);
            unsigned p1 = pk2((t.z-mean)*rstd*wv.z + bv.z, (t.w-mean)*rstd*wv.w + bv.w);
            int kc = lane >> 4, g = (lane & 15) >> 1;
            *(uint2*)(sm + kc*16384 + r*128 + ((g ^ (r&7))<<4) + (lane&1)*8) = make_uint2(p0, p1);
        }
        __syncthreads();

        const float* Ws[4] = { Wq, Wk, Wv, Wg };
        for (int mat = 0; mat < 4; mat++) {
            // stage whole W (128x128) bf16, both K chunks (staging area free here)
            for (int idx = tid; idx < 2048; idx += 512) {
                int r = idx >> 4, g16 = idx & 15;
                int kc = g16 >> 3, gg = g16 & 7;
                const float* src = Ws[mat] + (size_t)r*DPC + kc*64 + gg*8;
                float4 t0 = *(const float4*)src;
                float4 t1 = *(const float4*)(src + 4);
                uint4 o;
                o.x = pk2(t0.x,t0.y); o.y = pk2(t0.z,t0.w);
                o.z = pk2(t1.x,t1.y); o.w = pk2(t1.z,t1.w);
                *(uint4*)(sm + 32768 + kc*16384 + r*128 + ((gg ^ (r&7))<<4)) = o;
            }
            __syncthreads();

            float acc[2][4][4];
#pragma unroll
            for (int a = 0; a < 2; a++)
#pragma unroll
                for (int b = 0; b < 4; b++)
#pragma unroll
                    for (int cc = 0; cc < 4; cc++) acc[a][b][cc] = 0.f;
#pragma unroll
            for (int kc = 0; kc < 2; kc++)
#pragma unroll
                for (int kk = 0; kk < 4; kk++)
                    wstep<2,4>(acc, sXa + kc*16384, sWa + kc*16384, wm*32, wn*32, kk*16, lane);
            __syncthreads();   // all warps done reading sW; reuse as staging

            // ---- stage results to smem (overwrites sW region) ----
            unsigned char* smT8 = sm + 32768;          // fp8 [i][c] 16KB
            bf16* smT16 = (bf16*)(sm + 32768);         // bf16 32KB
#pragma unroll
            for (int mt = 0; mt < 2; mt++)
#pragma unroll
                for (int nt = 0; nt < 4; nt++) {
                    float* ac = acc[mt][nt];
                    int rl = wm*32 + mt*16 + (lane >> 2);
                    int c  = wn*32 + nt*8 + 2*(lane & 3);
#pragma unroll
                    for (int half = 0; half < 2; half++) {
                        int il = rl + half*8;
                        float v0 = ac[half*2+0], v1 = ac[half*2+1];
                        if (mat < 2) {
                            *(unsigned short*)&smT8[il*128 + c] = pk8(v0, v1);
                        } else if (mat == 2) {
                            // transpose: [c][il] for K-major v2
                            smT16[(c)  *128 + il] = __float2bfloat16_rn(v0);
                            smT16[(c+1)*128 + il] = __float2bfloat16_rn(v1);
                        } else {
                            float z0 = v0 + bg[c], z1 = v1 + bg[c+1];
                            *(bf162*)&smT16[il*128 + c] =
                                __floats2bfloat162_rn(1.f/(1.f+expf(-z0)), 1.f/(1.f+expf(-z1)));
                        }
                    }
                }
            __syncthreads();

            // ---- coalesced global writes ----
            if (mat < 2) {
                unsigned char* dst = (mat == 0) ? g_q8 : g_k8;
                // 128 rows x 128B, 4B per thread, 8 iters
#pragma unroll
                for (int k = 0; k < 8; k++) {
                    int idx = tid + k*512;           // 0..4095
                    int i = idx >> 5, seg = idx & 31; // seg: 4B unit
                    int c4 = seg*4;
                    int hh = c4 >> 5, d = c4 & 31;
                    *(unsigned*)&dst[((size_t)(hh*LREF + i0b + i))*KTOT + nn*DHD + d] =
                        *(unsigned*)&smT8[i*128 + c4];
                }
            } else if (mat == 2) {
                // v2: 128 cols x 256B per col, 16B per thread, 16 segs/col, 4 iters
#pragma unroll
                for (int k = 0; k < 4; k++) {
                    int idx = tid + k*512;           // 0..2047
                    int col = idx >> 4, seg = idx & 15;  // seg: 16B unit (8 bf16)
                    int hh = col >> 5, d = col & 31;
                    *(uint4*)&g_v2[((size_t)hh*KTOT + nn*DHD + d)*LREF + i0b + seg*8] =
                        *(uint4*)&smT16[col*128 + seg*8];
                }
            } else {
                // gate: 128 rows x 256B, 16B per thread, 4 iters
#pragma unroll
                for (int k = 0; k < 4; k++) {
                    int idx = tid + k*512;
                    int i = idx >> 4, seg = idx & 15;
                    *(uint4*)&g_gateb[((size_t)(nn*LREF + i0b + i))*DPC + seg*8] =
                        *(uint4*)&smT16[i*128 + seg*8];
                }
            }
            __syncthreads();   // staging region free for next W
        }
    } else {
        // ================= bias =================
        float* sWb = (float*)sm;           // 4*128 floats
        int bid = blockIdx.x - NB_PROJ;
        for (int c = tid; c < 4*DPC; c += 512) sWb[c] = Wb[c];
        __syncthreads();

        float4 wg = *(const float4*)(lnbg + lane*4);
        float4 wb = *(const float4*)(lnbb + lane*4);
        float4 W0 = *(const float4*)(sWb + 0*DPC + lane*4);
        float4 W1 = *(const float4*)(sWb + 1*DPC + lane*4);
        float4 W2 = *(const float4*)(sWb + 2*DPC + lane*4);
        float4 W3 = *(const float4*)(sWb + 3*DPC + lane*4);

        for (int rr = 0; rr < 2; rr++) {
            int row = bid*32 + wid*2 + rr;    // row = i*L + j
            int i = row / LREF, j = row - i*LREF;
            const float* x = biasp + ((size_t)j*LREF + i) * DPC;
            float4 t = *(const float4*)(x + lane*4);
            float s  = t.x + t.y + t.z + t.w;
            float s2 = t.x*t.x + t.y*t.y + t.z*t.z + t.w*t.w;
#pragma unroll
            for (int o = 16; o; o >>= 1) {
                s  += __shfl_xor_sync(0xffffffffu, s,  o);
                s2 += __shfl_xor_sync(0xffffffffu, s2, o);
            }
            float mean = s * (1.f/DPC);
            float rstd = rsqrtf(s2 * (1.f/DPC) - mean*mean + 1e-5f);
            float e0 = (t.x-mean)*rstd*wg.x + wb.x;
            float e1 = (t.y-mean)*rstd*wg.y + wb.y;
            float e2 = (t.z-mean)*rstd*wg.z + wb.z;
            float e3 = (t.w-mean)*rstd*wg.w + wb.w;
            float p0 = e0*W0.x + e1*W0.y + e2*W0.z + e3*W0.w;
            float p1 = e0*W1.x + e1*W1.y + e2*W1.z + e3*W1.w;
            float p2 = e0*W2.x + e1*W2.y + e2*W2.z + e3*W2.w;
            float p3 = e0*W3.x + e1*W3.y + e2*W3.z + e3*W3.w;
#pragma unroll
            for (int o = 16; o; o >>= 1) {
                p0 += __shfl_xor_sync(0xffffffffu, p0, o);
                p1 += __shfl_xor_sync(0xffffffffu, p1, o);
                p2 += __shfl_xor_sync(0xffffffffu, p2, o);
                p3 += __shfl_xor_sync(0xffffffffu, p3, o);
            }
            if (lane == 0) {
                g_attn[((size_t)0*LREF + i)*LREF + j] = p0;
                g_attn[((size_t)1*LREF + i)*LREF + j] = p1;
                g_attn[((size_t)2*LREF + i)*LREF + j] = p2;
                g_attn[((size_t)3*LREF + i)*LREF + j] = p3;
            }
        }
    }
}

// -------- kernel C: attn += scale*(q8.k8)  (128x128 tiles, split-K 8, fp8) ---
__global__ void __launch_bounds__(512,2) score_kernel()
{
    extern __shared__ unsigned char sm[];
    unsigned sA = (unsigned)__cvta_generic_to_shared(sm);     // 2 x 16KB
    unsigned sB = sA + 32768;                                 // 2 x 16KB
    int tid = threadIdx.x, lane = tid & 31, warp = tid >> 5;
    int wm = warp & 3, wn = warp >> 2;
    int h = blockIdx.z >> 3, ks = blockIdx.z & 7;
    int i0 = blockIdx.x * 128, j0 = blockIdx.y * 128;

    const unsigned char* ga = g_q8 + ((size_t)(h*LREF + i0))*KTOT + ks*(KTOT/8);
    const unsigned char* gb = g_k8 + ((size_t)(h*LREF + j0))*KTOT + ks*(KTOT/8);

    float acc[2][4][4];
#pragma unroll
    for (int a = 0; a < 2; a++)
#pragma unroll
        for (int b = 0; b < 4; b++)
#pragma unroll
            for (int cc = 0; cc < 4; cc++) acc[a][b][cc] = 0.f;

    const int NIT = (KTOT/8)/128;   // 12 iterations of k=128 bytes
    auto stage = [&](int it) {
        unsigned off = (it & 1) * 16384;
        for (int c = tid; c < 1024; c += 512) {
            int r = c >> 3, g = c & 7;
            unsigned d = r*128 + ((g ^ (r&7))<<4);
            cpa16(sA + off + d, ga + (size_t)r*KTOT + it*128 + g*16);
            cpa16(sB + off + d, gb + (size_t)r*KTOT + it*128 + g*16);
        }
        cpa_commit();
    };
    stage(0);
    for (int it = 0; it < NIT; it++) {
        if (it + 1 < NIT) { stage(it + 1); cpa_wait<1>(); }
        else cpa_wait<0>();
        __syncthreads();
        unsigned off = (it & 1) * 16384;
#pragma unroll
        for (int kk = 0; kk < 4; kk++)
            wstep8<2,4>(acc, sA + off, sB + off, wm*32, wn*32, kk*32, lane);
        __syncthreads();
    }

    const float SC = 0.17677669529663687f / 384.0f;
#pragma unroll
    for (int mt = 0; mt < 2; mt++)
#pragma unroll
        for (int nt = 0; nt < 4; nt++) {
            float* ac = acc[mt][nt];
            int r = i0 + wm*32 + mt*16 + (lane >> 2);
            int c = j0 + wn*32 + nt*8 + 2*(lane & 3);
            size_t base = ((size_t)h*LREF + r)*LREF + c;
            atomicAdd(&g_attn[base],            ac[0]*SC);
            atomicAdd(&g_attn[base + 1],        ac[1]*SC);
            atomicAdd(&g_attn[base + 8*LREF],   ac[2]*SC);
            atomicAdd(&g_attn[base + 8*LREF+1], ac[3]*SC);
        }
}

// -------- softmax over j per (h,i): fp32 in, bf16 out ------------------------
__global__ void __launch_bounds__(128) softmax_kernel()
{
    int i = blockIdx.x, h = blockIdx.y;
    const float* row = g_attn + ((size_t)h * LREF + i) * LREF;
    bf16* orow = g_attnb + ((size_t)h * LREF + i) * LREF;
    int tid = threadIdx.x, warp = tid >> 5, lane = tid & 31;
    __shared__ float smax[4], ssum[4];

    float a0 = row[tid], a1 = row[tid + 128], a2 = row[tid + 256];
    float m = fmaxf(a0, fmaxf(a1, a2));
#pragma unroll
    for (int o = 16; o; o >>= 1) m = fmaxf(m, __shfl_xor_sync(0xffffffffu, m, o));
    if (lane == 0) smax[warp] = m;
    __syncthreads();
    float M = fmaxf(fmaxf(smax[0], smax[1]), fmaxf(smax[2], smax[3]));

    float e0 = expf(a0 - M), e1 = expf(a1 - M), e2 = expf(a2 - M);
    float s = e0 + e1 + e2;
#pragma unroll
    for (int o = 16; o; o >>= 1) s += __shfl_xor_sync(0xffffffffu, s, o);
    if (lane == 0) ssum[warp] = s;
    __syncthreads();
    float S = ssum[0] + ssum[1] + ssum[2] + ssum[3];
    float inv = 1.f / S;
    orow[tid]       = __float2bfloat16_rn(e0 * inv);
    orow[tid + 128] = __float2bfloat16_rn(e1 * inv);
    orow[tid + 256] = __float2bfloat16_rn(e2 * inv);
}

// -------- kernel D: om = attn_b[h] @ v2^T, both operands K-major(j) ----------
__global__ void __launch_bounds__(512,2) av_kernel()
{
    extern __shared__ unsigned char sm[];
    unsigned sA = (unsigned)__cvta_generic_to_shared(sm);     // 2 x 16KB
    unsigned sB = sA + 32768;                                 // 2 x 16KB
    int tid = threadIdx.x, lane = tid & 31, warp = tid >> 5;
    int wm = warp & 3, wn = warp >> 2;
    int i0 = blockIdx.x * 128, col0 = blockIdx.y * 128, h = blockIdx.z;

    const bf16* ga = g_attnb + ((size_t)(h*LREF + i0))*LREF;
    const bf16* gv = g_v2 + ((size_t)h*KTOT + col0)*LREF;

    float acc[2][4][4];
#pragma unroll
    for (int a = 0; a < 2; a++)
#pragma unroll
        for (int b = 0; b < 4; b++)
#pragma unroll
            for (int cc = 0; cc < 4; cc++) acc[a][b][cc] = 0.f;

    const int NIT = LREF/64;   // 6
    auto stage = [&](int it) {
        unsigned off = (it & 1) * 16384;
        for (int c = tid; c < 1024; c += 512) {
            int r = c >> 3, g = c & 7;
            unsigned d = r*128 + ((g ^ (r&7))<<4);
            cpa16(sA + off + d, ga + (size_t)r*LREF + it*64 + g*8);
            cpa16(sB + off + d, gv + (size_t)r*LREF + it*64 + g*8);
        }
        cpa_commit();
    };
    stage(0);
    for (int it = 0; it < NIT; it++) {
        if (it + 1 < NIT) { stage(it + 1); cpa_wait<1>(); }
        else cpa_wait<0>();
        __syncthreads();
        unsigned off = (it & 1) * 16384;
#pragma unroll
        for (int kk = 0; kk < 4; kk++)
            wstep<2,4>(acc, sA + off, sB + off, wm*32, wn*32, kk*16, lane);
        __syncthreads();
    }

#pragma unroll
    for (int mt = 0; mt < 2; mt++)
#pragma unroll
        for (int nt = 0; nt < 4; nt++) {
            float* ac = acc[mt][nt];
            int c = col0 + wn*32 + nt*8 + 2*(lane & 3);
            int n = c >> 5, d = c & 31;
#pragma unroll
            for (int half = 0; half < 2; half++) {
                int i = i0 + wm*32 + mt*16 + (lane >> 2) + half*8;
                *(bf162*)&g_omb[((size_t)n*LREF + i)*DPC + h*DHD + d] =
                    __floats2bfloat162_rn(ac[half*2+0], ac[half*2+1]);
            }
        }
}

// -------- kernel E: y = (gate .* om) @ Wo^T + bo, write transposed -----------
__global__ void __launch_bounds__(512,2) out_kernel(
    const float* __restrict__ Wo, const float* __restrict__ bo, float* __restrict__ outp)
{
    extern __shared__ unsigned char sm[];
    unsigned sXa = (unsigned)__cvta_generic_to_shared(sm);   // 2 x 16KB
    unsigned sWa = sXa + 32768;                              // 2 x 16KB
    int tid = threadIdx.x, lane = tid & 31, warp = tid >> 5;
    int wm = warp & 3, wn = warp >> 2;
    int row0 = blockIdx.x * 128;

    // stage X = gate .* om (128 rows x 128 bf16) swizzled, both k-chunks
    for (int idx = tid; idx < 2048; idx += 512) {
        int r = idx >> 4, g16 = idx & 15;
        size_t goff = (size_t)(row0 + r) * DPC + g16*8;
        uint4 gt = *(const uint4*)&g_gateb[goff];
        uint4 ot = *(const uint4*)&g_omb[goff];
        uint4 o;
        ((bf162*)&o)[0] = __hmul2(((bf162*)&gt)[0], ((bf162*)&ot)[0]);
        ((bf162*)&o)[1] = __hmul2(((bf162*)&gt)[1], ((bf162*)&ot)[1]);
        ((bf162*)&o)[2] = __hmul2(((bf162*)&gt)[2], ((bf162*)&ot)[2]);
        ((bf162*)&o)[3] = __hmul2(((bf162*)&gt)[3], ((bf162*)&ot)[3]);
        int kc = g16 >> 3, gg = g16 & 7;
        *(uint4*)(sm + kc*16384 + r*128 + ((gg ^ (r&7))<<4)) = o;
    }
    // stage Wo (128x128) bf16, both k-chunks
    for (int idx = tid; idx < 2048; idx += 512) {
        int r = idx >> 4, g16 = idx & 15;
        int kc = g16 >> 3, gg = g16 & 7;
        const float* src = Wo + (size_t)r*DPC + kc*64 + gg*8;
        float4 t0 = *(const float4*)src;
        float4 t1 = *(const float4*)(src + 4);
        uint4 o;
        o.x = pk2(t0.x, t0.y); o.y = pk2(t0.z, t0.w);
        o.z = pk2(t1.x, t1.y); o.w = pk2(t1.z, t1.w);
        *(uint4*)(sm + 32768 + kc*16384 + r*128 + ((gg ^ (r&7))<<4)) = o;
    }
    __syncthreads();

    float acc[2][4][4];
#pragma unroll
    for (int a = 0; a < 2; a++)
#pragma unroll
        for (int b = 0; b < 4; b++)
#pragma unroll
            for (int cc = 0; cc < 4; cc++) acc[a][b][cc] = 0.f;

#pragma unroll
    for (int kc = 0; kc < 2; kc++)
#pragma unroll
        for (int kk = 0; kk < 4; kk++)
            wstep<2,4>(acc, sXa + kc*16384, sWa + kc*16384, wm*32, wn*32, kk*16, lane);

#pragma unroll
    for (int mt = 0; mt < 2; mt++)
#pragma unroll
        for (int nt = 0; nt < 4; nt++) {
            float* ac = acc[mt][nt];
            int rl = wm*32 + mt*16 + (lane >> 2);
            int c  = wn*32 + nt*8 + 2*(lane & 3);
            float b0 = bo[c], b1 = bo[c+1];
#pragma unroll
            for (int half = 0; half < 2; half++) {
                int row = row0 + rl + half*8;
                int n = row / LREF, i = row - n*LREF;
                *(float2*)&outp[((size_t)i*LREF + n)*DPC + c] =
                    make_float2(ac[half*2+0] + b0, ac[half*2+1] + b1);
            }
        }
}

extern "C" void kernel_launch(void* const* d_in, const int* in_sizes, int n_in,
                              void* d_out, int out_size)
{
    (void)in_sizes; (void)n_in; (void)out_size;
    const float* pair      = (const float*)d_in[0];
    const float* bias      = (const float*)d_in[1];
    const float* ln_pair_g = (const float*)d_in[2];
    const float* ln_pair_b = (const float*)d_in[3];
    const float* ln_bias_g = (const float*)d_in[4];
    const float* ln_bias_b = (const float*)d_in[5];
    const float* Wq = (const float*)d_in[6];
    const float* Wk = (const float*)d_in[7];
    const float* Wv = (const float*)d_in[8];
    const float* Wb = (const float*)d_in[9];
    const float* Wg = (const float*)d_in[10];
    const float* bg = (const float*)d_in[11];
    const float* Wo = (const float*)d_in[12];
    const float* bo = (const float*)d_in[13];
    float* outp = (float*)d_out;

    const int SMEM = 65536;
    cudaFuncSetAttribute(pb_kernel,    cudaFuncAttributeMaxDynamicSharedMemorySize, SMEM);
    cudaFuncSetAttribute(score_kernel, cudaFuncAttributeMaxDynamicSharedMemorySize, SMEM);
    cudaFuncSetAttribute(av_kernel,    cudaFuncAttributeMaxDynamicSharedMemorySize, SMEM);
    cudaFuncSetAttribute(out_kernel,   cudaFuncAttributeMaxDynamicSharedMemorySize, SMEM);

    pb_kernel<<<NB_PROJ + NB_BIAS, 512, SMEM>>>(pair, bias,
        ln_pair_g, ln_pair_b, ln_bias_g, ln_bias_b, Wq, Wk, Wv, Wg, bg, Wb);
    score_kernel<<<dim3(3, 3, 32), 512, SMEM>>>();
    softmax_kernel<<<dim3(LREF, HN), 128>>>();
    av_kernel<<<dim3(3, KTOT/128, HN), 512, SMEM>>>();
    out_kernel<<<LREF*LREF/128, 512, SMEM>>>(Wo, bo, outp);
}

// round 10
// speedup vs baseline: 1.6033x; 1.0149x over previous
#include <cuda_runtime.h>
#include <cuda_bf16.h>
#include <math.h>

#define LREF 384
#define DPC 128
#define HN 4
#define DHD 32
#define KTOT (LREF*DHD)   // 12288

typedef __nv_bfloat16 bf16;
typedef __nv_bfloat162 bf162;

#define NB_PROJ (LREF*LREF/128)   // 1152
#define NB_BIAS (LREF*LREF/32)    // 4608

// ---------------- scratch (device globals) ----------------------------------
__device__ unsigned char g_q8[(size_t)HN*LREF*KTOT]; // [h][i][n*32+d] e4m3, unscaled
__device__ unsigned char g_k8[(size_t)HN*LREF*KTOT]; // [h][j][n*32+d] e4m3, unscaled
__device__ bf16 g_v2[(size_t)HN*KTOT*LREF];     // [h][col=n*32+d][j]  K-major(j)
__device__ bf16 g_gateb[(size_t)LREF*LREF*DPC]; // [row=n*L+i][c]
__device__ bf16 g_omb[(size_t)LREF*LREF*DPC];   // [row=n*L+i][h*32+d]
__device__ float g_attn[(size_t)HN*LREF*LREF];  // fp32 logits (bias-init + atomics)
__device__ bf16 g_attnb[(size_t)HN*LREF*LREF];  // softmaxed, bf16

// ---------------- ptx helpers ------------------------------------------------
__device__ __forceinline__ void ldsm4(unsigned &r0,unsigned &r1,unsigned &r2,unsigned &r3,unsigned a){
    asm volatile("ldmatrix.sync.aligned.m8n8.x4.shared.b16 {%0,%1,%2,%3},[%4];"
        :"=r"(r0),"=r"(r1),"=r"(r2),"=r"(r3):"r"(a));
}
__device__ __forceinline__ void mma_bf16(float c[4], const unsigned a[4], const unsigned b[2]){
    asm volatile("mma.sync.aligned.m16n8k16.row.col.f32.bf16.bf16.f32 "
        "{%0,%1,%2,%3},{%4,%5,%6,%7},{%8,%9},{%0,%1,%2,%3};"
        :"+f"(c[0]),"+f"(c[1]),"+f"(c[2]),"+f"(c[3])
        :"r"(a[0]),"r"(a[1]),"r"(a[2]),"r"(a[3]),"r"(b[0]),"r"(b[1]));
}
__device__ __forceinline__ void mma_fp8(float c[4], const unsigned a[4], const unsigned b[2]){
    asm volatile("mma.sync.aligned.m16n8k32.row.col.f32.e4m3.e4m3.f32 "
        "{%0,%1,%2,%3},{%4,%5,%6,%7},{%8,%9},{%0,%1,%2,%3};"
        :"+f"(c[0]),"+f"(c[1]),"+f"(c[2]),"+f"(c[3])
        :"r"(a[0]),"r"(a[1]),"r"(a[2]),"r"(a[3]),"r"(b[0]),"r"(b[1]));
}
__device__ __forceinline__ void cpa16(unsigned saddr, const void* g) {
    asm volatile("cp.async.cg.shared.global [%0],[%1],16;\n" :: "r"(saddr), "l"(g));
}
__device__ __forceinline__ void cpa_commit() { asm volatile("cp.async.commit_group;\n"); }
template<int N>
__device__ __forceinline__ void cpa_wait() { asm volatile("cp.async.wait_group %0;\n" :: "n"(N)); }

__device__ __forceinline__ unsigned pk2(float a, float b){
    bf162 t = __floats2bfloat162_rn(a, b);
    return *(unsigned*)&t;
}
__device__ __forceinline__ unsigned short pk8(float lo, float hi){
    unsigned short u;
    asm("cvt.rn.satfinite.e4m3x2.f32 %0, %2, %1;" : "=h"(u) : "f"(lo), "f"(hi));
    return u;
}

// warp k16-step (bf16): A rows 128B [m][k64], B rows 128B [n][k64], SW128-swizzled
template<int MT,int NT>
__device__ __forceinline__ void wstep(float (&acc)[MT][NT][4], unsigned sA, unsigned sB,
                                      int m0, int n0, int k0, int lane)
{
    unsigned a[MT][4];
    int arow = lane & 15, acg = (k0>>3) + (lane>>4);
#pragma unroll
    for (int mt = 0; mt < MT; mt++) {
        int r = m0 + mt*16 + arow;
        ldsm4(a[mt][0],a[mt][1],a[mt][2],a[mt][3], sA + r*128 + ((acg ^ (r&7))<<4));
    }
    int brow_off = (lane & 7) + ((lane>>4)<<3);
    int bcg = (k0>>3) + ((lane>>3)&1);
#pragma unroll
    for (int nt = 0; nt < NT; nt += 2) {
        int r = n0 + nt*8 + brow_off;
        unsigned b[4];
        ldsm4(b[0],b[1],b[2],b[3], sB + r*128 + ((bcg ^ (r&7))<<4));
#pragma unroll
        for (int mt = 0; mt < MT; mt++) {
            mma_bf16(acc[mt][nt],   a[mt], b);
            mma_bf16(acc[mt][nt+1], a[mt], b+2);
        }
    }
}

// warp k32-step (fp8): A rows 128B [m][k128 bytes], B rows 128B [n][k128 bytes]
template<int MT,int NT>
__device__ __forceinline__ void wstep8(float (&acc)[MT][NT][4], unsigned sA, unsigned sB,
                                       int m0, int n0, int kb, int lane)
{
    unsigned a[MT][4];
    int arow = lane & 15, acg = (kb>>4) + (lane>>4);
#pragma unroll
    for (int mt = 0; mt < MT; mt++) {
        int r = m0 + mt*16 + arow;
        ldsm4(a[mt][0],a[mt][1],a[mt][2],a[mt][3], sA + r*128 + ((acg ^ (r&7))<<4));
    }
    int brow_off = (lane & 7) + ((lane>>4)<<3);
    int bcg = (kb>>4) + ((lane>>3)&1);
#pragma unroll
    for (int nt = 0; nt < NT; nt += 2) {
        int r = n0 + nt*8 + brow_off;
        unsigned b[4];
        ldsm4(b[0],b[1],b[2],b[3], sB + r*128 + ((bcg ^ (r&7))<<4));
#pragma unroll
        for (int mt = 0; mt < MT; mt++) {
            mma_fp8(acc[mt][nt],   a[mt], b);
            mma_fp8(acc[mt][nt+1], a[mt], b+2);
        }
    }
}

// -------- fused kernel A: proj (blocks 0..NB_PROJ) + bias (rest) -------------
__global__ void __launch_bounds__(512,2) pb_kernel(
    const float* __restrict__ pair, const float* __restrict__ biasp,
    const float* __restrict__ lnpg, const float* __restrict__ lnpb,
    const float* __restrict__ lnbg, const float* __restrict__ lnbb,
    const float* __restrict__ Wq, const float* __restrict__ Wk, const float* __restrict__ Wv,
    const float* __restrict__ Wg, const float* __restrict__ bg,
    const float* __restrict__ Wb)
{
    extern __shared__ unsigned char sm[];
    int tid = threadIdx.x, lane = tid & 31, wid = tid >> 5;

    if (blockIdx.x < NB_PROJ) {
        // ================= proj =================
        unsigned sXa = (unsigned)__cvta_generic_to_shared(sm);   // 2 x 16KB LN'ed X
        unsigned sWa = sXa + 32768;                              // 2 x 16KB W (also staging)
        int wm = wid & 3, wn = wid >> 2;     // 4m x 4n warps, tile 32x32
        int row0 = blockIdx.x * 128;
        int nn = row0 / LREF, i0b = row0 % LREF;

        // warp-cooperative single-pass LN: warp handles 8 rows
        for (int rr = 0; rr < 8; rr++) {
            int r = wid * 8 + rr;
            int i = i0b + r;
            const float* x = pair + ((size_t)i*LREF + nn) * DPC;
            float4 t = *(const float4*)(x + lane*4);
            float s  = t.x + t.y + t.z + t.w;
            float s2 = t.x*t.x + t.y*t.y + t.z*t.z + t.w*t.w;
#pragma unroll
            for (int o = 16; o; o >>= 1) {
                s  += __shfl_xor_sync(0xffffffffu, s,  o);
                s2 += __shfl_xor_sync(0xffffffffu, s2, o);
            }
            float mean = s * (1.f/DPC);
            float rstd = rsqrtf(s2 * (1.f/DPC) - mean*mean + 1e-5f);
            float4 wv = *(const float4*)(lnpg + lane*4);
            float4 bv = *(const float4*)(lnpb + lane*4);
            unsigned p0 = pk2((t.x-mean)*rstd*wv.x + bv.x, (t.y-mean)*rstd*wv.y + bv.y);
            unsigned p1 = pk2((t.z-mean)*rstd*wv.z + bv.z, (t.w-mean)*rstd*wv.w + bv.w);
            int kc = lane >> 4, g = (lane & 15) >> 1;
            *(uint2*)(sm + kc*16384 + r*128 + ((g ^ (r&7))<<4) + (lane&1)*8) = make_uint2(p0, p1);
        }
        __syncthreads();

        const float* Ws[4] = { Wq, Wk, Wv, Wg };
        for (int mat = 0; mat < 4; mat++) {
            // stage whole W (128x128) bf16, both K chunks (staging area free here)
            for (int idx = tid; idx < 2048; idx += 512) {
                int r = idx >> 4, g16 = idx & 15;
                int kc = g16 >> 3, gg = g16 & 7;
                const float* src = Ws[mat] + (size_t)r*DPC + kc*64 + gg*8;
                float4 t0 = *(const float4*)src;
                float4 t1 = *(const float4*)(src + 4);
                uint4 o;
                o.x = pk2(t0.x,t0.y); o.y = pk2(t0.z,t0.w);
                o.z = pk2(t1.x,t1.y); o.w = pk2(t1.z,t1.w);
                *(uint4*)(sm + 32768 + kc*16384 + r*128 + ((gg ^ (r&7))<<4)) = o;
            }
            __syncthreads();

            float acc[2][4][4];
#pragma unroll
            for (int a = 0; a < 2; a++)
#pragma unroll
                for (int b = 0; b < 4; b++)
#pragma unroll
                    for (int cc = 0; cc < 4; cc++) acc[a][b][cc] = 0.f;
#pragma unroll
            for (int kc = 0; kc < 2; kc++)
#pragma unroll
                for (int kk = 0; kk < 4; kk++)
                    wstep<2,4>(acc, sXa + kc*16384, sWa + kc*16384, wm*32, wn*32, kk*16, lane);
            __syncthreads();   // all warps done reading sW; reuse as staging

            // ---- stage results to smem (overwrites sW region) ----
            unsigned char* smT8 = sm + 32768;          // fp8 [i][c] 16KB
            bf16* smT16 = (bf16*)(sm + 32768);         // bf16 32KB
#pragma unroll
            for (int mt = 0; mt < 2; mt++)
#pragma unroll
                for (int nt = 0; nt < 4; nt++) {
                    float* ac = acc[mt][nt];
                    int rl = wm*32 + mt*16 + (lane >> 2);
                    int c  = wn*32 + nt*8 + 2*(lane & 3);
#pragma unroll
                    for (int half = 0; half < 2; half++) {
                        int il = rl + half*8;
                        float v0 = ac[half*2+0], v1 = ac[half*2+1];
                        if (mat < 2) {
                            *(unsigned short*)&smT8[il*128 + c] = pk8(v0, v1);
                        } else if (mat == 2) {
                            // transpose: [c][il] for K-major v2
                            smT16[(c)  *128 + il] = __float2bfloat16_rn(v0);
                            smT16[(c+1)*128 + il] = __float2bfloat16_rn(v1);
                        } else {
                            float z0 = v0 + bg[c], z1 = v1 + bg[c+1];
                            *(bf162*)&smT16[il*128 + c] =
                                __floats2bfloat162_rn(1.f/(1.f+expf(-z0)), 1.f/(1.f+expf(-z1)));
                        }
                    }
                }
            __syncthreads();

            // ---- coalesced global writes ----
            if (mat < 2) {
                unsigned char* dst = (mat == 0) ? g_q8 : g_k8;
#pragma unroll
                for (int k = 0; k < 8; k++) {
                    int idx = tid + k*512;
                    int i = idx >> 5, seg = idx & 31;
                    int c4 = seg*4;
                    int hh = c4 >> 5, d = c4 & 31;
                    *(unsigned*)&dst[((size_t)(hh*LREF + i0b + i))*KTOT + nn*DHD + d] =
                        *(unsigned*)&smT8[i*128 + c4];
                }
            } else if (mat == 2) {
#pragma unroll
                for (int k = 0; k < 4; k++) {
                    int idx = tid + k*512;
                    int col = idx >> 4, seg = idx & 15;
                    int hh = col >> 5, d = col & 31;
                    *(uint4*)&g_v2[((size_t)hh*KTOT + nn*DHD + d)*LREF + i0b + seg*8] =
                        *(uint4*)&smT16[col*128 + seg*8];
                }
            } else {
#pragma unroll
                for (int k = 0; k < 4; k++) {
                    int idx = tid + k*512;
                    int i = idx >> 4, seg = idx & 15;
                    *(uint4*)&g_gateb[((size_t)(nn*LREF + i0b + i))*DPC + seg*8] =
                        *(uint4*)&smT16[i*128 + seg*8];
                }
            }
            __syncthreads();   // staging region free for next W
        }
    } else {
        // ================= bias =================
        float* sWb = (float*)sm;           // 4*128 floats
        int bid = blockIdx.x - NB_PROJ;
        for (int c = tid; c < 4*DPC; c += 512) sWb[c] = Wb[c];
        __syncthreads();

        float4 wg = *(const float4*)(lnbg + lane*4);
        float4 wb = *(const float4*)(lnbb + lane*4);
        float4 W0 = *(const float4*)(sWb + 0*DPC + lane*4);
        float4 W1 = *(const float4*)(sWb + 1*DPC + lane*4);
        float4 W2 = *(const float4*)(sWb + 2*DPC + lane*4);
        float4 W3 = *(const float4*)(sWb + 3*DPC + lane*4);

        for (int rr = 0; rr < 2; rr++) {
            int row = bid*32 + wid*2 + rr;    // row = i*L + j
            int i = row / LREF, j = row - i*LREF;
            const float* x = biasp + ((size_t)j*LREF + i) * DPC;
            float4 t = *(const float4*)(x + lane*4);
            float s  = t.x + t.y + t.z + t.w;
            float s2 = t.x*t.x + t.y*t.y + t.z*t.z + t.w*t.w;
#pragma unroll
            for (int o = 16; o; o >>= 1) {
                s  += __shfl_xor_sync(0xffffffffu, s,  o);
                s2 += __shfl_xor_sync(0xffffffffu, s2, o);
            }
            float mean = s * (1.f/DPC);
            float rstd = rsqrtf(s2 * (1.f/DPC) - mean*mean + 1e-5f);
            float e0 = (t.x-mean)*rstd*wg.x + wb.x;
            float e1 = (t.y-mean)*rstd*wg.y + wb.y;
            float e2 = (t.z-mean)*rstd*wg.z + wb.z;
            float e3 = (t.w-mean)*rstd*wg.w + wb.w;
            float p0 = e0*W0.x + e1*W0.y + e2*W0.z + e3*W0.w;
            float p1 = e0*W1.x + e1*W1.y + e2*W1.z + e3*W1.w;
            float p2 = e0*W2.x + e1*W2.y + e2*W2.z + e3*W2.w;
            float p3 = e0*W3.x + e1*W3.y + e2*W3.z + e3*W3.w;
#pragma unroll
            for (int o = 16; o; o >>= 1) {
                p0 += __shfl_xor_sync(0xffffffffu, p0, o);
                p1 += __shfl_xor_sync(0xffffffffu, p1, o);
                p2 += __shfl_xor_sync(0xffffffffu, p2, o);
                p3 += __shfl_xor_sync(0xffffffffu, p3, o);
            }
            if (lane == 0) {
                g_attn[((size_t)0*LREF + i)*LREF + j] = p0;
                g_attn[((size_t)1*LREF + i)*LREF + j] = p1;
                g_attn[((size_t)2*LREF + i)*LREF + j] = p2;
                g_attn[((size_t)3*LREF + i)*LREF + j] = p3;
            }
        }
    }
}

// -------- kernel C: attn += scale*(q8.k8)  (3-stage pipeline, fp8) -----------
__global__ void __launch_bounds__(512,2) score_kernel()
{
    extern __shared__ unsigned char sm[];
    unsigned sbase = (unsigned)__cvta_generic_to_shared(sm);   // 3 x 32KB (A16+B16)
    int tid = threadIdx.x, lane = tid & 31, warp = tid >> 5;
    int wm = warp & 3, wn = warp >> 2;
    int h = blockIdx.z >> 3, ks = blockIdx.z & 7;
    int i0 = blockIdx.x * 128, j0 = blockIdx.y * 128;

    const unsigned char* ga = g_q8 + ((size_t)(h*LREF + i0))*KTOT + ks*(KTOT/8);
    const unsigned char* gb = g_k8 + ((size_t)(h*LREF + j0))*KTOT + ks*(KTOT/8);

    float acc[2][4][4];
#pragma unroll
    for (int a = 0; a < 2; a++)
#pragma unroll
        for (int b = 0; b < 4; b++)
#pragma unroll
            for (int cc = 0; cc < 4; cc++) acc[a][b][cc] = 0.f;

    const int NIT = (KTOT/8)/128;   // 12 iterations of k=128 bytes
    auto stage = [&](int it) {
        unsigned buf = sbase + (unsigned)(it % 3) * 32768;
        for (int c = tid; c < 1024; c += 512) {
            int r = c >> 3, g = c & 7;
            unsigned d = r*128 + ((g ^ (r&7))<<4);
            cpa16(buf + d,         ga + (size_t)r*KTOT + it*128 + g*16);
            cpa16(buf + 16384 + d, gb + (size_t)r*KTOT + it*128 + g*16);
        }
        cpa_commit();
    };
    stage(0); stage(1);
    for (int it = 0; it < NIT; it++) {
        if (it < NIT-1) cpa_wait<1>(); else cpa_wait<0>();
        __syncthreads();
        unsigned buf = sbase + (unsigned)(it % 3) * 32768;
#pragma unroll
        for (int kk = 0; kk < 4; kk++)
            wstep8<2,4>(acc, buf, buf + 16384, wm*32, wn*32, kk*32, lane);
        if (it + 2 < NIT) stage(it + 2);
    }

    const float SC = 0.17677669529663687f / 384.0f;
#pragma unroll
    for (int mt = 0; mt < 2; mt++)
#pragma unroll
        for (int nt = 0; nt < 4; nt++) {
            float* ac = acc[mt][nt];
            int r = i0 + wm*32 + mt*16 + (lane >> 2);
            int c = j0 + wn*32 + nt*8 + 2*(lane & 3);
            size_t base = ((size_t)h*LREF + r)*LREF + c;
            atomicAdd(&g_attn[base],            ac[0]*SC);
            atomicAdd(&g_attn[base + 1],        ac[1]*SC);
            atomicAdd(&g_attn[base + 8*LREF],   ac[2]*SC);
            atomicAdd(&g_attn[base + 8*LREF+1], ac[3]*SC);
        }
}

// -------- softmax over j per (h,i): fp32 in, bf16 out ------------------------
__global__ void __launch_bounds__(128) softmax_kernel()
{
    int i = blockIdx.x, h = blockIdx.y;
    const float* row = g_attn + ((size_t)h * LREF + i) * LREF;
    bf16* orow = g_attnb + ((size_t)h * LREF + i) * LREF;
    int tid = threadIdx.x, warp = tid >> 5, lane = tid & 31;
    __shared__ float smax[4], ssum[4];

    float a0 = row[tid], a1 = row[tid + 128], a2 = row[tid + 256];
    float m = fmaxf(a0, fmaxf(a1, a2));
#pragma unroll
    for (int o = 16; o; o >>= 1) m = fmaxf(m, __shfl_xor_sync(0xffffffffu, m, o));
    if (lane == 0) smax[warp] = m;
    __syncthreads();
    float M = fmaxf(fmaxf(smax[0], smax[1]), fmaxf(smax[2], smax[3]));

    float e0 = expf(a0 - M), e1 = expf(a1 - M), e2 = expf(a2 - M);
    float s = e0 + e1 + e2;
#pragma unroll
    for (int o = 16; o; o >>= 1) s += __shfl_xor_sync(0xffffffffu, s, o);
    if (lane == 0) ssum[warp] = s;
    __syncthreads();
    float S = ssum[0] + ssum[1] + ssum[2] + ssum[3];
    float inv = 1.f / S;
    orow[tid]       = __float2bfloat16_rn(e0 * inv);
    orow[tid + 128] = __float2bfloat16_rn(e1 * inv);
    orow[tid + 256] = __float2bfloat16_rn(e2 * inv);
}

// -------- kernel D: om = attn_b[h] @ v2^T (3-stage pipeline) -----------------
__global__ void __launch_bounds__(512,2) av_kernel()
{
    extern __shared__ unsigned char sm[];
    unsigned sbase = (unsigned)__cvta_generic_to_shared(sm);   // 3 x 32KB
    int tid = threadIdx.x, lane = tid & 31, warp = tid >> 5;
    int wm = warp & 3, wn = warp >> 2;
    int i0 = blockIdx.x * 128, col0 = blockIdx.y * 128, h = blockIdx.z;

    const bf16* ga = g_attnb + ((size_t)(h*LREF + i0))*LREF;
    const bf16* gv = g_v2 + ((size_t)h*KTOT + col0)*LREF;

    float acc[2][4][4];
#pragma unroll
    for (int a = 0; a < 2; a++)
#pragma unroll
        for (int b = 0; b < 4; b++)
#pragma unroll
            for (int cc = 0; cc < 4; cc++) acc[a][b][cc] = 0.f;

    const int NIT = LREF/64;   // 6
    auto stage = [&](int it) {
        unsigned buf = sbase + (unsigned)(it % 3) * 32768;
        for (int c = tid; c < 1024; c += 512) {
            int r = c >> 3, g = c & 7;
            unsigned d = r*128 + ((g ^ (r&7))<<4);
            cpa16(buf + d,         ga + (size_t)r*LREF + it*64 + g*8);
            cpa16(buf + 16384 + d, gv + (size_t)r*LREF + it*64 + g*8);
        }
        cpa_commit();
    };
    stage(0); stage(1);
    for (int it = 0; it < NIT; it++) {
        if (it < NIT-1) cpa_wait<1>(); else cpa_wait<0>();
        __syncthreads();
        unsigned buf = sbase + (unsigned)(it % 3) * 32768;
#pragma unroll
        for (int kk = 0; kk < 4; kk++)
            wstep<2,4>(acc, buf, buf + 16384, wm*32, wn*32, kk*16, lane);
        if (it + 2 < NIT) stage(it + 2);
    }

#pragma unroll
    for (int mt = 0; mt < 2; mt++)
#pragma unroll
        for (int nt = 0; nt < 4; nt++) {
            float* ac = acc[mt][nt];
            int c = col0 + wn*32 + nt*8 + 2*(lane & 3);
            int n = c >> 5, d = c & 31;
#pragma unroll
            for (int half = 0; half < 2; half++) {
                int i = i0 + wm*32 + mt*16 + (lane >> 2) + half*8;
                *(bf162*)&g_omb[((size_t)n*LREF + i)*DPC + h*DHD + d] =
                    __floats2bfloat162_rn(ac[half*2+0], ac[half*2+1]);
            }
        }
}

// -------- kernel E: y = (gate .* om) @ Wo^T + bo, write transposed -----------
__global__ void __launch_bounds__(512,2) out_kernel(
    const float* __restrict__ Wo, const float* __restrict__ bo, float* __restrict__ outp)
{
    extern __shared__ unsigned char sm[];
    unsigned sXa = (unsigned)__cvta_generic_to_shared(sm);   // 2 x 16KB
    unsigned sWa = sXa + 32768;                              // 2 x 16KB
    int tid = threadIdx.x, lane = tid & 31, warp = tid >> 5;
    int wm = warp & 3, wn = warp >> 2;
    int row0 = blockIdx.x * 128;

    // stage X = gate .* om (128 rows x 128 bf16) swizzled, both k-chunks
    for (int idx = tid; idx < 2048; idx += 512) {
        int r = idx >> 4, g16 = idx & 15;
        size_t goff = (size_t)(row0 + r) * DPC + g16*8;
        uint4 gt = *(const uint4*)&g_gateb[goff];
        uint4 ot = *(const uint4*)&g_omb[goff];
        uint4 o;
        ((bf162*)&o)[0] = __hmul2(((bf162*)&gt)[0], ((bf162*)&ot)[0]);
        ((bf162*)&o)[1] = __hmul2(((bf162*)&gt)[1], ((bf162*)&ot)[1]);
        ((bf162*)&o)[2] = __hmul2(((bf162*)&gt)[2], ((bf162*)&ot)[2]);
        ((bf162*)&o)[3] = __hmul2(((bf162*)&gt)[3], ((bf162*)&ot)[3]);
        int kc = g16 >> 3, gg = g16 & 7;
        *(uint4*)(sm + kc*16384 + r*128 + ((gg ^ (r&7))<<4)) = o;
    }
    // stage Wo (128x128) bf16, both k-chunks
    for (int idx = tid; idx < 2048; idx += 512) {
        int r = idx >> 4, g16 = idx & 15;
        int kc = g16 >> 3, gg = g16 & 7;
        const float* src = Wo + (size_t)r*DPC + kc*64 + gg*8;
        float4 t0 = *(const float4*)src;
        float4 t1 = *(const float4*)(src + 4);
        uint4 o;
        o.x = pk2(t0.x, t0.y); o.y = pk2(t0.z, t0.w);
        o.z = pk2(t1.x, t1.y); o.w = pk2(t1.z, t1.w);
        *(uint4*)(sm + 32768 + kc*16384 + r*128 + ((gg ^ (r&7))<<4)) = o;
    }
    __syncthreads();

    float acc[2][4][4];
#pragma unroll
    for (int a = 0; a < 2; a++)
#pragma unroll
        for (int b = 0; b < 4; b++)
#pragma unroll
            for (int cc = 0; cc < 4; cc++) acc[a][b][cc] = 0.f;

#pragma unroll
    for (int kc = 0; kc < 2; kc++)
#pragma unroll
        for (int kk = 0; kk < 4; kk++)
            wstep<2,4>(acc, sXa + kc*16384, sWa + kc*16384, wm*32, wn*32, kk*16, lane);

#pragma unroll
    for (int mt = 0; mt < 2; mt++)
#pragma unroll
        for (int nt = 0; nt < 4; nt++) {
            float* ac = acc[mt][nt];
            int rl = wm*32 + mt*16 + (lane >> 2);
            int c  = wn*32 + nt*8 + 2*(lane & 3);
            float b0 = bo[c], b1 = bo[c+1];
#pragma unroll
            for (int half = 0; half < 2; half++) {
                int row = row0 + rl + half*8;
                int n = row / LREF, i = row - n*LREF;
                *(float2*)&outp[((size_t)i*LREF + n)*DPC + c] =
                    make_float2(ac[half*2+0] + b0, ac[half*2+1] + b1);
            }
        }
}

extern "C" void kernel_launch(void* const* d_in, const int* in_sizes, int n_in,
                              void* d_out, int out_size)
{
    (void)in_sizes; (void)n_in; (void)out_size;
    const float* pair      = (const float*)d_in[0];
    const float* bias      = (const float*)d_in[1];
    const float* ln_pair_g = (const float*)d_in[2];
    const float* ln_pair_b = (const float*)d_in[3];
    const float* ln_bias_g = (const float*)d_in[4];
    const float* ln_bias_b = (const float*)d_in[5];
    const float* Wq = (const float*)d_in[6];
    const float* Wk = (const float*)d_in[7];
    const float* Wv = (const float*)d_in[8];
    const float* Wb = (const float*)d_in[9];
    const float* Wg = (const float*)d_in[10];
    const float* bg = (const float*)d_in[11];
    const float* Wo = (const float*)d_in[12];
    const float* bo = (const float*)d_in[13];
    float* outp = (float*)d_out;

    const int SMEM2 = 65536;    // 2-stage kernels (pb, out)
    const int SMEM3 = 98304;    // 3-stage pipelined GEMMs (score, av)
    cudaFuncSetAttribute(pb_kernel,    cudaFuncAttributeMaxDynamicSharedMemorySize, SMEM2);
    cudaFuncSetAttribute(score_kernel, cudaFuncAttributeMaxDynamicSharedMemorySize, SMEM3);
    cudaFuncSetAttribute(av_kernel,    cudaFuncAttributeMaxDynamicSharedMemorySize, SMEM3);
    cudaFuncSetAttribute(out_kernel,   cudaFuncAttributeMaxDynamicSharedMemorySize, SMEM2);

    pb_kernel<<<NB_PROJ + NB_BIAS, 512, SMEM2>>>(pair, bias,
        ln_pair_g, ln_pair_b, ln_bias_g, ln_bias_b, Wq, Wk, Wv, Wg, bg, Wb);
    score_kernel<<<dim3(3, 3, 32), 512, SMEM3>>>();
    softmax_kernel<<<dim3(LREF, HN), 128>>>();
    av_kernel<<<dim3(3, KTOT/128, HN), 512, SMEM3>>>();
    out_kernel<<<LREF*LREF/128, 512, SMEM2>>>(Wo, bo, outp);
}

// round 12
// speedup vs baseline: 1.6793x; 1.0474x over previous
#include <cuda_runtime.h>
#include <cuda_bf16.h>
#include <math.h>

#define LREF 384
#define DPC 128
#define HN 4
#define DHD 32
#define KTOT (LREF*DHD)   // 12288

typedef __nv_bfloat16 bf16;
typedef __nv_bfloat162 bf162;

#define NB_PROJ (LREF*LREF/128)   // 1152
#define NB_BIAS (LREF*LREF/32)    // 4608

// ---------------- scratch (device globals) ----------------------------------
__device__ unsigned char g_q8[(size_t)HN*LREF*KTOT]; // [h][i][n*32+d] e4m3, unscaled
__device__ unsigned char g_k8[(size_t)HN*LREF*KTOT]; // [h][j][n*32+d] e4m3, unscaled
__device__ bf16 g_v2[(size_t)HN*KTOT*LREF];     // [h][col=n*32+d][j]  K-major(j)
__device__ bf16 g_gateb[(size_t)LREF*LREF*DPC]; // [row=n*L+i][c]
__device__ bf16 g_omb[(size_t)LREF*LREF*DPC];   // [row=n*L+i][h*32+d]  (gate-multiplied)
__device__ float g_attn[(size_t)HN*LREF*LREF];  // fp32 logits (bias-init + atomics)
__device__ bf16 g_attnb[(size_t)HN*LREF*LREF];  // softmaxed, bf16
__device__ unsigned char g_wbf[5*32768];        // bf16 weights, pre-swizzled smem layout

// ---------------- ptx helpers ------------------------------------------------
__device__ __forceinline__ void ldsm4(unsigned &r0,unsigned &r1,unsigned &r2,unsigned &r3,unsigned a){
    asm volatile("ldmatrix.sync.aligned.m8n8.x4.shared.b16 {%0,%1,%2,%3},[%4];"
        :"=r"(r0),"=r"(r1),"=r"(r2),"=r"(r3):"r"(a));
}
__device__ __forceinline__ void mma_bf16(float c[4], const unsigned a[4], const unsigned b[2]){
    asm volatile("mma.sync.aligned.m16n8k16.row.col.f32.bf16.bf16.f32 "
        "{%0,%1,%2,%3},{%4,%5,%6,%7},{%8,%9},{%0,%1,%2,%3};"
        :"+f"(c[0]),"+f"(c[1]),"+f"(c[2]),"+f"(c[3])
        :"r"(a[0]),"r"(a[1]),"r"(a[2]),"r"(a[3]),"r"(b[0]),"r"(b[1]));
}
__device__ __forceinline__ void mma_fp8(float c[4], const unsigned a[4], const unsigned b[2]){
    asm volatile("mma.sync.aligned.m16n8k32.row.col.f32.e4m3.e4m3.f32 "
        "{%0,%1,%2,%3},{%4,%5,%6,%7},{%8,%9},{%0,%1,%2,%3};"
        :"+f"(c[0]),"+f"(c[1]),"+f"(c[2]),"+f"(c[3])
        :"r"(a[0]),"r"(a[1]),"r"(a[2]),"r"(a[3]),"r"(b[0]),"r"(b[1]));
}
__device__ __forceinline__ void cpa16(unsigned saddr, const void* g) {
    asm volatile("cp.async.cg.shared.global [%0],[%1],16;\n" :: "r"(saddr), "l"(g));
}
__device__ __forceinline__ void cpa_commit() { asm volatile("cp.async.commit_group;\n"); }
template<int N>
__device__ __forceinline__ void cpa_wait() { asm volatile("cp.async.wait_group %0;\n" :: "n"(N)); }

__device__ __forceinline__ unsigned pk2(float a, float b){
    bf162 t = __floats2bfloat162_rn(a, b);
    return *(unsigned*)&t;
}
__device__ __forceinline__ unsigned short pk8(float lo, float hi){
    unsigned short u;
    asm("cvt.rn.satfinite.e4m3x2.f32 %0, %2, %1;" : "=h"(u) : "f"(lo), "f"(hi));
    return u;
}

// warp k16-step (bf16): A rows 128B [m][k64], B rows 128B [n][k64], SW128-swizzled
template<int MT,int NT>
__device__ __forceinline__ void wstep(float (&acc)[MT][NT][4], unsigned sA, unsigned sB,
                                      int m0, int n0, int k0, int lane)
{
    unsigned a[MT][4];
    int arow = lane & 15, acg = (k0>>3) + (lane>>4);
#pragma unroll
    for (int mt = 0; mt < MT; mt++) {
        int r = m0 + mt*16 + arow;
        ldsm4(a[mt][0],a[mt][1],a[mt][2],a[mt][3], sA + r*128 + ((acg ^ (r&7))<<4));
    }
    int brow_off = (lane & 7) + ((lane>>4)<<3);
    int bcg = (k0>>3) + ((lane>>3)&1);
#pragma unroll
    for (int nt = 0; nt < NT; nt += 2) {
        int r = n0 + nt*8 + brow_off;
        unsigned b[4];
        ldsm4(b[0],b[1],b[2],b[3], sB + r*128 + ((bcg ^ (r&7))<<4));
#pragma unroll
        for (int mt = 0; mt < MT; mt++) {
            mma_bf16(acc[mt][nt],   a[mt], b);
            mma_bf16(acc[mt][nt+1], a[mt], b+2);
        }
    }
}

// warp k32-step (fp8): A rows 128B [m][k128 bytes], B rows 128B [n][k128 bytes]
template<int MT,int NT>
__device__ __forceinline__ void wstep8(float (&acc)[MT][NT][4], unsigned sA, unsigned sB,
                                       int m0, int n0, int kb, int lane)
{
    unsigned a[MT][4];
    int arow = lane & 15, acg = (kb>>4) + (lane>>4);
#pragma unroll
    for (int mt = 0; mt < MT; mt++) {
        int r = m0 + mt*16 + arow;
        ldsm4(a[mt][0],a[mt][1],a[mt][2],a[mt][3], sA + r*128 + ((acg ^ (r&7))<<4));
    }
    int brow_off = (lane & 7) + ((lane>>4)<<3);
    int bcg = (kb>>4) + ((lane>>3)&1);
#pragma unroll
    for (int nt = 0; nt < NT; nt += 2) {
        int r = n0 + nt*8 + brow_off;
        unsigned b[4];
        ldsm4(b[0],b[1],b[2],b[3], sB + r*128 + ((bcg ^ (r&7))<<4));
#pragma unroll
        for (int mt = 0; mt < MT; mt++) {
            mma_fp8(acc[mt][nt],   a[mt], b);
            mma_fp8(acc[mt][nt+1], a[mt], b+2);
        }
    }
}

// -------- kernel 0: convert weights fp32 -> bf16, pre-swizzled ---------------
__global__ void __launch_bounds__(512) wconv_kernel(
    const float* __restrict__ Wq, const float* __restrict__ Wk, const float* __restrict__ Wv,
    const float* __restrict__ Wg, const float* __restrict__ Wo)
{
    const float* Ws[5] = { Wq, Wk, Wv, Wg, Wo };
    const float* W = Ws[blockIdx.x];
    unsigned char* dst = g_wbf + (size_t)blockIdx.x * 32768;
    int tid = threadIdx.x;
    for (int idx = tid; idx < 2048; idx += 512) {
        int r = idx >> 4, g16 = idx & 15;
        int kc = g16 >> 3, gg = g16 & 7;
        const float* src = W + (size_t)r*DPC + kc*64 + gg*8;
        float4 t0 = *(const float4*)src;
        float4 t1 = *(const float4*)(src + 4);
        uint4 o;
        o.x = pk2(t0.x,t0.y); o.y = pk2(t0.z,t0.w);
        o.z = pk2(t1.x,t1.y); o.w = pk2(t1.z,t1.w);
        *(uint4*)(dst + kc*16384 + r*128 + ((gg ^ (r&7))<<4)) = o;
    }
}

// -------- fused kernel A: proj (blocks 0..NB_PROJ) + bias (rest) -------------
__global__ void __launch_bounds__(512,2) pb_kernel(
    const float* __restrict__ pair, const float* __restrict__ biasp,
    const float* __restrict__ lnpg, const float* __restrict__ lnpb,
    const float* __restrict__ lnbg, const float* __restrict__ lnbb,
    const float* __restrict__ bg, const float* __restrict__ Wb)
{
    extern __shared__ unsigned char sm[];
    int tid = threadIdx.x, lane = tid & 31, wid = tid >> 5;

    if (blockIdx.x < NB_PROJ) {
        // ================= proj =================
        unsigned sXa = (unsigned)__cvta_generic_to_shared(sm);   // 2 x 16KB LN'ed X
        unsigned sWa = sXa + 32768;                              // 2 x 32KB W double buffer
        int wm = wid & 3, wn = wid >> 2;     // 4m x 4n warps, tile 32x32
        int row0 = blockIdx.x * 128;
        int nn = row0 / LREF, i0b = row0 % LREF;

        auto stageW = [&](int mat) {
            const unsigned char* src = g_wbf + (size_t)mat * 32768;
            unsigned buf = sWa + (unsigned)(mat & 1) * 32768;
#pragma unroll
            for (int k = 0; k < 4; k++) {
                unsigned off = (unsigned)(tid + k*512) * 16;
                cpa16(buf + off, src + off);
            }
            cpa_commit();
        };
        stageW(0);   // group 0
        stageW(1);   // group 1

        // warp-cooperative single-pass LN: warp handles 8 rows
        for (int rr = 0; rr < 8; rr++) {
            int r = wid * 8 + rr;
            int i = i0b + r;
            const float* x = pair + ((size_t)i*LREF + nn) * DPC;
            float4 t = *(const float4*)(x + lane*4);
            float s  = t.x + t.y + t.z + t.w;
            float s2 = t.x*t.x + t.y*t.y + t.z*t.z + t.w*t.w;
#pragma unroll
            for (int o = 16; o; o >>= 1) {
                s  += __shfl_xor_sync(0xffffffffu, s,  o);
                s2 += __shfl_xor_sync(0xffffffffu, s2, o);
            }
            float mean = s * (1.f/DPC);
            float rstd = rsqrtf(s2 * (1.f/DPC) - mean*mean + 1e-5f);
            float4 wv = *(const float4*)(lnpg + lane*4);
            float4 bv = *(const float4*)(lnpb + lane*4);
            unsigned p0 = pk2((t.x-mean)*rstd*wv.x + bv.x, (t.y-mean)*rstd*wv.y + bv.y);
            unsigned p1 = pk2((t.z-mean)*rstd*wv.z + bv.z, (t.w-mean)*rstd*wv.w + bv.w);
            int kc = lane >> 4, g = (lane & 15) >> 1;
            *(uint2*)(sm + kc*16384 + r*128 + ((g ^ (r&7))<<4) + (lane&1)*8) = make_uint2(p0, p1);
        }

        for (int mat = 0; mat < 4; mat++) {
            if (mat < 3) cpa_wait<1>(); else cpa_wait<0>();
            __syncthreads();   // W(mat) visible + (mat==0: LN writes visible)

            unsigned bufW = sWa + (unsigned)(mat & 1) * 32768;
            float acc[2][4][4];
#pragma unroll
            for (int a = 0; a < 2; a++)
#pragma unroll
                for (int b = 0; b < 4; b++)
#pragma unroll
                    for (int cc = 0; cc < 4; cc++) acc[a][b][cc] = 0.f;
#pragma unroll
            for (int kc = 0; kc < 2; kc++)
#pragma unroll
                for (int kk = 0; kk < 4; kk++)
                    wstep<2,4>(acc, sXa + kc*16384, bufW + kc*16384, wm*32, wn*32, kk*16, lane);
            __syncthreads();   // all warps done reading this W buffer

            // ---- stage results to smem (overwrites just-consumed W buffer) ----
            unsigned char* smTb = sm + 32768 + (size_t)(mat & 1) * 32768;
            unsigned char* smT8 = smTb;
            bf16* smT16 = (bf16*)smTb;
#pragma unroll
            for (int mt = 0; mt < 2; mt++)
#pragma unroll
                for (int nt = 0; nt < 4; nt++) {
                    float* ac = acc[mt][nt];
                    int rl = wm*32 + mt*16 + (lane >> 2);
                    int c  = wn*32 + nt*8 + 2*(lane & 3);
#pragma unroll
                    for (int half = 0; half < 2; half++) {
                        int il = rl + half*8;
                        float v0 = ac[half*2+0], v1 = ac[half*2+1];
                        if (mat < 2) {
                            *(unsigned short*)&smT8[il*128 + c] = pk8(v0, v1);
                        } else if (mat == 2) {
                            smT16[(c)  *128 + il] = __float2bfloat16_rn(v0);
                            smT16[(c+1)*128 + il] = __float2bfloat16_rn(v1);
                        } else {
                            float z0 = v0 + bg[c], z1 = v1 + bg[c+1];
                            *(bf162*)&smT16[il*128 + c] =
                                __floats2bfloat162_rn(1.f/(1.f+expf(-z0)), 1.f/(1.f+expf(-z1)));
                        }
                    }
                }
            __syncthreads();

            // ---- coalesced global writes ----
            if (mat < 2) {
                unsigned char* dst = (mat == 0) ? g_q8 : g_k8;
#pragma unroll
                for (int k = 0; k < 8; k++) {
                    int idx = tid + k*512;
                    int i = idx >> 5, seg = idx & 31;
                    int c4 = seg*4;
                    int hh = c4 >> 5, d = c4 & 31;
                    *(unsigned*)&dst[((size_t)(hh*LREF + i0b + i))*KTOT + nn*DHD + d] =
                        *(unsigned*)&smT8[i*128 + c4];
                }
            } else if (mat == 2) {
#pragma unroll
                for (int k = 0; k < 4; k++) {
                    int idx = tid + k*512;
                    int col = idx >> 4, seg = idx & 15;
                    int hh = col >> 5, d = col & 31;
                    *(uint4*)&g_v2[((size_t)hh*KTOT + nn*DHD + d)*LREF + i0b + seg*8] =
                        *(uint4*)&smT16[col*128 + seg*8];
                }
            } else {
#pragma unroll
                for (int k = 0; k < 4; k++) {
                    int idx = tid + k*512;
                    int i = idx >> 4, seg = idx & 15;
                    *(uint4*)&g_gateb[((size_t)(nn*LREF + i0b + i))*DPC + seg*8] =
                        *(uint4*)&smT16[i*128 + seg*8];
                }
            }
            __syncthreads();   // staging buffer free
            if (mat + 2 < 4) stageW(mat + 2);   // prefetch into the freed buffer
        }
    } else {
        // ================= bias =================
        float* sWb = (float*)sm;           // 4*128 floats
        int bid = blockIdx.x - NB_PROJ;
        for (int c = tid; c < 4*DPC; c += 512) sWb[c] = Wb[c];
        __syncthreads();

        float4 wg = *(const float4*)(lnbg + lane*4);
        float4 wb = *(const float4*)(lnbb + lane*4);
        float4 W0 = *(const float4*)(sWb + 0*DPC + lane*4);
        float4 W1 = *(const float4*)(sWb + 1*DPC + lane*4);
        float4 W2 = *(const float4*)(sWb + 2*DPC + lane*4);
        float4 W3 = *(const float4*)(sWb + 3*DPC + lane*4);

        for (int rr = 0; rr < 2; rr++) {
            int row = bid*32 + wid*2 + rr;    // row = i*L + j
            int i = row / LREF, j = row - i*LREF;
            const float* x = biasp + ((size_t)j*LREF + i) * DPC;
            float4 t = *(const float4*)(x + lane*4);
            float s  = t.x + t.y + t.z + t.w;
            float s2 = t.x*t.x + t.y*t.y + t.z*t.z + t.w*t.w;
#pragma unroll
            for (int o = 16; o; o >>= 1) {
                s  += __shfl_xor_sync(0xffffffffu, s,  o);
                s2 += __shfl_xor_sync(0xffffffffu, s2, o);
            }
            float mean = s * (1.f/DPC);
            float rstd = rsqrtf(s2 * (1.f/DPC) - mean*mean + 1e-5f);
            float e0 = (t.x-mean)*rstd*wg.x + wb.x;
            float e1 = (t.y-mean)*rstd*wg.y + wb.y;
            float e2 = (t.z-mean)*rstd*wg.z + wb.z;
            float e3 = (t.w-mean)*rstd*wg.w + wb.w;
            float p0 = e0*W0.x + e1*W0.y + e2*W0.z + e3*W0.w;
            float p1 = e0*W1.x + e1*W1.y + e2*W1.z + e3*W1.w;
            float p2 = e0*W2.x + e1*W2.y + e2*W2.z + e3*W2.w;
            float p3 = e0*W3.x + e1*W3.y + e2*W3.z + e3*W3.w;
#pragma unroll
            for (int o = 16; o; o >>= 1) {
                p0 += __shfl_xor_sync(0xffffffffu, p0, o);
                p1 += __shfl_xor_sync(0xffffffffu, p1, o);
                p2 += __shfl_xor_sync(0xffffffffu, p2, o);
                p3 += __shfl_xor_sync(0xffffffffu, p3, o);
            }
            if (lane == 0) {
                g_attn[((size_t)0*LREF + i)*LREF + j] = p0;
                g_attn[((size_t)1*LREF + i)*LREF + j] = p1;
                g_attn[((size_t)2*LREF + i)*LREF + j] = p2;
                g_attn[((size_t)3*LREF + i)*LREF + j] = p3;
            }
        }
    }
}

// -------- kernel C: attn += scale*(q8.k8)  (3-stage pipeline, fp8) -----------
__global__ void __launch_bounds__(512,2) score_kernel()
{
    extern __shared__ unsigned char sm[];
    unsigned sbase = (unsigned)__cvta_generic_to_shared(sm);   // 3 x 32KB (A16+B16)
    int tid = threadIdx.x, lane = tid & 31, warp = tid >> 5;
    int wm = warp & 3, wn = warp >> 2;
    int h = blockIdx.z >> 3, ks = blockIdx.z & 7;
    int i0 = blockIdx.x * 128, j0 = blockIdx.y * 128;

    const unsigned char* ga = g_q8 + ((size_t)(h*LREF + i0))*KTOT + ks*(KTOT/8);
    const unsigned char* gb = g_k8 + ((size_t)(h*LREF + j0))*KTOT + ks*(KTOT/8);

    float acc[2][4][4];
#pragma unroll
    for (int a = 0; a < 2; a++)
#pragma unroll
        for (int b = 0; b < 4; b++)
#pragma unroll
            for (int cc = 0; cc < 4; cc++) acc[a][b][cc] = 0.f;

    const int NIT = (KTOT/8)/128;   // 12
    auto stage = [&](int it) {
        unsigned buf = sbase + (unsigned)(it % 3) * 32768;
        for (int c = tid; c < 1024; c += 512) {
            int r = c >> 3, g = c & 7;
            unsigned d = r*128 + ((g ^ (r&7))<<4);
            cpa16(buf + d,         ga + (size_t)r*KTOT + it*128 + g*16);
            cpa16(buf + 16384 + d, gb + (size_t)r*KTOT + it*128 + g*16);
        }
        cpa_commit();
    };
    stage(0); stage(1);
    for (int it = 0; it < NIT; it++) {
        if (it < NIT-1) cpa_wait<1>(); else cpa_wait<0>();
        __syncthreads();
        unsigned buf = sbase + (unsigned)(it % 3) * 32768;
#pragma unroll
        for (int kk = 0; kk < 4; kk++)
            wstep8<2,4>(acc, buf, buf + 16384, wm*32, wn*32, kk*32, lane);
        if (it + 2 < NIT) stage(it + 2);
    }

    const float SC = 0.17677669529663687f / 384.0f;
#pragma unroll
    for (int mt = 0; mt < 2; mt++)
#pragma unroll
        for (int nt = 0; nt < 4; nt++) {
            float* ac = acc[mt][nt];
            int r = i0 + wm*32 + mt*16 + (lane >> 2);
            int c = j0 + wn*32 + nt*8 + 2*(lane & 3);
            size_t base = ((size_t)h*LREF + r)*LREF + c;
            atomicAdd(&g_attn[base],            ac[0]*SC);
            atomicAdd(&g_attn[base + 1],        ac[1]*SC);
            atomicAdd(&g_attn[base + 8*LREF],   ac[2]*SC);
            atomicAdd(&g_attn[base + 8*LREF+1], ac[3]*SC);
        }
}

// -------- softmax over j per (h,i): fp32 in, bf16 out ------------------------
__global__ void __launch_bounds__(128) softmax_kernel()
{
    int i = blockIdx.x, h = blockIdx.y;
    const float* row = g_attn + ((size_t)h * LREF + i) * LREF;
    bf16* orow = g_attnb + ((size_t)h * LREF + i) * LREF;
    int tid = threadIdx.x, warp = tid >> 5, lane = tid & 31;
    __shared__ float smax[4], ssum[4];

    float a0 = row[tid], a1 = row[tid + 128], a2 = row[tid + 256];
    float m = fmaxf(a0, fmaxf(a1, a2));
#pragma unroll
    for (int o = 16; o; o >>= 1) m = fmaxf(m, __shfl_xor_sync(0xffffffffu, m, o));
    if (lane == 0) smax[warp] = m;
    __syncthreads();
    float M = fmaxf(fmaxf(smax[0], smax[1]), fmaxf(smax[2], smax[3]));

    float e0 = expf(a0 - M), e1 = expf(a1 - M), e2 = expf(a2 - M);
    float s = e0 + e1 + e2;
#pragma unroll
    for (int o = 16; o; o >>= 1) s += __shfl_xor_sync(0xffffffffu, s, o);
    if (lane == 0) ssum[warp] = s;
    __syncthreads();
    float S = ssum[0] + ssum[1] + ssum[2] + ssum[3];
    float inv = 1.f / S;
    orow[tid]       = __float2bfloat16_rn(e0 * inv);
    orow[tid + 128] = __float2bfloat16_rn(e1 * inv);
    orow[tid + 256] = __float2bfloat16_rn(e2 * inv);
}

// -------- kernel D: om = gate .* (attn_b[h] @ v2^T)  (3-stage pipeline) ------
__global__ void __launch_bounds__(512,2) av_kernel()
{
    extern __shared__ unsigned char sm[];
    unsigned sbase = (unsigned)__cvta_generic_to_shared(sm);   // 3 x 32KB
    int tid = threadIdx.x, lane = tid & 31, warp = tid >> 5;
    int wm = warp & 3, wn = warp >> 2;
    int i0 = blockIdx.x * 128, col0 = blockIdx.y * 128, h = blockIdx.z;

    const bf16* ga = g_attnb + ((size_t)(h*LREF + i0))*LREF;
    const bf16* gv = g_v2 + ((size_t)h*KTOT + col0)*LREF;

    float acc[2][4][4];
#pragma unroll
    for (int a = 0; a < 2; a++)
#pragma unroll
        for (int b = 0; b < 4; b++)
#pragma unroll
            for (int cc = 0; cc < 4; cc++) acc[a][b][cc] = 0.f;

    const int NIT = LREF/64;   // 6
    auto stage = [&](int it) {
        unsigned buf = sbase + (unsigned)(it % 3) * 32768;
        for (int c = tid; c < 1024; c += 512) {
            int r = c >> 3, g = c & 7;
            unsigned d = r*128 + ((g ^ (r&7))<<4);
            cpa16(buf + d,         ga + (size_t)r*LREF + it*64 + g*8);
            cpa16(buf + 16384 + d, gv + (size_t)r*LREF + it*64 + g*8);
        }
        cpa_commit();
    };
    stage(0); stage(1);
    for (int it = 0; it < NIT; it++) {
        if (it < NIT-1) cpa_wait<1>(); else cpa_wait<0>();
        __syncthreads();
        unsigned buf = sbase + (unsigned)(it % 3) * 32768;
#pragma unroll
        for (int kk = 0; kk < 4; kk++)
            wstep<2,4>(acc, buf, buf + 16384, wm*32, wn*32, kk*16, lane);
        if (it + 2 < NIT) stage(it + 2);
    }

#pragma unroll
    for (int mt = 0; mt < 2; mt++)
#pragma unroll
        for (int nt = 0; nt < 4; nt++) {
            float* ac = acc[mt][nt];
            int c = col0 + wn*32 + nt*8 + 2*(lane & 3);
            int n = c >> 5, d = c & 31;
#pragma unroll
            for (int half = 0; half < 2; half++) {
                int i = i0 + wm*32 + mt*16 + (lane >> 2) + half*8;
                size_t ofs = ((size_t)n*LREF + i)*DPC + h*DHD + d;
                bf162 gv2 = *(const bf162*)&g_gateb[ofs];
                bf162 r2 = __floats2bfloat162_rn(ac[half*2+0], ac[half*2+1]);
                *(bf162*)&g_omb[ofs] = __hmul2(gv2, r2);
            }
        }
}

// -------- kernel E: y = omb @ Wo^T + bo, write transposed --------------------
__global__ void __launch_bounds__(512,2) out_kernel(
    const float* __restrict__ bo, float* __restrict__ outp)
{
    extern __shared__ unsigned char sm[];
    unsigned sXa = (unsigned)__cvta_generic_to_shared(sm);   // 2 x 16KB
    unsigned sWa = sXa + 32768;                              // 32KB
    int tid = threadIdx.x, lane = tid & 31, warp = tid >> 5;
    int wm = warp & 3, wn = warp >> 2;
    int row0 = blockIdx.x * 128;

    // cpa X from g_omb (already gate-multiplied): swizzled per k-chunk layout
    {
        const unsigned char* srcX = (const unsigned char*)g_omb + (size_t)row0 * 256;
        for (int idx = tid; idx < 2048; idx += 512) {
            int r = idx >> 4, g16 = idx & 15;
            int kc = g16 >> 3, gg = g16 & 7;
            cpa16(sXa + kc*16384 + r*128 + ((gg ^ (r&7))<<4),
                  srcX + (size_t)r*256 + kc*128 + gg*16);
        }
        cpa_commit();
        // cpa Wo (pre-swizzled global)
        const unsigned char* srcW = g_wbf + 4*32768;
#pragma unroll
        for (int k = 0; k < 4; k++) {
            unsigned off = (unsigned)(tid + k*512) * 16;
            cpa16(sWa + off, srcW + off);
        }
        cpa_commit();
    }
    cpa_wait<0>();
    __syncthreads();

    float acc[2][4][4];
#pragma unroll
    for (int a = 0; a < 2; a++)
#pragma unroll
        for (int b = 0; b < 4; b++)
#pragma unroll
            for (int cc = 0; cc < 4; cc++) acc[a][b][cc] = 0.f;

#pragma unroll
    for (int kc = 0; kc < 2; kc++)
#pragma unroll
        for (int kk = 0; kk < 4; kk++)
            wstep<2,4>(acc, sXa + kc*16384, sWa + kc*16384, wm*32, wn*32, kk*16, lane);

#pragma unroll
    for (int mt = 0; mt < 2; mt++)
#pragma unroll
        for (int nt = 0; nt < 4; nt++) {
            float* ac = acc[mt][nt];
            int rl = wm*32 + mt*16 + (lane >> 2);
            int c  = wn*32 + nt*8 + 2*(lane & 3);
            float b0 = bo[c], b1 = bo[c+1];
#pragma unroll
            for (int half = 0; half < 2; half++) {
                int row = row0 + rl + half*8;
                int n = row / LREF, i = row - n*LREF;
                *(float2*)&outp[((size_t)i*LREF + n)*DPC + c] =
                    make_float2(ac[half*2+0] + b0, ac[half*2+1] + b1);
            }
        }
}

extern "C" void kernel_launch(void* const* d_in, const int* in_sizes, int n_in,
                              void* d_out, int out_size)
{
    (void)in_sizes; (void)n_in; (void)out_size;
    const float* pair      = (const float*)d_in[0];
    const float* bias      = (const float*)d_in[1];
    const float* ln_pair_g = (const float*)d_in[2];
    const float* ln_pair_b = (const float*)d_in[3];
    const float* ln_bias_g = (const float*)d_in[4];
    const float* ln_bias_b = (const float*)d_in[5];
    const float* Wq = (const float*)d_in[6];
    const float* Wk = (const float*)d_in[7];
    const float* Wv = (const float*)d_in[8];
    const float* Wb = (const float*)d_in[9];
    const float* Wg = (const float*)d_in[10];
    const float* bg = (const float*)d_in[11];
    const float* Wo = (const float*)d_in[12];
    const float* bo = (const float*)d_in[13];
    float* outp = (float*)d_out;

    const int PB_SMEM  = 98304;   // 32KB X + 2x32KB W buffers
    const int SMEM3    = 98304;   // 3-stage pipelined GEMMs (score, av)
    const int OUT_SMEM = 65536;   // 32KB X + 32KB Wo
    cudaFuncSetAttribute(pb_kernel,    cudaFuncAttributeMaxDynamicSharedMemorySize, PB_SMEM);
    cudaFuncSetAttribute(score_kernel, cudaFuncAttributeMaxDynamicSharedMemorySize, SMEM3);
    cudaFuncSetAttribute(av_kernel,    cudaFuncAttributeMaxDynamicSharedMemorySize, SMEM3);
    cudaFuncSetAttribute(out_kernel,   cudaFuncAttributeMaxDynamicSharedMemorySize, OUT_SMEM);

    wconv_kernel<<<5, 512>>>(Wq, Wk, Wv, Wg, Wo);
    pb_kernel<<<NB_PROJ + NB_BIAS, 512, PB_SMEM>>>(pair, bias,
        ln_pair_g, ln_pair_b, ln_bias_g, ln_bias_b, bg, Wb);
    score_kernel<<<dim3(3, 3, 32), 512, SMEM3>>>();
    softmax_kernel<<<dim3(LREF, HN), 128>>>();
    av_kernel<<<dim3(3, KTOT/128, HN), 512, SMEM3>>>();
    out_kernel<<<LREF*LREF/128, 512, OUT_SMEM>>>(bo, outp);
}

// round 13
// speedup vs baseline: 1.6892x; 1.0059x over previous
#include <cuda_runtime.h>
#include <cuda_bf16.h>
#include <math.h>

#define LREF 384
#define DPC 128
#define HN 4
#define DHD 32
#define KTOT (LREF*DHD)   // 12288

typedef __nv_bfloat16 bf16;
typedef __nv_bfloat162 bf162;

#define NB_PROJ (LREF*LREF/128)   // 1152
#define NB_BIAS (LREF*LREF/32)    // 4608

// ---------------- scratch (device globals) ----------------------------------
__device__ unsigned char g_q8[(size_t)HN*LREF*KTOT]; // [h][i][n*32+d] e4m3, unscaled
__device__ unsigned char g_k8[(size_t)HN*LREF*KTOT]; // [h][j][n*32+d] e4m3, unscaled
__device__ bf16 g_v2[(size_t)HN*KTOT*LREF];     // [h][col=n*32+d][j]  K-major(j)
__device__ bf16 g_gateb[(size_t)LREF*LREF*DPC]; // [row=n*L+i][c]
__device__ bf16 g_omb[(size_t)LREF*LREF*DPC];   // [row=n*L+i][h*32+d]  (gate-multiplied)
__device__ float g_attn[(size_t)HN*LREF*LREF];  // fp32 logits (bias-init + atomics)
__device__ bf16 g_attnb[(size_t)HN*LREF*LREF];  // softmaxed, bf16
__device__ unsigned char g_wbf[5*32768];        // bf16 weights, pre-swizzled smem layout

// ---------------- ptx helpers ------------------------------------------------
__device__ __forceinline__ void ldsm4(unsigned &r0,unsigned &r1,unsigned &r2,unsigned &r3,unsigned a){
    asm volatile("ldmatrix.sync.aligned.m8n8.x4.shared.b16 {%0,%1,%2,%3},[%4];"
        :"=r"(r0),"=r"(r1),"=r"(r2),"=r"(r3):"r"(a));
}
__device__ __forceinline__ void mma_bf16(float c[4], const unsigned a[4], const unsigned b[2]){
    asm volatile("mma.sync.aligned.m16n8k16.row.col.f32.bf16.bf16.f32 "
        "{%0,%1,%2,%3},{%4,%5,%6,%7},{%8,%9},{%0,%1,%2,%3};"
        :"+f"(c[0]),"+f"(c[1]),"+f"(c[2]),"+f"(c[3])
        :"r"(a[0]),"r"(a[1]),"r"(a[2]),"r"(a[3]),"r"(b[0]),"r"(b[1]));
}
__device__ __forceinline__ void mma_fp8(float c[4], const unsigned a[4], const unsigned b[2]){
    asm volatile("mma.sync.aligned.m16n8k32.row.col.f32.e4m3.e4m3.f32 "
        "{%0,%1,%2,%3},{%4,%5,%6,%7},{%8,%9},{%0,%1,%2,%3};"
        :"+f"(c[0]),"+f"(c[1]),"+f"(c[2]),"+f"(c[3])
        :"r"(a[0]),"r"(a[1]),"r"(a[2]),"r"(a[3]),"r"(b[0]),"r"(b[1]));
}
__device__ __forceinline__ void cpa16(unsigned saddr, const void* g) {
    asm volatile("cp.async.cg.shared.global [%0],[%1],16;\n" :: "r"(saddr), "l"(g));
}
__device__ __forceinline__ void cpa_commit() { asm volatile("cp.async.commit_group;\n"); }
template<int N>
__device__ __forceinline__ void cpa_wait() { asm volatile("cp.async.wait_group %0;\n" :: "n"(N)); }

__device__ __forceinline__ unsigned pk2(float a, float b){
    bf162 t = __floats2bfloat162_rn(a, b);
    return *(unsigned*)&t;
}
__device__ __forceinline__ unsigned short pk8(float lo, float hi){
    unsigned short u;
    asm("cvt.rn.satfinite.e4m3x2.f32 %0, %2, %1;" : "=h"(u) : "f"(lo), "f"(hi));
    return u;
}

// warp k16-step (bf16): A rows 128B [m][k64], B rows 128B [n][k64], SW128-swizzled
template<int MT,int NT>
__device__ __forceinline__ void wstep(float (&acc)[MT][NT][4], unsigned sA, unsigned sB,
                                      int m0, int n0, int k0, int lane)
{
    unsigned a[MT][4];
    int arow = lane & 15, acg = (k0>>3) + (lane>>4);
#pragma unroll
    for (int mt = 0; mt < MT; mt++) {
        int r = m0 + mt*16 + arow;
        ldsm4(a[mt][0],a[mt][1],a[mt][2],a[mt][3], sA + r*128 + ((acg ^ (r&7))<<4));
    }
    int brow_off = (lane & 7) + ((lane>>4)<<3);
    int bcg = (k0>>3) + ((lane>>3)&1);
#pragma unroll
    for (int nt = 0; nt < NT; nt += 2) {
        int r = n0 + nt*8 + brow_off;
        unsigned b[4];
        ldsm4(b[0],b[1],b[2],b[3], sB + r*128 + ((bcg ^ (r&7))<<4));
#pragma unroll
        for (int mt = 0; mt < MT; mt++) {
            mma_bf16(acc[mt][nt],   a[mt], b);
            mma_bf16(acc[mt][nt+1], a[mt], b+2);
        }
    }
}

// warp k32-step (fp8): A rows 128B [m][k128 bytes], B rows 128B [n][k128 bytes]
template<int MT,int NT>
__device__ __forceinline__ void wstep8(float (&acc)[MT][NT][4], unsigned sA, unsigned sB,
                                       int m0, int n0, int kb, int lane)
{
    unsigned a[MT][4];
    int arow = lane & 15, acg = (kb>>4) + (lane>>4);
#pragma unroll
    for (int mt = 0; mt < MT; mt++) {
        int r = m0 + mt*16 + arow;
        ldsm4(a[mt][0],a[mt][1],a[mt][2],a[mt][3], sA + r*128 + ((acg ^ (r&7))<<4));
    }
    int brow_off = (lane & 7) + ((lane>>4)<<3);
    int bcg = (kb>>4) + ((lane>>3)&1);
#pragma unroll
    for (int nt = 0; nt < NT; nt += 2) {
        int r = n0 + nt*8 + brow_off;
        unsigned b[4];
        ldsm4(b[0],b[1],b[2],b[3], sB + r*128 + ((bcg ^ (r&7))<<4));
#pragma unroll
        for (int mt = 0; mt < MT; mt++) {
            mma_fp8(acc[mt][nt],   a[mt], b);
            mma_fp8(acc[mt][nt+1], a[mt], b+2);
        }
    }
}

// -------- kernel 0: convert weights fp32 -> bf16, pre-swizzled ---------------
__global__ void __launch_bounds__(512) wconv_kernel(
    const float* __restrict__ Wq, const float* __restrict__ Wk, const float* __restrict__ Wv,
    const float* __restrict__ Wg, const float* __restrict__ Wo)
{
    const float* Ws[5] = { Wq, Wk, Wv, Wg, Wo };
    const float* W = Ws[blockIdx.x];
    unsigned char* dst = g_wbf + (size_t)blockIdx.x * 32768;
    int tid = threadIdx.x;
    for (int idx = tid; idx < 2048; idx += 512) {
        int r = idx >> 4, g16 = idx & 15;
        int kc = g16 >> 3, gg = g16 & 7;
        const float* src = W + (size_t)r*DPC + kc*64 + gg*8;
        float4 t0 = *(const float4*)src;
        float4 t1 = *(const float4*)(src + 4);
        uint4 o;
        o.x = pk2(t0.x,t0.y); o.y = pk2(t0.z,t0.w);
        o.z = pk2(t1.x,t1.y); o.w = pk2(t1.z,t1.w);
        *(uint4*)(dst + kc*16384 + r*128 + ((gg ^ (r&7))<<4)) = o;
    }
}

// -------- fused kernel A: proj (blocks 0..NB_PROJ) + bias (rest) -------------
__global__ void __launch_bounds__(512,2) pb_kernel(
    const float* __restrict__ pair, const float* __restrict__ biasp,
    const float* __restrict__ lnpg, const float* __restrict__ lnpb,
    const float* __restrict__ lnbg, const float* __restrict__ lnbb,
    const float* __restrict__ bg, const float* __restrict__ Wb)
{
    extern __shared__ unsigned char sm[];
    int tid = threadIdx.x, lane = tid & 31, wid = tid >> 5;

    if (blockIdx.x < NB_PROJ) {
        // ================= proj =================
        unsigned sXa = (unsigned)__cvta_generic_to_shared(sm);   // 2 x 16KB LN'ed X
        unsigned sWa = sXa + 32768;                              // 2 x 32KB W double buffer
        int wm = wid & 3, wn = wid >> 2;     // 4m x 4n warps, tile 32x32
        int row0 = blockIdx.x * 128;
        int nn = row0 / LREF, i0b = row0 % LREF;

        auto stageW = [&](int mat) {
            const unsigned char* src = g_wbf + (size_t)mat * 32768;
            unsigned buf = sWa + (unsigned)(mat & 1) * 32768;
#pragma unroll
            for (int k = 0; k < 4; k++) {
                unsigned off = (unsigned)(tid + k*512) * 16;
                cpa16(buf + off, src + off);
            }
            cpa_commit();
        };
        stageW(0);   // group 0
        stageW(1);   // group 1

        // warp-cooperative single-pass LN: warp handles 8 rows
        for (int rr = 0; rr < 8; rr++) {
            int r = wid * 8 + rr;
            int i = i0b + r;
            const float* x = pair + ((size_t)i*LREF + nn) * DPC;
            float4 t = *(const float4*)(x + lane*4);
            float s  = t.x + t.y + t.z + t.w;
            float s2 = t.x*t.x + t.y*t.y + t.z*t.z + t.w*t.w;
#pragma unroll
            for (int o = 16; o; o >>= 1) {
                s  += __shfl_xor_sync(0xffffffffu, s,  o);
                s2 += __shfl_xor_sync(0xffffffffu, s2, o);
            }
            float mean = s * (1.f/DPC);
            float rstd = rsqrtf(s2 * (1.f/DPC) - mean*mean + 1e-5f);
            float4 wv = *(const float4*)(lnpg + lane*4);
            float4 bv = *(const float4*)(lnpb + lane*4);
            unsigned p0 = pk2((t.x-mean)*rstd*wv.x + bv.x, (t.y-mean)*rstd*wv.y + bv.y);
            unsigned p1 = pk2((t.z-mean)*rstd*wv.z + bv.z, (t.w-mean)*rstd*wv.w + bv.w);
            int kc = lane >> 4, g = (lane & 15) >> 1;
            *(uint2*)(sm + kc*16384 + r*128 + ((g ^ (r&7))<<4) + (lane&1)*8) = make_uint2(p0, p1);
        }

        for (int mat = 0; mat < 4; mat++) {
            if (mat < 3) cpa_wait<1>(); else cpa_wait<0>();
            __syncthreads();   // W(mat) visible + (mat==0: LN writes visible)

            unsigned bufW = sWa + (unsigned)(mat & 1) * 32768;
            float acc[2][4][4];
#pragma unroll
            for (int a = 0; a < 2; a++)
#pragma unroll
                for (int b = 0; b < 4; b++)
#pragma unroll
                    for (int cc = 0; cc < 4; cc++) acc[a][b][cc] = 0.f;
#pragma unroll
            for (int kc = 0; kc < 2; kc++)
#pragma unroll
                for (int kk = 0; kk < 4; kk++)
                    wstep<2,4>(acc, sXa + kc*16384, bufW + kc*16384, wm*32, wn*32, kk*16, lane);
            __syncthreads();   // all warps done reading this W buffer

            // ---- stage results to smem (overwrites just-consumed W buffer) ----
            unsigned char* smTb = sm + 32768 + (size_t)(mat & 1) * 32768;
            unsigned char* smT8 = smTb;
            bf16* smT16 = (bf16*)smTb;
#pragma unroll
            for (int mt = 0; mt < 2; mt++)
#pragma unroll
                for (int nt = 0; nt < 4; nt++) {
                    float* ac = acc[mt][nt];
                    int rl = wm*32 + mt*16 + (lane >> 2);
                    int c  = wn*32 + nt*8 + 2*(lane & 3);
#pragma unroll
                    for (int half = 0; half < 2; half++) {
                        int il = rl + half*8;
                        float v0 = ac[half*2+0], v1 = ac[half*2+1];
                        if (mat < 2) {
                            *(unsigned short*)&smT8[il*128 + c] = pk8(v0, v1);
                        } else if (mat == 2) {
                            smT16[(c)  *128 + il] = __float2bfloat16_rn(v0);
                            smT16[(c+1)*128 + il] = __float2bfloat16_rn(v1);
                        } else {
                            float z0 = v0 + bg[c], z1 = v1 + bg[c+1];
                            *(bf162*)&smT16[il*128 + c] =
                                __floats2bfloat162_rn(1.f/(1.f+expf(-z0)), 1.f/(1.f+expf(-z1)));
                        }
                    }
                }
            __syncthreads();

            // ---- coalesced global writes ----
            if (mat < 2) {
                unsigned char* dst = (mat == 0) ? g_q8 : g_k8;
#pragma unroll
                for (int k = 0; k < 8; k++) {
                    int idx = tid + k*512;
                    int i = idx >> 5, seg = idx & 31;
                    int c4 = seg*4;
                    int hh = c4 >> 5, d = c4 & 31;
                    *(unsigned*)&dst[((size_t)(hh*LREF + i0b + i))*KTOT + nn*DHD + d] =
                        *(unsigned*)&smT8[i*128 + c4];
                }
            } else if (mat == 2) {
#pragma unroll
                for (int k = 0; k < 4; k++) {
                    int idx = tid + k*512;
                    int col = idx >> 4, seg = idx & 15;
                    int hh = col >> 5, d = col & 31;
                    *(uint4*)&g_v2[((size_t)hh*KTOT + nn*DHD + d)*LREF + i0b + seg*8] =
                        *(uint4*)&smT16[col*128 + seg*8];
                }
            } else {
#pragma unroll
                for (int k = 0; k < 4; k++) {
                    int idx = tid + k*512;
                    int i = idx >> 4, seg = idx & 15;
                    *(uint4*)&g_gateb[((size_t)(nn*LREF + i0b + i))*DPC + seg*8] =
                        *(uint4*)&smT16[i*128 + seg*8];
                }
            }
            __syncthreads();   // staging buffer free
            if (mat + 2 < 4) stageW(mat + 2);   // prefetch into the freed buffer
        }
    } else {
        // ================= bias =================
        float* sWb = (float*)sm;           // 4*128 floats
        int bid = blockIdx.x - NB_PROJ;
        for (int c = tid; c < 4*DPC; c += 512) sWb[c] = Wb[c];
        __syncthreads();

        float4 wg = *(const float4*)(lnbg + lane*4);
        float4 wb = *(const float4*)(lnbb + lane*4);
        float4 W0 = *(const float4*)(sWb + 0*DPC + lane*4);
        float4 W1 = *(const float4*)(sWb + 1*DPC + lane*4);
        float4 W2 = *(const float4*)(sWb + 2*DPC + lane*4);
        float4 W3 = *(const float4*)(sWb + 3*DPC + lane*4);

        for (int rr = 0; rr < 2; rr++) {
            int row = bid*32 + wid*2 + rr;    // row = i*L + j
            int i = row / LREF, j = row - i*LREF;
            const float* x = biasp + ((size_t)j*LREF + i) * DPC;
            float4 t = *(const float4*)(x + lane*4);
            float s  = t.x + t.y + t.z + t.w;
            float s2 = t.x*t.x + t.y*t.y + t.z*t.z + t.w*t.w;
#pragma unroll
            for (int o = 16; o; o >>= 1) {
                s  += __shfl_xor_sync(0xffffffffu, s,  o);
                s2 += __shfl_xor_sync(0xffffffffu, s2, o);
            }
            float mean = s * (1.f/DPC);
            float rstd = rsqrtf(s2 * (1.f/DPC) - mean*mean + 1e-5f);
            float e0 = (t.x-mean)*rstd*wg.x + wb.x;
            float e1 = (t.y-mean)*rstd*wg.y + wb.y;
            float e2 = (t.z-mean)*rstd*wg.z + wb.z;
            float e3 = (t.w-mean)*rstd*wg.w + wb.w;
            float p0 = e0*W0.x + e1*W0.y + e2*W0.z + e3*W0.w;
            float p1 = e0*W1.x + e1*W1.y + e2*W1.z + e3*W1.w;
            float p2 = e0*W2.x + e1*W2.y + e2*W2.z + e3*W2.w;
            float p3 = e0*W3.x + e1*W3.y + e2*W3.z + e3*W3.w;
#pragma unroll
            for (int o = 16; o; o >>= 1) {
                p0 += __shfl_xor_sync(0xffffffffu, p0, o);
                p1 += __shfl_xor_sync(0xffffffffu, p1, o);
                p2 += __shfl_xor_sync(0xffffffffu, p2, o);
                p3 += __shfl_xor_sync(0xffffffffu, p3, o);
            }
            if (lane == 0) {
                g_attn[((size_t)0*LREF + i)*LREF + j] = p0;
                g_attn[((size_t)1*LREF + i)*LREF + j] = p1;
                g_attn[((size_t)2*LREF + i)*LREF + j] = p2;
                g_attn[((size_t)3*LREF + i)*LREF + j] = p3;
            }
        }
    }
}

// -------- kernel C: attn += scale*(q8.k8)  (256 thr, 32x64 warp tile) --------
__global__ void __launch_bounds__(256,2) score_kernel()
{
    extern __shared__ unsigned char sm[];
    unsigned sbase = (unsigned)__cvta_generic_to_shared(sm);   // 3 x 32KB (A16+B16)
    int tid = threadIdx.x, lane = tid & 31, warp = tid >> 5;
    int wm = warp & 3, wn = warp >> 2;      // 4m x 2n, warp tile 32x64
    int h = blockIdx.z >> 3, ks = blockIdx.z & 7;
    int i0 = blockIdx.x * 128, j0 = blockIdx.y * 128;

    const unsigned char* ga = g_q8 + ((size_t)(h*LREF + i0))*KTOT + ks*(KTOT/8);
    const unsigned char* gb = g_k8 + ((size_t)(h*LREF + j0))*KTOT + ks*(KTOT/8);

    float acc[2][8][4];
#pragma unroll
    for (int a = 0; a < 2; a++)
#pragma unroll
        for (int b = 0; b < 8; b++)
#pragma unroll
            for (int cc = 0; cc < 4; cc++) acc[a][b][cc] = 0.f;

    const int NIT = (KTOT/8)/128;   // 12
    auto stage = [&](int it) {
        unsigned buf = sbase + (unsigned)(it % 3) * 32768;
        for (int c = tid; c < 1024; c += 256) {
            int r = c >> 3, g = c & 7;
            unsigned d = r*128 + ((g ^ (r&7))<<4);
            cpa16(buf + d,         ga + (size_t)r*KTOT + it*128 + g*16);
            cpa16(buf + 16384 + d, gb + (size_t)r*KTOT + it*128 + g*16);
        }
        cpa_commit();
    };
    stage(0); stage(1);
    for (int it = 0; it < NIT; it++) {
        if (it < NIT-1) cpa_wait<1>(); else cpa_wait<0>();
        __syncthreads();
        unsigned buf = sbase + (unsigned)(it % 3) * 32768;
#pragma unroll
        for (int kk = 0; kk < 4; kk++)
            wstep8<2,8>(acc, buf, buf + 16384, wm*32, wn*64, kk*32, lane);
        if (it + 2 < NIT) stage(it + 2);
    }

    const float SC = 0.17677669529663687f / 384.0f;
#pragma unroll
    for (int mt = 0; mt < 2; mt++)
#pragma unroll
        for (int nt = 0; nt < 8; nt++) {
            float* ac = acc[mt][nt];
            int r = i0 + wm*32 + mt*16 + (lane >> 2);
            int c = j0 + wn*64 + nt*8 + 2*(lane & 3);
            size_t base = ((size_t)h*LREF + r)*LREF + c;
            atomicAdd(&g_attn[base],            ac[0]*SC);
            atomicAdd(&g_attn[base + 1],        ac[1]*SC);
            atomicAdd(&g_attn[base + 8*LREF],   ac[2]*SC);
            atomicAdd(&g_attn[base + 8*LREF+1], ac[3]*SC);
        }
}

// -------- softmax over j per (h,i): fp32 in, bf16 out ------------------------
__global__ void __launch_bounds__(128) softmax_kernel()
{
    int i = blockIdx.x, h = blockIdx.y;
    const float* row = g_attn + ((size_t)h * LREF + i) * LREF;
    bf16* orow = g_attnb + ((size_t)h * LREF + i) * LREF;
    int tid = threadIdx.x, warp = tid >> 5, lane = tid & 31;
    __shared__ float smax[4], ssum[4];

    float a0 = row[tid], a1 = row[tid + 128], a2 = row[tid + 256];
    float m = fmaxf(a0, fmaxf(a1, a2));
#pragma unroll
    for (int o = 16; o; o >>= 1) m = fmaxf(m, __shfl_xor_sync(0xffffffffu, m, o));
    if (lane == 0) smax[warp] = m;
    __syncthreads();
    float M = fmaxf(fmaxf(smax[0], smax[1]), fmaxf(smax[2], smax[3]));

    float e0 = expf(a0 - M), e1 = expf(a1 - M), e2 = expf(a2 - M);
    float s = e0 + e1 + e2;
#pragma unroll
    for (int o = 16; o; o >>= 1) s += __shfl_xor_sync(0xffffffffu, s, o);
    if (lane == 0) ssum[warp] = s;
    __syncthreads();
    float S = ssum[0] + ssum[1] + ssum[2] + ssum[3];
    float inv = 1.f / S;
    orow[tid]       = __float2bfloat16_rn(e0 * inv);
    orow[tid + 128] = __float2bfloat16_rn(e1 * inv);
    orow[tid + 256] = __float2bfloat16_rn(e2 * inv);
}

// -------- kernel D: om = gate .* (attn_b @ v2^T)  (256 thr, 32x64 tile) ------
__global__ void __launch_bounds__(256,2) av_kernel()
{
    extern __shared__ unsigned char sm[];
    unsigned sbase = (unsigned)__cvta_generic_to_shared(sm);   // 3 x 32KB
    int tid = threadIdx.x, lane = tid & 31, warp = tid >> 5;
    int wm = warp & 3, wn = warp >> 2;      // 4m x 2n, warp tile 32x64
    int i0 = blockIdx.x * 128, col0 = blockIdx.y * 128, h = blockIdx.z;

    const bf16* ga = g_attnb + ((size_t)(h*LREF + i0))*LREF;
    const bf16* gv = g_v2 + ((size_t)h*KTOT + col0)*LREF;

    float acc[2][8][4];
#pragma unroll
    for (int a = 0; a < 2; a++)
#pragma unroll
        for (int b = 0; b < 8; b++)
#pragma unroll
            for (int cc = 0; cc < 4; cc++) acc[a][b][cc] = 0.f;

    const int NIT = LREF/64;   // 6
    auto stage = [&](int it) {
        unsigned buf = sbase + (unsigned)(it % 3) * 32768;
        for (int c = tid; c < 1024; c += 256) {
            int r = c >> 3, g = c & 7;
            unsigned d = r*128 + ((g ^ (r&7))<<4);
            cpa16(buf + d,         ga + (size_t)r*LREF + it*64 + g*8);
            cpa16(buf + 16384 + d, gv + (size_t)r*LREF + it*64 + g*8);
        }
        cpa_commit();
    };
    stage(0); stage(1);
    for (int it = 0; it < NIT; it++) {
        if (it < NIT-1) cpa_wait<1>(); else cpa_wait<0>();
        __syncthreads();
        unsigned buf = sbase + (unsigned)(it % 3) * 32768;
#pragma unroll
        for (int kk = 0; kk < 4; kk++)
            wstep<2,8>(acc, buf, buf + 16384, wm*32, wn*64, kk*16, lane);
        if (it + 2 < NIT) stage(it + 2);
    }

#pragma unroll
    for (int mt = 0; mt < 2; mt++)
#pragma unroll
        for (int nt = 0; nt < 8; nt++) {
            float* ac = acc[mt][nt];
            int c = col0 + wn*64 + nt*8 + 2*(lane & 3);
            int n = c >> 5, d = c & 31;
#pragma unroll
            for (int half = 0; half < 2; half++) {
                int i = i0 + wm*32 + mt*16 + (lane >> 2) + half*8;
                size_t ofs = ((size_t)n*LREF + i)*DPC + h*DHD + d;
                bf162 gv2 = *(const bf162*)&g_gateb[ofs];
                bf162 r2 = __floats2bfloat162_rn(ac[half*2+0], ac[half*2+1]);
                *(bf162*)&g_omb[ofs] = __hmul2(gv2, r2);
            }
        }
}

// -------- kernel E: y = omb @ Wo^T + bo, write transposed --------------------
__global__ void __launch_bounds__(512,2) out_kernel(
    const float* __restrict__ bo, float* __restrict__ outp)
{
    extern __shared__ unsigned char sm[];
    unsigned sXa = (unsigned)__cvta_generic_to_shared(sm);   // 2 x 16KB
    unsigned sWa = sXa + 32768;                              // 32KB
    int tid = threadIdx.x, lane = tid & 31, warp = tid >> 5;
    int wm = warp & 3, wn = warp >> 2;
    int row0 = blockIdx.x * 128;

    // cpa X from g_omb (already gate-multiplied): swizzled per k-chunk layout
    {
        const unsigned char* srcX = (const unsigned char*)g_omb + (size_t)row0 * 256;
        for (int idx = tid; idx < 2048; idx += 512) {
            int r = idx >> 4, g16 = idx & 15;
            int kc = g16 >> 3, gg = g16 & 7;
            cpa16(sXa + kc*16384 + r*128 + ((gg ^ (r&7))<<4),
                  srcX + (size_t)r*256 + kc*128 + gg*16);
        }
        cpa_commit();
        // cpa Wo (pre-swizzled global)
        const unsigned char* srcW = g_wbf + 4*32768;
#pragma unroll
        for (int k = 0; k < 4; k++) {
            unsigned off = (unsigned)(tid + k*512) * 16;
            cpa16(sWa + off, srcW + off);
        }
        cpa_commit();
    }
    cpa_wait<0>();
    __syncthreads();

    float acc[2][4][4];
#pragma unroll
    for (int a = 0; a < 2; a++)
#pragma unroll
        for (int b = 0; b < 4; b++)
#pragma unroll
            for (int cc = 0; cc < 4; cc++) acc[a][b][cc] = 0.f;

#pragma unroll
    for (int kc = 0; kc < 2; kc++)
#pragma unroll
        for (int kk = 0; kk < 4; kk++)
            wstep<2,4>(acc, sXa + kc*16384, sWa + kc*16384, wm*32, wn*32, kk*16, lane);

#pragma unroll
    for (int mt = 0; mt < 2; mt++)
#pragma unroll
        for (int nt = 0; nt < 4; nt++) {
            float* ac = acc[mt][nt];
            int rl = wm*32 + mt*16 + (lane >> 2);
            int c  = wn*32 + nt*8 + 2*(lane & 3);
            float b0 = bo[c], b1 = bo[c+1];
#pragma unroll
            for (int half = 0; half < 2; half++) {
                int row = row0 + rl + half*8;
                int n = row / LREF, i = row - n*LREF;
                *(float2*)&outp[((size_t)i*LREF + n)*DPC + c] =
                    make_float2(ac[half*2+0] + b0, ac[half*2+1] + b1);
            }
        }
}

extern "C" void kernel_launch(void* const* d_in, const int* in_sizes, int n_in,
                              void* d_out, int out_size)
{
    (void)in_sizes; (void)n_in; (void)out_size;
    const float* pair      = (const float*)d_in[0];
    const float* bias      = (const float*)d_in[1];
    const float* ln_pair_g = (const float*)d_in[2];
    const float* ln_pair_b = (const float*)d_in[3];
    const float* ln_bias_g = (const float*)d_in[4];
    const float* ln_bias_b = (const float*)d_in[5];
    const float* Wq = (const float*)d_in[6];
    const float* Wk = (const float*)d_in[7];
    const float* Wv = (const float*)d_in[8];
    const float* Wb = (const float*)d_in[9];
    const float* Wg = (const float*)d_in[10];
    const float* bg = (const float*)d_in[11];
    const float* Wo = (const float*)d_in[12];
    const float* bo = (const float*)d_in[13];
    float* outp = (float*)d_out;

    const int PB_SMEM  = 98304;   // 32KB X + 2x32KB W buffers
    const int SMEM3    = 98304;   // 3-stage pipelined GEMMs (score, av)
    const int OUT_SMEM = 65536;   // 32KB X + 32KB Wo
    cudaFuncSetAttribute(pb_kernel,    cudaFuncAttributeMaxDynamicSharedMemorySize, PB_SMEM);
    cudaFuncSetAttribute(score_kernel, cudaFuncAttributeMaxDynamicSharedMemorySize, SMEM3);
    cudaFuncSetAttribute(av_kernel,    cudaFuncAttributeMaxDynamicSharedMemorySize, SMEM3);
    cudaFuncSetAttribute(out_kernel,   cudaFuncAttributeMaxDynamicSharedMemorySize, OUT_SMEM);

    wconv_kernel<<<5, 512>>>(Wq, Wk, Wv, Wg, Wo);
    pb_kernel<<<NB_PROJ + NB_BIAS, 512, PB_SMEM>>>(pair, bias,
        ln_pair_g, ln_pair_b, ln_bias_g, ln_bias_b, bg, Wb);
    score_kernel<<<dim3(3, 3, 32), 256, SMEM3>>>();
    softmax_kernel<<<dim3(LREF, HN), 128>>>();
    av_kernel<<<dim3(3, KTOT/128, HN), 256, SMEM3>>>();
    out_kernel<<<LREF*LREF/128, 512, OUT_SMEM>>>(bo, outp);
}

// round 14
// speedup vs baseline: 1.7226x; 1.0198x over previous
#include <cuda_runtime.h>
#include <cuda_bf16.h>
#include <math.h>

#define LREF 384
#define DPC 128
#define HN 4
#define DHD 32
#define KTOT (LREF*DHD)   // 12288

typedef __nv_bfloat16 bf16;
typedef __nv_bfloat162 bf162;

#define NB_PROJ (LREF*LREF/128)   // 1152
#define NB_BIAS (LREF*LREF/64)    // 2304

// ---------------- scratch (device globals) ----------------------------------
__device__ unsigned char g_q8[(size_t)HN*LREF*KTOT]; // [h][i][n*32+d] e4m3, unscaled
__device__ unsigned char g_k8[(size_t)HN*LREF*KTOT]; // [h][j][n*32+d] e4m3, unscaled
__device__ bf16 g_v2[(size_t)HN*KTOT*LREF];     // [h][col=n*32+d][j]  K-major(j)
__device__ bf16 g_gateb[(size_t)LREF*LREF*DPC]; // [row=n*L+i][c]
__device__ bf16 g_omb[(size_t)LREF*LREF*DPC];   // [row=n*L+i][h*32+d]  (gate-multiplied)
__device__ float g_attn[(size_t)HN*LREF*LREF];  // fp32 logits (bias-init + atomics)
__device__ bf16 g_attnb[(size_t)HN*LREF*LREF];  // softmaxed, bf16
__device__ unsigned char g_wbf[5*32768];        // bf16 weights, pre-swizzled smem layout

// ---------------- ptx helpers ------------------------------------------------
__device__ __forceinline__ void ldsm4(unsigned &r0,unsigned &r1,unsigned &r2,unsigned &r3,unsigned a){
    asm volatile("ldmatrix.sync.aligned.m8n8.x4.shared.b16 {%0,%1,%2,%3},[%4];"
        :"=r"(r0),"=r"(r1),"=r"(r2),"=r"(r3):"r"(a));
}
__device__ __forceinline__ void mma_bf16(float c[4], const unsigned a[4], const unsigned b[2]){
    asm volatile("mma.sync.aligned.m16n8k16.row.col.f32.bf16.bf16.f32 "
        "{%0,%1,%2,%3},{%4,%5,%6,%7},{%8,%9},{%0,%1,%2,%3};"
        :"+f"(c[0]),"+f"(c[1]),"+f"(c[2]),"+f"(c[3])
        :"r"(a[0]),"r"(a[1]),"r"(a[2]),"r"(a[3]),"r"(b[0]),"r"(b[1]));
}
__device__ __forceinline__ void mma_fp8(float c[4], const unsigned a[4], const unsigned b[2]){
    asm volatile("mma.sync.aligned.m16n8k32.row.col.f32.e4m3.e4m3.f32 "
        "{%0,%1,%2,%3},{%4,%5,%6,%7},{%8,%9},{%0,%1,%2,%3};"
        :"+f"(c[0]),"+f"(c[1]),"+f"(c[2]),"+f"(c[3])
        :"r"(a[0]),"r"(a[1]),"r"(a[2]),"r"(a[3]),"r"(b[0]),"r"(b[1]));
}
__device__ __forceinline__ void cpa16(unsigned saddr, const void* g) {
    asm volatile("cp.async.cg.shared.global [%0],[%1],16;\n" :: "r"(saddr), "l"(g));
}
__device__ __forceinline__ void cpa_commit() { asm volatile("cp.async.commit_group;\n"); }
template<int N>
__device__ __forceinline__ void cpa_wait() { asm volatile("cp.async.wait_group %0;\n" :: "n"(N)); }

__device__ __forceinline__ unsigned pk2(float a, float b){
    bf162 t = __floats2bfloat162_rn(a, b);
    return *(unsigned*)&t;
}
__device__ __forceinline__ unsigned short pk8(float lo, float hi){
    unsigned short u;
    asm("cvt.rn.satfinite.e4m3x2.f32 %0, %2, %1;" : "=h"(u) : "f"(lo), "f"(hi));
    return u;
}

// warp k16-step (bf16): A rows 128B [m][k64], B rows 128B [n][k64], SW128-swizzled
template<int MT,int NT>
__device__ __forceinline__ void wstep(float (&acc)[MT][NT][4], unsigned sA, unsigned sB,
                                      int m0, int n0, int k0, int lane)
{
    unsigned a[MT][4];
    int arow = lane & 15, acg = (k0>>3) + (lane>>4);
#pragma unroll
    for (int mt = 0; mt < MT; mt++) {
        int r = m0 + mt*16 + arow;
        ldsm4(a[mt][0],a[mt][1],a[mt][2],a[mt][3], sA + r*128 + ((acg ^ (r&7))<<4));
    }
    int brow_off = (lane & 7) + ((lane>>4)<<3);
    int bcg = (k0>>3) + ((lane>>3)&1);
#pragma unroll
    for (int nt = 0; nt < NT; nt += 2) {
        int r = n0 + nt*8 + brow_off;
        unsigned b[4];
        ldsm4(b[0],b[1],b[2],b[3], sB + r*128 + ((bcg ^ (r&7))<<4));
#pragma unroll
        for (int mt = 0; mt < MT; mt++) {
            mma_bf16(acc[mt][nt],   a[mt], b);
            mma_bf16(acc[mt][nt+1], a[mt], b+2);
        }
    }
}

// warp k32-step (fp8): A rows 128B [m][k128 bytes], B rows 128B [n][k128 bytes]
template<int MT,int NT>
__device__ __forceinline__ void wstep8(float (&acc)[MT][NT][4], unsigned sA, unsigned sB,
                                       int m0, int n0, int kb, int lane)
{
    unsigned a[MT][4];
    int arow = lane & 15, acg = (kb>>4) + (lane>>4);
#pragma unroll
    for (int mt = 0; mt < MT; mt++) {
        int r = m0 + mt*16 + arow;
        ldsm4(a[mt][0],a[mt][1],a[mt][2],a[mt][3], sA + r*128 + ((acg ^ (r&7))<<4));
    }
    int brow_off = (lane & 7) + ((lane>>4)<<3);
    int bcg = (kb>>4) + ((lane>>3)&1);
#pragma unroll
    for (int nt = 0; nt < NT; nt += 2) {
        int r = n0 + nt*8 + brow_off;
        unsigned b[4];
        ldsm4(b[0],b[1],b[2],b[3], sB + r*128 + ((bcg ^ (r&7))<<4));
#pragma unroll
        for (int mt = 0; mt < MT; mt++) {
            mma_fp8(acc[mt][nt],   a[mt], b);
            mma_fp8(acc[mt][nt+1], a[mt], b+2);
        }
    }
}

// -------- kernel 0: convert weights fp32 -> bf16, pre-swizzled ---------------
__global__ void __launch_bounds__(512) wconv_kernel(
    const float* __restrict__ Wq, const float* __restrict__ Wk, const float* __restrict__ Wv,
    const float* __restrict__ Wg, const float* __restrict__ Wo)
{
    const float* Ws[5] = { Wq, Wk, Wv, Wg, Wo };
    const float* W = Ws[blockIdx.x];
    unsigned char* dst = g_wbf + (size_t)blockIdx.x * 32768;
    int tid = threadIdx.x;
    for (int idx = tid; idx < 2048; idx += 512) {
        int r = idx >> 4, g16 = idx & 15;
        int kc = g16 >> 3, gg = g16 & 7;
        const float* src = W + (size_t)r*DPC + kc*64 + gg*8;
        float4 t0 = *(const float4*)src;
        float4 t1 = *(const float4*)(src + 4);
        uint4 o;
        o.x = pk2(t0.x,t0.y); o.y = pk2(t0.z,t0.w);
        o.z = pk2(t1.x,t1.y); o.w = pk2(t1.z,t1.w);
        *(uint4*)(dst + kc*16384 + r*128 + ((gg ^ (r&7))<<4)) = o;
    }
}

// -------- fused kernel A: proj (blocks 0..NB_PROJ) + bias (rest) -------------
__global__ void __launch_bounds__(512,2) pb_kernel(
    const float* __restrict__ pair, const float* __restrict__ biasp,
    const float* __restrict__ lnpg, const float* __restrict__ lnpb,
    const float* __restrict__ lnbg, const float* __restrict__ lnbb,
    const float* __restrict__ bg, const float* __restrict__ Wb)
{
    extern __shared__ unsigned char sm[];
    int tid = threadIdx.x, lane = tid & 31, wid = tid >> 5;

    if (blockIdx.x < NB_PROJ) {
        // ================= proj =================
        unsigned sXa = (unsigned)__cvta_generic_to_shared(sm);   // 2 x 16KB LN'ed X
        unsigned sWa = sXa + 32768;                              // 2 x 32KB W double buffer
        int wm = wid & 3, wn = wid >> 2;     // 4m x 4n warps, tile 32x32
        int row0 = blockIdx.x * 128;
        int nn = row0 / LREF, i0b = row0 % LREF;

        auto stageW = [&](int mat) {
            const unsigned char* src = g_wbf + (size_t)mat * 32768;
            unsigned buf = sWa + (unsigned)(mat & 1) * 32768;
#pragma unroll
            for (int k = 0; k < 4; k++) {
                unsigned off = (unsigned)(tid + k*512) * 16;
                cpa16(buf + off, src + off);
            }
            cpa_commit();
        };
        stageW(0);   // group 0
        stageW(1);   // group 1

        // warp-cooperative single-pass LN: warp handles 8 rows
        for (int rr = 0; rr < 8; rr++) {
            int r = wid * 8 + rr;
            int i = i0b + r;
            const float* x = pair + ((size_t)i*LREF + nn) * DPC;
            float4 t = *(const float4*)(x + lane*4);
            float s  = t.x + t.y + t.z + t.w;
            float s2 = t.x*t.x + t.y*t.y + t.z*t.z + t.w*t.w;
#pragma unroll
            for (int o = 16; o; o >>= 1) {
                s  += __shfl_xor_sync(0xffffffffu, s,  o);
                s2 += __shfl_xor_sync(0xffffffffu, s2, o);
            }
            float mean = s * (1.f/DPC);
            float rstd = rsqrtf(s2 * (1.f/DPC) - mean*mean + 1e-5f);
            float4 wv = *(const float4*)(lnpg + lane*4);
            float4 bv = *(const float4*)(lnpb + lane*4);
            unsigned p0 = pk2((t.x-mean)*rstd*wv.x + bv.x, (t.y-mean)*rstd*wv.y + bv.y);
            unsigned p1 = pk2((t.z-mean)*rstd*wv.z + bv.z, (t.w-mean)*rstd*wv.w + bv.w);
            int kc = lane >> 4, g = (lane & 15) >> 1;
            *(uint2*)(sm + kc*16384 + r*128 + ((g ^ (r&7))<<4) + (lane&1)*8) = make_uint2(p0, p1);
        }

        for (int mat = 0; mat < 4; mat++) {
            if (mat < 3) cpa_wait<1>(); else cpa_wait<0>();
            __syncthreads();   // W(mat) visible + (mat==0: LN writes visible)

            unsigned bufW = sWa + (unsigned)(mat & 1) * 32768;
            float acc[2][4][4];
#pragma unroll
            for (int a = 0; a < 2; a++)
#pragma unroll
                for (int b = 0; b < 4; b++)
#pragma unroll
                    for (int cc = 0; cc < 4; cc++) acc[a][b][cc] = 0.f;
#pragma unroll
            for (int kc = 0; kc < 2; kc++)
#pragma unroll
                for (int kk = 0; kk < 4; kk++)
                    wstep<2,4>(acc, sXa + kc*16384, bufW + kc*16384, wm*32, wn*32, kk*16, lane);
            __syncthreads();   // all warps done reading this W buffer

            // ---- stage results to smem (overwrites just-consumed W buffer) ----
            unsigned char* smTb = sm + 32768 + (size_t)(mat & 1) * 32768;
            unsigned char* smT8 = smTb;
            bf16* smT16 = (bf16*)smTb;
#pragma unroll
            for (int mt = 0; mt < 2; mt++)
#pragma unroll
                for (int nt = 0; nt < 4; nt++) {
                    float* ac = acc[mt][nt];
                    int rl = wm*32 + mt*16 + (lane >> 2);
                    int c  = wn*32 + nt*8 + 2*(lane & 3);
#pragma unroll
                    for (int half = 0; half < 2; half++) {
                        int il = rl + half*8;
                        float v0 = ac[half*2+0], v1 = ac[half*2+1];
                        if (mat < 2) {
                            *(unsigned short*)&smT8[il*128 + c] = pk8(v0, v1);
                        } else if (mat == 2) {
                            smT16[(c)  *128 + il] = __float2bfloat16_rn(v0);
                            smT16[(c+1)*128 + il] = __float2bfloat16_rn(v1);
                        } else {
                            float z0 = v0 + bg[c], z1 = v1 + bg[c+1];
                            *(bf162*)&smT16[il*128 + c] =
                                __floats2bfloat162_rn(1.f/(1.f+expf(-z0)), 1.f/(1.f+expf(-z1)));
                        }
                    }
                }
            __syncthreads();

            // ---- coalesced global writes ----
            if (mat < 2) {
                unsigned char* dst = (mat == 0) ? g_q8 : g_k8;
#pragma unroll
                for (int k = 0; k < 8; k++) {
                    int idx = tid + k*512;
                    int i = idx >> 5, seg = idx & 31;
                    int c4 = seg*4;
                    int hh = c4 >> 5, d = c4 & 31;
                    *(unsigned*)&dst[((size_t)(hh*LREF + i0b + i))*KTOT + nn*DHD + d] =
                        *(unsigned*)&smT8[i*128 + c4];
                }
            } else if (mat == 2) {
#pragma unroll
                for (int k = 0; k < 4; k++) {
                    int idx = tid + k*512;
                    int col = idx >> 4, seg = idx & 15;
                    int hh = col >> 5, d = col & 31;
                    *(uint4*)&g_v2[((size_t)hh*KTOT + nn*DHD + d)*LREF + i0b + seg*8] =
                        *(uint4*)&smT16[col*128 + seg*8];
                }
            } else {
#pragma unroll
                for (int k = 0; k < 4; k++) {
                    int idx = tid + k*512;
                    int i = idx >> 4, seg = idx & 15;
                    *(uint4*)&g_gateb[((size_t)(nn*LREF + i0b + i))*DPC + seg*8] =
                        *(uint4*)&smT16[i*128 + seg*8];
                }
            }
            __syncthreads();   // staging buffer free
            if (mat + 2 < 4) stageW(mat + 2);   // prefetch into the freed buffer
        }
    } else {
        // ================= bias: 64 rows/block, 4 rows/warp =================
        float* sWb = (float*)sm;           // 4*128 floats
        int bid = blockIdx.x - NB_PROJ;
        for (int c = tid; c < 4*DPC; c += 512) sWb[c] = Wb[c];
        __syncthreads();

        float4 wg = *(const float4*)(lnbg + lane*4);
        float4 wb = *(const float4*)(lnbb + lane*4);
        float4 W0 = *(const float4*)(sWb + 0*DPC + lane*4);
        float4 W1 = *(const float4*)(sWb + 1*DPC + lane*4);
        float4 W2 = *(const float4*)(sWb + 2*DPC + lane*4);
        float4 W3 = *(const float4*)(sWb + 3*DPC + lane*4);

        for (int rr = 0; rr < 4; rr++) {
            int row = bid*64 + wid*4 + rr;    // row = i*L + j
            int i = row / LREF, j = row - i*LREF;
            const float* x = biasp + ((size_t)j*LREF + i) * DPC;
            float4 t = *(const float4*)(x + lane*4);
            float s  = t.x + t.y + t.z + t.w;
            float s2 = t.x*t.x + t.y*t.y + t.z*t.z + t.w*t.w;
#pragma unroll
            for (int o = 16; o; o >>= 1) {
                s  += __shfl_xor_sync(0xffffffffu, s,  o);
                s2 += __shfl_xor_sync(0xffffffffu, s2, o);
            }
            float mean = s * (1.f/DPC);
            float rstd = rsqrtf(s2 * (1.f/DPC) - mean*mean + 1e-5f);
            float e0 = (t.x-mean)*rstd*wg.x + wb.x;
            float e1 = (t.y-mean)*rstd*wg.y + wb.y;
            float e2 = (t.z-mean)*rstd*wg.z + wb.z;
            float e3 = (t.w-mean)*rstd*wg.w + wb.w;
            float p0 = e0*W0.x + e1*W0.y + e2*W0.z + e3*W0.w;
            float p1 = e0*W1.x + e1*W1.y + e2*W1.z + e3*W1.w;
            float p2 = e0*W2.x + e1*W2.y + e2*W2.z + e3*W2.w;
            float p3 = e0*W3.x + e1*W3.y + e2*W3.z + e3*W3.w;
#pragma unroll
            for (int o = 16; o; o >>= 1) {
                p0 += __shfl_xor_sync(0xffffffffu, p0, o);
                p1 += __shfl_xor_sync(0xffffffffu, p1, o);
                p2 += __shfl_xor_sync(0xffffffffu, p2, o);
                p3 += __shfl_xor_sync(0xffffffffu, p3, o);
            }
            if (lane == 0) {
                g_attn[((size_t)0*LREF + i)*LREF + j] = p0;
                g_attn[((size_t)1*LREF + i)*LREF + j] = p1;
                g_attn[((size_t)2*LREF + i)*LREF + j] = p2;
                g_attn[((size_t)3*LREF + i)*LREF + j] = p3;
            }
        }
    }
}

// -------- kernel C: attn += scale*(q8.k8)  (256 thr, 32x64 warp tile) --------
__global__ void __launch_bounds__(256,2) score_kernel()
{
    extern __shared__ unsigned char sm[];
    unsigned sbase = (unsigned)__cvta_generic_to_shared(sm);   // 3 x 32KB (A16+B16)
    int tid = threadIdx.x, lane = tid & 31, warp = tid >> 5;
    int wm = warp & 3, wn = warp >> 2;      // 4m x 2n, warp tile 32x64
    int h = blockIdx.z >> 3, ks = blockIdx.z & 7;
    int i0 = blockIdx.x * 128, j0 = blockIdx.y * 128;

    const unsigned char* ga = g_q8 + ((size_t)(h*LREF + i0))*KTOT + ks*(KTOT/8);
    const unsigned char* gb = g_k8 + ((size_t)(h*LREF + j0))*KTOT + ks*(KTOT/8);

    float acc[2][8][4];
#pragma unroll
    for (int a = 0; a < 2; a++)
#pragma unroll
        for (int b = 0; b < 8; b++)
#pragma unroll
            for (int cc = 0; cc < 4; cc++) acc[a][b][cc] = 0.f;

    const int NIT = (KTOT/8)/128;   // 12
    auto stage = [&](int it) {
        unsigned buf = sbase + (unsigned)(it % 3) * 32768;
        for (int c = tid; c < 1024; c += 256) {
            int r = c >> 3, g = c & 7;
            unsigned d = r*128 + ((g ^ (r&7))<<4);
            cpa16(buf + d,         ga + (size_t)r*KTOT + it*128 + g*16);
            cpa16(buf + 16384 + d, gb + (size_t)r*KTOT + it*128 + g*16);
        }
        cpa_commit();
    };
    stage(0); stage(1);
    for (int it = 0; it < NIT; it++) {
        if (it < NIT-1) cpa_wait<1>(); else cpa_wait<0>();
        __syncthreads();
        unsigned buf = sbase + (unsigned)(it % 3) * 32768;
#pragma unroll
        for (int kk = 0; kk < 4; kk++)
            wstep8<2,8>(acc, buf, buf + 16384, wm*32, wn*64, kk*32, lane);
        if (it + 2 < NIT) stage(it + 2);
    }

    const float SC = 0.17677669529663687f / 384.0f;
#pragma unroll
    for (int mt = 0; mt < 2; mt++)
#pragma unroll
        for (int nt = 0; nt < 8; nt++) {
            float* ac = acc[mt][nt];
            int r = i0 + wm*32 + mt*16 + (lane >> 2);
            int c = j0 + wn*64 + nt*8 + 2*(lane & 3);
            size_t base = ((size_t)h*LREF + r)*LREF + c;
            atomicAdd(&g_attn[base],            ac[0]*SC);
            atomicAdd(&g_attn[base + 1],        ac[1]*SC);
            atomicAdd(&g_attn[base + 8*LREF],   ac[2]*SC);
            atomicAdd(&g_attn[base + 8*LREF+1], ac[3]*SC);
        }
}

// -------- softmax over j per (h,i): fp32 in, bf16 out ------------------------
__global__ void __launch_bounds__(128) softmax_kernel()
{
    int i = blockIdx.x, h = blockIdx.y;
    const float* row = g_attn + ((size_t)h * LREF + i) * LREF;
    bf16* orow = g_attnb + ((size_t)h * LREF + i) * LREF;
    int tid = threadIdx.x, warp = tid >> 5, lane = tid & 31;
    __shared__ float smax[4], ssum[4];

    float a0 = row[tid], a1 = row[tid + 128], a2 = row[tid + 256];
    float m = fmaxf(a0, fmaxf(a1, a2));
#pragma unroll
    for (int o = 16; o; o >>= 1) m = fmaxf(m, __shfl_xor_sync(0xffffffffu, m, o));
    if (lane == 0) smax[warp] = m;
    __syncthreads();
    float M = fmaxf(fmaxf(smax[0], smax[1]), fmaxf(smax[2], smax[3]));

    float e0 = expf(a0 - M), e1 = expf(a1 - M), e2 = expf(a2 - M);
    float s = e0 + e1 + e2;
#pragma unroll
    for (int o = 16; o; o >>= 1) s += __shfl_xor_sync(0xffffffffu, s, o);
    if (lane == 0) ssum[warp] = s;
    __syncthreads();
    float S = ssum[0] + ssum[1] + ssum[2] + ssum[3];
    float inv = 1.f / S;
    orow[tid]       = __float2bfloat16_rn(e0 * inv);
    orow[tid + 128] = __float2bfloat16_rn(e1 * inv);
    orow[tid + 256] = __float2bfloat16_rn(e2 * inv);
}

// -------- kernel D: om = gate .* (attn_b @ v2^T)  (256 thr, 32x64 tile) ------
__global__ void __launch_bounds__(256,2) av_kernel()
{
    extern __shared__ unsigned char sm[];
    unsigned sbase = (unsigned)__cvta_generic_to_shared(sm);   // 3 x 32KB
    int tid = threadIdx.x, lane = tid & 31, warp = tid >> 5;
    int wm = warp & 3, wn = warp >> 2;      // 4m x 2n, warp tile 32x64
    int i0 = blockIdx.x * 128, col0 = blockIdx.y * 128, h = blockIdx.z;

    const bf16* ga = g_attnb + ((size_t)(h*LREF + i0))*LREF;
    const bf16* gv = g_v2 + ((size_t)h*KTOT + col0)*LREF;

    float acc[2][8][4];
#pragma unroll
    for (int a = 0; a < 2; a++)
#pragma unroll
        for (int b = 0; b < 8; b++)
#pragma unroll
            for (int cc = 0; cc < 4; cc++) acc[a][b][cc] = 0.f;

    const int NIT = LREF/64;   // 6
    auto stage = [&](int it) {
        unsigned buf = sbase + (unsigned)(it % 3) * 32768;
        for (int c = tid; c < 1024; c += 256) {
            int r = c >> 3, g = c & 7;
            unsigned d = r*128 + ((g ^ (r&7))<<4);
            cpa16(buf + d,         ga + (size_t)r*LREF + it*64 + g*8);
            cpa16(buf + 16384 + d, gv + (size_t)r*LREF + it*64 + g*8);
        }
        cpa_commit();
    };
    stage(0); stage(1);
    for (int it = 0; it < NIT; it++) {
        if (it < NIT-1) cpa_wait<1>(); else cpa_wait<0>();
        __syncthreads();
        unsigned buf = sbase + (unsigned)(it % 3) * 32768;
#pragma unroll
        for (int kk = 0; kk < 4; kk++)
            wstep<2,8>(acc, buf, buf + 16384, wm*32, wn*64, kk*16, lane);
        if (it + 2 < NIT) stage(it + 2);
    }

#pragma unroll
    for (int mt = 0; mt < 2; mt++)
#pragma unroll
        for (int nt = 0; nt < 8; nt++) {
            float* ac = acc[mt][nt];
            int c = col0 + wn*64 + nt*8 + 2*(lane & 3);
            int n = c >> 5, d = c & 31;
#pragma unroll
            for (int half = 0; half < 2; half++) {
                int i = i0 + wm*32 + mt*16 + (lane >> 2) + half*8;
                size_t ofs = ((size_t)n*LREF + i)*DPC + h*DHD + d;
                bf162 gv2 = *(const bf162*)&g_gateb[ofs];
                bf162 r2 = __floats2bfloat162_rn(ac[half*2+0], ac[half*2+1]);
                *(bf162*)&g_omb[ofs] = __hmul2(gv2, r2);
            }
        }
}

// -------- kernel E: y = omb @ Wo^T + bo (2 row-tiles/block) ------------------
__global__ void __launch_bounds__(512,2) out_kernel(
    const float* __restrict__ bo, float* __restrict__ outp)
{
    extern __shared__ unsigned char sm[];
    unsigned sXa = (unsigned)__cvta_generic_to_shared(sm);   // 2 tiles x 32KB X
    unsigned sWa = sXa + 65536;                              // 32KB Wo
    int tid = threadIdx.x, lane = tid & 31, warp = tid >> 5;
    int wm = warp & 3, wn = warp >> 2;

    // stage X for tile 0, Wo, then X for tile 1 (three cp.async groups)
    auto stageX = [&](int t) {
        int row0 = (blockIdx.x*2 + t) * 128;
        const unsigned char* srcX = (const unsigned char*)g_omb + (size_t)row0 * 256;
        unsigned dst = sXa + (unsigned)t * 32768;
        for (int idx = tid; idx < 2048; idx += 512) {
            int r = idx >> 4, g16 = idx & 15;
            int kc = g16 >> 3, gg = g16 & 7;
            cpa16(dst + kc*16384 + r*128 + ((gg ^ (r&7))<<4),
                  srcX + (size_t)r*256 + kc*128 + gg*16);
        }
        cpa_commit();
    };
    stageX(0);
    {
        const unsigned char* srcW = g_wbf + 4*32768;
#pragma unroll
        for (int k = 0; k < 4; k++) {
            unsigned off = (unsigned)(tid + k*512) * 16;
            cpa16(sWa + off, srcW + off);
        }
        cpa_commit();
    }
    stageX(1);

    float bb0, bb1;
    {
        int c = wn*32 + 2*(lane & 3);   // reused per nt below via offset
        (void)c;
    }

    for (int t = 0; t < 2; t++) {
        if (t == 0) cpa_wait<1>(); else cpa_wait<0>();
        __syncthreads();
        int row0 = (blockIdx.x*2 + t) * 128;
        unsigned sX = sXa + (unsigned)t * 32768;

        float acc[2][4][4];
#pragma unroll
        for (int a = 0; a < 2; a++)
#pragma unroll
            for (int b = 0; b < 4; b++)
#pragma unroll
                for (int cc = 0; cc < 4; cc++) acc[a][b][cc] = 0.f;

#pragma unroll
        for (int kc = 0; kc < 2; kc++)
#pragma unroll
            for (int kk = 0; kk < 4; kk++)
                wstep<2,4>(acc, sX + kc*16384, sWa + kc*16384, wm*32, wn*32, kk*16, lane);

#pragma unroll
        for (int mt = 0; mt < 2; mt++)
#pragma unroll
            for (int nt = 0; nt < 4; nt++) {
                float* ac = acc[mt][nt];
                int rl = wm*32 + mt*16 + (lane >> 2);
                int c  = wn*32 + nt*8 + 2*(lane & 3);
                bb0 = bo[c]; bb1 = bo[c+1];
#pragma unroll
                for (int half = 0; half < 2; half++) {
                    int row = row0 + rl + half*8;
                    int n = row / LREF, i = row - n*LREF;
                    *(float2*)&outp[((size_t)i*LREF + n)*DPC + c] =
                        make_float2(ac[half*2+0] + bb0, ac[half*2+1] + bb1);
                }
            }
        __syncthreads();   // before reusing anything (not strictly needed for t=1)
    }
}

extern "C" void kernel_launch(void* const* d_in, const int* in_sizes, int n_in,
                              void* d_out, int out_size)
{
    (void)in_sizes; (void)n_in; (void)out_size;
    const float* pair      = (const float*)d_in[0];
    const float* bias      = (const float*)d_in[1];
    const float* ln_pair_g = (const float*)d_in[2];
    const float* ln_pair_b = (const float*)d_in[3];
    const float* ln_bias_g = (const float*)d_in[4];
    const float* ln_bias_b = (const float*)d_in[5];
    const float* Wq = (const float*)d_in[6];
    const float* Wk = (const float*)d_in[7];
    const float* Wv = (const float*)d_in[8];
    const float* Wb = (const float*)d_in[9];
    const float* Wg = (const float*)d_in[10];
    const float* bg = (const float*)d_in[11];
    const float* Wo = (const float*)d_in[12];
    const float* bo = (const float*)d_in[13];
    float* outp = (float*)d_out;

    const int PB_SMEM  = 98304;   // 32KB X + 2x32KB W buffers
    const int SMEM3    = 98304;   // 3-stage pipelined GEMMs (score, av)
    const int OUT_SMEM = 98304;   // 2x32KB X + 32KB Wo
    cudaFuncSetAttribute(pb_kernel,    cudaFuncAttributeMaxDynamicSharedMemorySize, PB_SMEM);
    cudaFuncSetAttribute(score_kernel, cudaFuncAttributeMaxDynamicSharedMemorySize, SMEM3);
    cudaFuncSetAttribute(av_kernel,    cudaFuncAttributeMaxDynamicSharedMemorySize, SMEM3);
    cudaFuncSetAttribute(out_kernel,   cudaFuncAttributeMaxDynamicSharedMemorySize, OUT_SMEM);

    wconv_kernel<<<5, 512>>>(Wq, Wk, Wv, Wg, Wo);
    pb_kernel<<<NB_PROJ + NB_BIAS, 512, PB_SMEM>>>(pair, bias,
        ln_pair_g, ln_pair_b, ln_bias_g, ln_bias_b, bg, Wb);
    score_kernel<<<dim3(3, 3, 32), 256, SMEM3>>>();
    softmax_kernel<<<dim3(LREF, HN), 128>>>();
    av_kernel<<<dim3(3, KTOT/128, HN), 256, SMEM3>>>();
    out_kernel<<<LREF*LREF/256, 512, OUT_SMEM>>>(bo, outp);
}

// round 16
// speedup vs baseline: 1.7353x; 1.0074x over previous
#include <cuda_runtime.h>
#include <cuda_bf16.h>
#include <math.h>

#define LREF 384
#define DPC 128
#define HN 4
#define DHD 32
#define KTOT (LREF*DHD)   // 12288

typedef __nv_bfloat16 bf16;
typedef __nv_bfloat162 bf162;

#define NB_PROJ (LREF*LREF/128)   // 1152
#define NB_BIAS (LREF*LREF/64)    // 2304

// ---------------- scratch (device globals) ----------------------------------
__device__ unsigned char g_q8[(size_t)HN*LREF*KTOT]; // [h][i][n*32+d] e4m3, unscaled
__device__ unsigned char g_k8[(size_t)HN*LREF*KTOT]; // [h][j][n*32+d] e4m3, unscaled
__device__ bf16 g_v2[(size_t)HN*KTOT*LREF];     // [h][col=n*32+d][j]  K-major(j)
__device__ bf16 g_gateb[(size_t)LREF*LREF*DPC]; // [row=n*L+i][c]
__device__ bf16 g_omb[(size_t)LREF*LREF*DPC];   // [row=n*L+i][h*32+d]  (gate-multiplied)
__device__ float g_attn[(size_t)HN*LREF*LREF];  // fp32 logits (bias-init + atomics)
__device__ bf16 g_attnb[(size_t)HN*LREF*LREF];  // softmaxed, bf16
__device__ unsigned char g_wbf[5*32768];        // bf16 weights, pre-swizzled smem layout

// ---------------- ptx helpers ------------------------------------------------
__device__ __forceinline__ void ldsm4(unsigned &r0,unsigned &r1,unsigned &r2,unsigned &r3,unsigned a){
    asm volatile("ldmatrix.sync.aligned.m8n8.x4.shared.b16 {%0,%1,%2,%3},[%4];"
        :"=r"(r0),"=r"(r1),"=r"(r2),"=r"(r3):"r"(a));
}
__device__ __forceinline__ void mma_bf16(float c[4], const unsigned a[4], const unsigned b[2]){
    asm volatile("mma.sync.aligned.m16n8k16.row.col.f32.bf16.bf16.f32 "
        "{%0,%1,%2,%3},{%4,%5,%6,%7},{%8,%9},{%0,%1,%2,%3};"
        :"+f"(c[0]),"+f"(c[1]),"+f"(c[2]),"+f"(c[3])
        :"r"(a[0]),"r"(a[1]),"r"(a[2]),"r"(a[3]),"r"(b[0]),"r"(b[1]));
}
__device__ __forceinline__ void mma_fp8(float c[4], const unsigned a[4], const unsigned b[2]){
    asm volatile("mma.sync.aligned.m16n8k32.row.col.f32.e4m3.e4m3.f32 "
        "{%0,%1,%2,%3},{%4,%5,%6,%7},{%8,%9},{%0,%1,%2,%3};"
        :"+f"(c[0]),"+f"(c[1]),"+f"(c[2]),"+f"(c[3])
        :"r"(a[0]),"r"(a[1]),"r"(a[2]),"r"(a[3]),"r"(b[0]),"r"(b[1]));
}
__device__ __forceinline__ void cpa16(unsigned saddr, const void* g) {
    asm volatile("cp.async.cg.shared.global [%0],[%1],16;\n" :: "r"(saddr), "l"(g));
}
__device__ __forceinline__ void cpa_commit() { asm volatile("cp.async.commit_group;\n"); }
template<int N>
__device__ __forceinline__ void cpa_wait() { asm volatile("cp.async.wait_group %0;\n" :: "n"(N)); }

__device__ __forceinline__ unsigned pk2(float a, float b){
    bf162 t = __floats2bfloat162_rn(a, b);
    return *(unsigned*)&t;
}
__device__ __forceinline__ unsigned short pk8(float lo, float hi){
    unsigned short u;
    asm("cvt.rn.satfinite.e4m3x2.f32 %0, %2, %1;" : "=h"(u) : "f"(lo), "f"(hi));
    return u;
}

// warp k16-step (bf16): A rows 128B [m][k64], B rows 128B [n][k64], SW128-swizzled
template<int MT,int NT>
__device__ __forceinline__ void wstep(float (&acc)[MT][NT][4], unsigned sA, unsigned sB,
                                      int m0, int n0, int k0, int lane)
{
    unsigned a[MT][4];
    int arow = lane & 15, acg = (k0>>3) + (lane>>4);
#pragma unroll
    for (int mt = 0; mt < MT; mt++) {
        int r = m0 + mt*16 + arow;
        ldsm4(a[mt][0],a[mt][1],a[mt][2],a[mt][3], sA + r*128 + ((acg ^ (r&7))<<4));
    }
    int brow_off = (lane & 7) + ((lane>>4)<<3);
    int bcg = (k0>>3) + ((lane>>3)&1);
#pragma unroll
    for (int nt = 0; nt < NT; nt += 2) {
        int r = n0 + nt*8 + brow_off;
        unsigned b[4];
        ldsm4(b[0],b[1],b[2],b[3], sB + r*128 + ((bcg ^ (r&7))<<4));
#pragma unroll
        for (int mt = 0; mt < MT; mt++) {
            mma_bf16(acc[mt][nt],   a[mt], b);
            mma_bf16(acc[mt][nt+1], a[mt], b+2);
        }
    }
}

// warp k32-step (fp8): A rows 128B [m][k128 bytes], B rows 128B [n][k128 bytes]
template<int MT,int NT>
__device__ __forceinline__ void wstep8(float (&acc)[MT][NT][4], unsigned sA, unsigned sB,
                                       int m0, int n0, int kb, int lane)
{
    unsigned a[MT][4];
    int arow = lane & 15, acg = (kb>>4) + (lane>>4);
#pragma unroll
    for (int mt = 0; mt < MT; mt++) {
        int r = m0 + mt*16 + arow;
        ldsm4(a[mt][0],a[mt][1],a[mt][2],a[mt][3], sA + r*128 + ((acg ^ (r&7))<<4));
    }
    int brow_off = (lane & 7) + ((lane>>4)<<3);
    int bcg = (kb>>4) + ((lane>>3)&1);
#pragma unroll
    for (int nt = 0; nt < NT; nt += 2) {
        int r = n0 + nt*8 + brow_off;
        unsigned b[4];
        ldsm4(b[0],b[1],b[2],b[3], sB + r*128 + ((bcg ^ (r&7))<<4));
#pragma unroll
        for (int mt = 0; mt < MT; mt++) {
            mma_fp8(acc[mt][nt],   a[mt], b);
            mma_fp8(acc[mt][nt+1], a[mt], b+2);
        }
    }
}

// -------- kernel 0: convert weights fp32 -> bf16, pre-swizzled ---------------
__global__ void __launch_bounds__(512) wconv_kernel(
    const float* __restrict__ Wq, const float* __restrict__ Wk, const float* __restrict__ Wv,
    const float* __restrict__ Wg, const float* __restrict__ Wo)
{
    const float* Ws[5] = { Wq, Wk, Wv, Wg, Wo };
    const float* W = Ws[blockIdx.x];
    unsigned char* dst = g_wbf + (size_t)blockIdx.x * 32768;
    int tid = threadIdx.x;
    for (int idx = tid; idx < 2048; idx += 512) {
        int r = idx >> 4, g16 = idx & 15;
        int kc = g16 >> 3, gg = g16 & 7;
        const float* src = W + (size_t)r*DPC + kc*64 + gg*8;
        float4 t0 = *(const float4*)src;
        float4 t1 = *(const float4*)(src + 4);
        uint4 o;
        o.x = pk2(t0.x,t0.y); o.y = pk2(t0.z,t0.w);
        o.z = pk2(t1.x,t1.y); o.w = pk2(t1.z,t1.w);
        *(uint4*)(dst + kc*16384 + r*128 + ((gg ^ (r&7))<<4)) = o;
    }
}

// -------- fused kernel A: proj (blocks 0..NB_PROJ) + bias (rest) -------------
__global__ void __launch_bounds__(512,2) pb_kernel(
    const float* __restrict__ pair, const float* __restrict__ biasp,
    const float* __restrict__ lnpg, const float* __restrict__ lnpb,
    const float* __restrict__ lnbg, const float* __restrict__ lnbb,
    const float* __restrict__ bg, const float* __restrict__ Wb)
{
    extern __shared__ unsigned char sm[];
    int tid = threadIdx.x, lane = tid & 31, wid = tid >> 5;

    if (blockIdx.x < NB_PROJ) {
        // ================= proj =================
        unsigned sXa = (unsigned)__cvta_generic_to_shared(sm);   // 2 x 16KB LN'ed X
        unsigned sWa = sXa + 32768;                              // 2 x 32KB W double buffer
        int wm = wid & 3, wn = wid >> 2;     // 4m x 4n warps, tile 32x32
        int row0 = blockIdx.x * 128;
        int nn = row0 / LREF, i0b = row0 % LREF;

        auto stageW = [&](int mat) {
            const unsigned char* src = g_wbf + (size_t)mat * 32768;
            unsigned buf = sWa + (unsigned)(mat & 1) * 32768;
#pragma unroll
            for (int k = 0; k < 4; k++) {
                unsigned off = (unsigned)(tid + k*512) * 16;
                cpa16(buf + off, src + off);
            }
            cpa_commit();
        };
        stageW(0);   // group 0
        stageW(1);   // group 1

        // warp-cooperative single-pass LN: warp handles 8 rows
        for (int rr = 0; rr < 8; rr++) {
            int r = wid * 8 + rr;
            int i = i0b + r;
            const float* x = pair + ((size_t)i*LREF + nn) * DPC;
            float4 t = *(const float4*)(x + lane*4);
            float s  = t.x + t.y + t.z + t.w;
            float s2 = t.x*t.x + t.y*t.y + t.z*t.z + t.w*t.w;
#pragma unroll
            for (int o = 16; o; o >>= 1) {
                s  += __shfl_xor_sync(0xffffffffu, s,  o);
                s2 += __shfl_xor_sync(0xffffffffu, s2, o);
            }
            float mean = s * (1.f/DPC);
            float rstd = rsqrtf(s2 * (1.f/DPC) - mean*mean + 1e-5f);
            float4 wv = *(const float4*)(lnpg + lane*4);
            float4 bv = *(const float4*)(lnpb + lane*4);
            unsigned p0 = pk2((t.x-mean)*rstd*wv.x + bv.x, (t.y-mean)*rstd*wv.y + bv.y);
            unsigned p1 = pk2((t.z-mean)*rstd*wv.z + bv.z, (t.w-mean)*rstd*wv.w + bv.w);
            int kc = lane >> 4, g = (lane & 15) >> 1;
            *(uint2*)(sm + kc*16384 + r*128 + ((g ^ (r&7))<<4) + (lane&1)*8) = make_uint2(p0, p1);
        }

        for (int mat = 0; mat < 4; mat++) {
            if (mat < 3) cpa_wait<1>(); else cpa_wait<0>();
            __syncthreads();   // W(mat) visible + (mat==0: LN writes visible)

            unsigned bufW = sWa + (unsigned)(mat & 1) * 32768;
            float acc[2][4][4];
#pragma unroll
            for (int a = 0; a < 2; a++)
#pragma unroll
                for (int b = 0; b < 4; b++)
#pragma unroll
                    for (int cc = 0; cc < 4; cc++) acc[a][b][cc] = 0.f;
#pragma unroll
            for (int kc = 0; kc < 2; kc++)
#pragma unroll
                for (int kk = 0; kk < 4; kk++)
                    wstep<2,4>(acc, sXa + kc*16384, bufW + kc*16384, wm*32, wn*32, kk*16, lane);
            __syncthreads();   // all warps done reading this W buffer

            // ---- stage results to smem (overwrites just-consumed W buffer) ----
            unsigned char* smTb = sm + 32768 + (size_t)(mat & 1) * 32768;
            unsigned char* smT8 = smTb;
            bf16* smT16 = (bf16*)smTb;
#pragma unroll
            for (int mt = 0; mt < 2; mt++)
#pragma unroll
                for (int nt = 0; nt < 4; nt++) {
                    float* ac = acc[mt][nt];
                    int rl = wm*32 + mt*16 + (lane >> 2);
                    int c  = wn*32 + nt*8 + 2*(lane & 3);
#pragma unroll
                    for (int half = 0; half < 2; half++) {
                        int il = rl + half*8;
                        float v0 = ac[half*2+0], v1 = ac[half*2+1];
                        if (mat < 2) {
                            *(unsigned short*)&smT8[il*128 + c] = pk8(v0, v1);
                        } else if (mat == 2) {
                            smT16[(c)  *128 + il] = __float2bfloat16_rn(v0);
                            smT16[(c+1)*128 + il] = __float2bfloat16_rn(v1);
                        } else {
                            float z0 = v0 + bg[c], z1 = v1 + bg[c+1];
                            *(bf162*)&smT16[il*128 + c] =
                                __floats2bfloat162_rn(1.f/(1.f+expf(-z0)), 1.f/(1.f+expf(-z1)));
                        }
                    }
                }
            __syncthreads();

            // ---- coalesced global writes ----
            if (mat < 2) {
                unsigned char* dst = (mat == 0) ? g_q8 : g_k8;
#pragma unroll
                for (int k = 0; k < 8; k++) {
                    int idx = tid + k*512;
                    int i = idx >> 5, seg = idx & 31;
                    int c4 = seg*4;
                    int hh = c4 >> 5, d = c4 & 31;
                    *(unsigned*)&dst[((size_t)(hh*LREF + i0b + i))*KTOT + nn*DHD + d] =
                        *(unsigned*)&smT8[i*128 + c4];
                }
            } else if (mat == 2) {
#pragma unroll
                for (int k = 0; k < 4; k++) {
                    int idx = tid + k*512;
                    int col = idx >> 4, seg = idx & 15;
                    int hh = col >> 5, d = col & 31;
                    *(uint4*)&g_v2[((size_t)hh*KTOT + nn*DHD + d)*LREF + i0b + seg*8] =
                        *(uint4*)&smT16[col*128 + seg*8];
                }
            } else {
#pragma unroll
                for (int k = 0; k < 4; k++) {
                    int idx = tid + k*512;
                    int i = idx >> 4, seg = idx & 15;
                    *(uint4*)&g_gateb[((size_t)(nn*LREF + i0b + i))*DPC + seg*8] =
                        *(uint4*)&smT16[i*128 + seg*8];
                }
            }
            __syncthreads();   // staging buffer free
            if (mat + 2 < 4) stageW(mat + 2);   // prefetch into the freed buffer
        }
    } else {
        // ================= bias: 64 rows/block, 4 rows/warp =================
        float* sWb = (float*)sm;           // 4*128 floats
        int bid = blockIdx.x - NB_PROJ;
        for (int c = tid; c < 4*DPC; c += 512) sWb[c] = Wb[c];
        __syncthreads();

        float4 wg = *(const float4*)(lnbg + lane*4);
        float4 wb = *(const float4*)(lnbb + lane*4);
        float4 W0 = *(const float4*)(sWb + 0*DPC + lane*4);
        float4 W1 = *(const float4*)(sWb + 1*DPC + lane*4);
        float4 W2 = *(const float4*)(sWb + 2*DPC + lane*4);
        float4 W3 = *(const float4*)(sWb + 3*DPC + lane*4);

        for (int rr = 0; rr < 4; rr++) {
            int row = bid*64 + wid*4 + rr;    // row = i*L + j
            int i = row / LREF, j = row - i*LREF;
            const float* x = biasp + ((size_t)j*LREF + i) * DPC;
            float4 t = *(const float4*)(x + lane*4);
            float s  = t.x + t.y + t.z + t.w;
            float s2 = t.x*t.x + t.y*t.y + t.z*t.z + t.w*t.w;
#pragma unroll
            for (int o = 16; o; o >>= 1) {
                s  += __shfl_xor_sync(0xffffffffu, s,  o);
                s2 += __shfl_xor_sync(0xffffffffu, s2, o);
            }
            float mean = s * (1.f/DPC);
            float rstd = rsqrtf(s2 * (1.f/DPC) - mean*mean + 1e-5f);
            float e0 = (t.x-mean)*rstd*wg.x + wb.x;
            float e1 = (t.y-mean)*rstd*wg.y + wb.y;
            float e2 = (t.z-mean)*rstd*wg.z + wb.z;
            float e3 = (t.w-mean)*rstd*wg.w + wb.w;
            float p0 = e0*W0.x + e1*W0.y + e2*W0.z + e3*W0.w;
            float p1 = e0*W1.x + e1*W1.y + e2*W1.z + e3*W1.w;
            float p2 = e0*W2.x + e1*W2.y + e2*W2.z + e3*W2.w;
            float p3 = e0*W3.x + e1*W3.y + e2*W3.z + e3*W3.w;
#pragma unroll
            for (int o = 16; o; o >>= 1) {
                p0 += __shfl_xor_sync(0xffffffffu, p0, o);
                p1 += __shfl_xor_sync(0xffffffffu, p1, o);
                p2 += __shfl_xor_sync(0xffffffffu, p2, o);
                p3 += __shfl_xor_sync(0xffffffffu, p3, o);
            }
            if (lane == 0) {
                g_attn[((size_t)0*LREF + i)*LREF + j] = p0;
                g_attn[((size_t)1*LREF + i)*LREF + j] = p1;
                g_attn[((size_t)2*LREF + i)*LREF + j] = p2;
                g_attn[((size_t)3*LREF + i)*LREF + j] = p3;
            }
        }
    }
}

// -------- kernel C: attn += scale*(q8.k8)  (256 thr, 32x64 warp tile) --------
__global__ void __launch_bounds__(256,2) score_kernel()
{
    extern __shared__ unsigned char sm[];
    unsigned sbase = (unsigned)__cvta_generic_to_shared(sm);   // 3 x 32KB (A16+B16)
    int tid = threadIdx.x, lane = tid & 31, warp = tid >> 5;
    int wm = warp & 3, wn = warp >> 2;      // 4m x 2n, warp tile 32x64
    int h = blockIdx.z >> 3, ks = blockIdx.z & 7;
    int i0 = blockIdx.x * 128, j0 = blockIdx.y * 128;

    const unsigned char* ga = g_q8 + ((size_t)(h*LREF + i0))*KTOT + ks*(KTOT/8);
    const unsigned char* gb = g_k8 + ((size_t)(h*LREF + j0))*KTOT + ks*(KTOT/8);

    float acc[2][8][4];
#pragma unroll
    for (int a = 0; a < 2; a++)
#pragma unroll
        for (int b = 0; b < 8; b++)
#pragma unroll
            for (int cc = 0; cc < 4; cc++) acc[a][b][cc] = 0.f;

    const int NIT = (KTOT/8)/128;   // 12
    auto stage = [&](int it) {
        unsigned buf = sbase + (unsigned)(it % 3) * 32768;
        for (int c = tid; c < 1024; c += 256) {
            int r = c >> 3, g = c & 7;
            unsigned d = r*128 + ((g ^ (r&7))<<4);
            cpa16(buf + d,         ga + (size_t)r*KTOT + it*128 + g*16);
            cpa16(buf + 16384 + d, gb + (size_t)r*KTOT + it*128 + g*16);
        }
        cpa_commit();
    };
    stage(0); stage(1);
    for (int it = 0; it < NIT; it++) {
        if (it < NIT-1) cpa_wait<1>(); else cpa_wait<0>();
        __syncthreads();
        unsigned buf = sbase + (unsigned)(it % 3) * 32768;
#pragma unroll
        for (int kk = 0; kk < 4; kk++)
            wstep8<2,8>(acc, buf, buf + 16384, wm*32, wn*64, kk*32, lane);
        if (it + 2 < NIT) stage(it + 2);
    }

    const float SC = 0.17677669529663687f / 384.0f;
#pragma unroll
    for (int mt = 0; mt < 2; mt++)
#pragma unroll
        for (int nt = 0; nt < 8; nt++) {
            float* ac = acc[mt][nt];
            int r = i0 + wm*32 + mt*16 + (lane >> 2);
            int c = j0 + wn*64 + nt*8 + 2*(lane & 3);
            size_t base = ((size_t)h*LREF + r)*LREF + c;
            atomicAdd(&g_attn[base],            ac[0]*SC);
            atomicAdd(&g_attn[base + 1],        ac[1]*SC);
            atomicAdd(&g_attn[base + 8*LREF],   ac[2]*SC);
            atomicAdd(&g_attn[base + 8*LREF+1], ac[3]*SC);
        }
}

// -------- softmax: 4 rows/block (512 thr), fp32 in, bf16 out -----------------
__global__ void __launch_bounds__(512) softmax_kernel()
{
    int tid = threadIdx.x;
    int rl = tid >> 7;                 // row slot 0..3
    int t = tid & 127;
    int warp = t >> 5, lane = t & 31;
    int flat = blockIdx.x * 4 + rl;    // (h*LREF + i) in [0, 1536)
    const float* row = g_attn + (size_t)flat * LREF;
    bf16* orow = g_attnb + (size_t)flat * LREF;
    __shared__ float smax[4][4], ssum[4][4];

    float a0 = row[t], a1 = row[t + 128], a2 = row[t + 256];
    float m = fmaxf(a0, fmaxf(a1, a2));
#pragma unroll
    for (int o = 16; o; o >>= 1) m = fmaxf(m, __shfl_xor_sync(0xffffffffu, m, o));
    if (lane == 0) smax[rl][warp] = m;
    __syncthreads();
    float M = fmaxf(fmaxf(smax[rl][0], smax[rl][1]), fmaxf(smax[rl][2], smax[rl][3]));

    float e0 = expf(a0 - M), e1 = expf(a1 - M), e2 = expf(a2 - M);
    float s = e0 + e1 + e2;
#pragma unroll
    for (int o = 16; o; o >>= 1) s += __shfl_xor_sync(0xffffffffu, s, o);
    if (lane == 0) ssum[rl][warp] = s;
    __syncthreads();
    float S = ssum[rl][0] + ssum[rl][1] + ssum[rl][2] + ssum[rl][3];
    float inv = 1.f / S;
    orow[t]       = __float2bfloat16_rn(e0 * inv);
    orow[t + 128] = __float2bfloat16_rn(e1 * inv);
    orow[t + 256] = __float2bfloat16_rn(e2 * inv);
}

// -------- kernel D: om = gate .* (attn_b @ v2^T)  (256 thr, 32x64 tile) ------
__global__ void __launch_bounds__(256,2) av_kernel()
{
    extern __shared__ unsigned char sm[];
    unsigned sbase = (unsigned)__cvta_generic_to_shared(sm);   // 3 x 32KB
    int tid = threadIdx.x, lane = tid & 31, warp = tid >> 5;
    int wm = warp & 3, wn = warp >> 2;      // 4m x 2n, warp tile 32x64
    int i0 = blockIdx.x * 128, col0 = blockIdx.y * 128, h = blockIdx.z;

    const bf16* ga = g_attnb + ((size_t)(h*LREF + i0))*LREF;
    const bf16* gv = g_v2 + ((size_t)h*KTOT + col0)*LREF;

    float acc[2][8][4];
#pragma unroll
    for (int a = 0; a < 2; a++)
#pragma unroll
        for (int b = 0; b < 8; b++)
#pragma unroll
            for (int cc = 0; cc < 4; cc++) acc[a][b][cc] = 0.f;

    const int NIT = LREF/64;   // 6
    auto stage = [&](int it) {
        unsigned buf = sbase + (unsigned)(it % 3) * 32768;
        for (int c = tid; c < 1024; c += 256) {
            int r = c >> 3, g = c & 7;
            unsigned d = r*128 + ((g ^ (r&7))<<4);
            cpa16(buf + d,         ga + (size_t)r*LREF + it*64 + g*8);
            cpa16(buf + 16384 + d, gv + (size_t)r*LREF + it*64 + g*8);
        }
        cpa_commit();
    };
    stage(0); stage(1);
    for (int it = 0; it < NIT; it++) {
        if (it < NIT-1) cpa_wait<1>(); else cpa_wait<0>();
        __syncthreads();
        unsigned buf = sbase + (unsigned)(it % 3) * 32768;
#pragma unroll
        for (int kk = 0; kk < 4; kk++)
            wstep<2,8>(acc, buf, buf + 16384, wm*32, wn*64, kk*16, lane);
        if (it + 2 < NIT) stage(it + 2);
    }

#pragma unroll
    for (int mt = 0; mt < 2; mt++)
#pragma unroll
        for (int nt = 0; nt < 8; nt++) {
            float* ac = acc[mt][nt];
            int c = col0 + wn*64 + nt*8 + 2*(lane & 3);
            int n = c >> 5, d = c & 31;
#pragma unroll
            for (int half = 0; half < 2; half++) {
                int i = i0 + wm*32 + mt*16 + (lane >> 2) + half*8;
                size_t ofs = ((size_t)n*LREF + i)*DPC + h*DHD + d;
                bf162 gv2 = *(const bf162*)&g_gateb[ofs];
                bf162 r2 = __floats2bfloat162_rn(ac[half*2+0], ac[half*2+1]);
                *(bf162*)&g_omb[ofs] = __hmul2(gv2, r2);
            }
        }
}

// -------- kernel E: y = omb @ Wo^T + bo (4 row-tiles/block) ------------------
__global__ void __launch_bounds__(512,2) out_kernel(
    const float* __restrict__ bo, float* __restrict__ outp)
{
    extern __shared__ unsigned char sm[];
    unsigned sXa = (unsigned)__cvta_generic_to_shared(sm);   // 2 rotating 32KB X bufs
    unsigned sWa = sXa + 65536;                              // 32KB Wo
    int tid = threadIdx.x, lane = tid & 31, warp = tid >> 5;
    int wm = warp & 3, wn = warp >> 2;

    auto stageX = [&](int t) {
        int row0 = (blockIdx.x*4 + t) * 128;
        const unsigned char* srcX = (const unsigned char*)g_omb + (size_t)row0 * 256;
        unsigned dst = sXa + (unsigned)(t & 1) * 32768;
        for (int idx = tid; idx < 2048; idx += 512) {
            int r = idx >> 4, g16 = idx & 15;
            int kc = g16 >> 3, gg = g16 & 7;
            cpa16(dst + kc*16384 + r*128 + ((gg ^ (r&7))<<4),
                  srcX + (size_t)r*256 + kc*128 + gg*16);
        }
        cpa_commit();
    };
    stageX(0);                         // group 0 -> buf0
    {
        const unsigned char* srcW = g_wbf + 4*32768;
#pragma unroll
        for (int k = 0; k < 4; k++) {
            unsigned off = (unsigned)(tid + k*512) * 16;
            cpa16(sWa + off, srcW + off);
        }
        cpa_commit();                  // group 1 (Wo)
    }
    stageX(1);                         // group 2 -> buf1

    for (int t = 0; t < 4; t++) {
        if (t < 3) cpa_wait<1>(); else cpa_wait<0>();
        __syncthreads();               // X(t) (+Wo at t=0) visible to all warps
        int row0 = (blockIdx.x*4 + t) * 128;
        unsigned sX = sXa + (unsigned)(t & 1) * 32768;

        float acc[2][4][4];
#pragma unroll
        for (int a = 0; a < 2; a++)
#pragma unroll
            for (int b = 0; b < 4; b++)
#pragma unroll
                for (int cc = 0; cc < 4; cc++) acc[a][b][cc] = 0.f;

#pragma unroll
        for (int kc = 0; kc < 2; kc++)
#pragma unroll
            for (int kk = 0; kk < 4; kk++)
                wstep<2,4>(acc, sX + kc*16384, sWa + kc*16384, wm*32, wn*32, kk*16, lane);

#pragma unroll
        for (int mt = 0; mt < 2; mt++)
#pragma unroll
            for (int nt = 0; nt < 4; nt++) {
                float* ac = acc[mt][nt];
                int rl = wm*32 + mt*16 + (lane >> 2);
                int c  = wn*32 + nt*8 + 2*(lane & 3);
                float b0 = bo[c], b1 = bo[c+1];
#pragma unroll
                for (int half = 0; half < 2; half++) {
                    int row = row0 + rl + half*8;
                    int n = row / LREF, i = row - n*LREF;
                    *(float2*)&outp[((size_t)i*LREF + n)*DPC + c] =
                        make_float2(ac[half*2+0] + b0, ac[half*2+1] + b1);
                }
            }
        __syncthreads();               // all warps done reading buf(t&1)
        if (t + 2 < 4) stageX(t + 2);  // prefetch into the freed buffer
    }
}

extern "C" void kernel_launch(void* const* d_in, const int* in_sizes, int n_in,
                              void* d_out, int out_size)
{
    (void)in_sizes; (void)n_in; (void)out_size;
    const float* pair      = (const float*)d_in[0];
    const float* bias      = (const float*)d_in[1];
    const float* ln_pair_g = (const float*)d_in[2];
    const float* ln_pair_b = (const float*)d_in[3];
    const float* ln_bias_g = (const float*)d_in[4];
    const float* ln_bias_b = (const float*)d_in[5];
    const float* Wq = (const float*)d_in[6];
    const float* Wk = (const float*)d_in[7];
    const float* Wv = (const float*)d_in[8];
    const float* Wb = (const float*)d_in[9];
    const float* Wg = (const float*)d_in[10];
    const float* bg = (const float*)d_in[11];
    const float* Wo = (const float*)d_in[12];
    const float* bo = (const float*)d_in[13];
    float* outp = (float*)d_out;

    const int PB_SMEM  = 98304;   // 32KB X + 2x32KB W buffers
    const int SMEM3    = 98304;   // 3-stage pipelined GEMMs (score, av)
    const int OUT_SMEM = 98304;   // 2x32KB X + 32KB Wo
    cudaFuncSetAttribute(pb_kernel,    cudaFuncAttributeMaxDynamicSharedMemorySize, PB_SMEM);
    cudaFuncSetAttribute(score_kernel, cudaFuncAttributeMaxDynamicSharedMemorySize, SMEM3);
    cudaFuncSetAttribute(av_kernel,    cudaFuncAttributeMaxDynamicSharedMemorySize, SMEM3);
    cudaFuncSetAttribute(out_kernel,   cudaFuncAttributeMaxDynamicSharedMemorySize, OUT_SMEM);

    wconv_kernel<<<5, 512>>>(Wq, Wk, Wv, Wg, Wo);
    pb_kernel<<<NB_PROJ + NB_BIAS, 512, PB_SMEM>>>(pair, bias,
        ln_pair_g, ln_pair_b, ln_bias_g, ln_bias_b, bg, Wb);
    score_kernel<<<dim3(3, 3, 32), 256, SMEM3>>>();
    softmax_kernel<<<LREF*HN/4, 512>>>();
    av_kernel<<<dim3(3, KTOT/128, HN), 256, SMEM3>>>();
    out_kernel<<<LREF*LREF/512, 512, OUT_SMEM>>>(bo, outp);
}